// round 2
// baseline (speedup 1.0000x reference)
#include <cuda_runtime.h>

#define NB 1024      // number of sequences (spatial positions)
#define NT 16        // sequence length (original batch)
#define TOK 16384    // NB*NT tokens, token = t*NB + b
#define DM 256       // d_model
#define DI 512       // d_inner
#define DS 16        // d_state
#define DR 16        // dt_rank

// ---- scratch (channel-major [C][token], token contiguous) ----
__device__ float g_xn[DM * TOK];      // rmsnorm output
__device__ float g_u[DI * TOK];       // pre-conv xm (first half of GEMM1)
__device__ float g_sres[DI * TOK];    // silu(res) (second half of GEMM1)
__device__ float g_xm[DI * TOK];      // post conv+silu
__device__ float g_dbc[48 * TOK];     // rows 0..15 delta_in, 16..31 B, 32..47 C
__device__ float g_delta[DI * TOK];   // softplus(delta_in @ w_dt + b_dt)
__device__ float g_y[DI * TOK];       // scan output * silu(res)

__device__ __forceinline__ float siluf(float x) {
    return __fdividef(x, 1.f + __expf(-x));
}
__device__ __forceinline__ float softplusf(float x) {
    float ax = fabsf(x);
    return fmaxf(x, 0.f) + __logf(1.f + __expf(-ax));
}

// ---------------- RMSNorm: feature [t][c][b] -> g_xn[c][t*NB+b] ----------------
__global__ __launch_bounds__(256) void k_rmsnorm(const float* __restrict__ feat,
                                                 const float* __restrict__ nw) {
    int t = blockIdx.y;
    int tx = threadIdx.x;            // b within chunk of 32
    int ty = threadIdx.y;            // 0..7
    int b = blockIdx.x * 32 + tx;
    const float* base = feat + (size_t)t * DM * NB + b;
    float v[32];
    float ss = 0.f;
#pragma unroll
    for (int i = 0; i < 32; i++) {
        int c = ty + i * 8;
        float x = base[(size_t)c * NB];
        v[i] = x;
        ss += x * x;
    }
    __shared__ float sred[8][32];
    sred[ty][tx] = ss;
    __syncthreads();
    float tot = 0.f;
#pragma unroll
    for (int j = 0; j < 8; j++) tot += sred[j][tx];
    float sc = rsqrtf(tot * (1.f / DM) + 1e-5f);
    int tok = t * NB + b;
#pragma unroll
    for (int i = 0; i < 32; i++) {
        int c = ty + i * 8;
        g_xn[(size_t)c * TOK + tok] = v[i] * sc * nw[c];
    }
}

// ---------------- GEMM1: out[n][m] = sum_k w_in[k][n] * g_xn[k][m] ----------------
// n<512 -> g_u raw ; n>=512 -> g_sres = silu
__global__ __launch_bounds__(256) void k_gemm1(const float* __restrict__ W) {
    __shared__ float sW[8][128];
    __shared__ float sX[8][128];
    int bm = blockIdx.x * 128, bn = blockIdx.y * 128;
    int tid = threadIdx.x;
    int txm = tid & 15, tyn = tid >> 4;
    float acc[8][8];
#pragma unroll
    for (int i = 0; i < 8; i++)
#pragma unroll
        for (int j = 0; j < 8; j++) acc[i][j] = 0.f;

    int lr = tid >> 5;
    int lc = (tid & 31) * 4;
    const float* Wp = W + (size_t)lr * 1024 + bn + lc;
    const float* Xp = g_xn + (size_t)lr * TOK + bm + lc;

    for (int k0 = 0; k0 < DM; k0 += 8) {
        *(float4*)&sW[lr][lc] = *(const float4*)(Wp + (size_t)k0 * 1024);
        *(float4*)&sX[lr][lc] = *(const float4*)(Xp + (size_t)k0 * TOK);
        __syncthreads();
#pragma unroll
        for (int k = 0; k < 8; k++) {
            float a[8], bb[8];
            *(float4*)&a[0] = *(const float4*)&sW[k][tyn * 4];
            *(float4*)&a[4] = *(const float4*)&sW[k][64 + tyn * 4];
            *(float4*)&bb[0] = *(const float4*)&sX[k][txm * 4];
            *(float4*)&bb[4] = *(const float4*)&sX[k][64 + txm * 4];
#pragma unroll
            for (int i = 0; i < 8; i++)
#pragma unroll
                for (int j = 0; j < 8; j++) acc[i][j] += a[i] * bb[j];
        }
        __syncthreads();
    }
    bool isRes = (bn >= DI);
#pragma unroll
    for (int i = 0; i < 8; i++) {
        int n = bn + ((i < 4) ? (tyn * 4 + i) : (64 + tyn * 4 + i - 4));
#pragma unroll
        for (int jq = 0; jq < 2; jq++) {
            int m = bm + ((jq == 0) ? (txm * 4) : (64 + txm * 4));
            float4 v;
            v.x = acc[i][jq * 4 + 0]; v.y = acc[i][jq * 4 + 1];
            v.z = acc[i][jq * 4 + 2]; v.w = acc[i][jq * 4 + 3];
            if (!isRes) {
                *(float4*)&g_u[(size_t)n * TOK + m] = v;
            } else {
                v.x = siluf(v.x); v.y = siluf(v.y); v.z = siluf(v.z); v.w = siluf(v.w);
                *(float4*)&g_sres[(size_t)(n - DI) * TOK + m] = v;
            }
        }
    }
}

// ---------------- depthwise causal conv (k=3) over t + silu ----------------
__global__ __launch_bounds__(256) void k_conv(const float* __restrict__ cw,
                                              const float* __restrict__ cb) {
    int m = blockIdx.x * 256 + threadIdx.x;
    int d = blockIdx.y;
    int t = m >> 10;
    float w0 = cw[d * 3 + 0], w1 = cw[d * 3 + 1], w2 = cw[d * 3 + 2];
    size_t base = (size_t)d * TOK + m;
    float acc = cb[d] + w2 * g_u[base];
    if (t >= 1) acc += w1 * g_u[base - NB];
    if (t >= 2) acc += w0 * g_u[base - 2 * NB];
    g_xm[base] = siluf(acc);
}

// ---------------- xproj: g_dbc[j][m] = sum_d w_xproj[d][j] * g_xm[d][m] ----------------
__global__ __launch_bounds__(256) void k_xproj(const float* __restrict__ Wx) {
    int m = blockIdx.x * 256 + threadIdx.x;
    int j0 = blockIdx.y * 24;
    __shared__ float sW[32][24];
    float acc[24];
#pragma unroll
    for (int j = 0; j < 24; j++) acc[j] = 0.f;
    for (int k0 = 0; k0 < DI; k0 += 32) {
        for (int i = threadIdx.x; i < 32 * 24; i += 256)
            sW[i / 24][i % 24] = Wx[(size_t)(k0 + i / 24) * 48 + j0 + (i % 24)];
        __syncthreads();
#pragma unroll
        for (int kk = 0; kk < 32; kk++) {
            float xv = g_xm[(size_t)(k0 + kk) * TOK + m];
#pragma unroll
            for (int j = 0; j < 24; j++) acc[j] += xv * sW[kk][j];
        }
        __syncthreads();
    }
#pragma unroll
    for (int j = 0; j < 24; j++) g_dbc[(size_t)(j0 + j) * TOK + m] = acc[j];
}

// ---------------- dt: g_delta[d][m] = softplus(sum_r g_dbc[r][m]*w_dt[r][d] + b_dt[d]) ----------------
__global__ __launch_bounds__(256) void k_dt(const float* __restrict__ Wdt,
                                            const float* __restrict__ bdt) {
    __shared__ float sW[16][64];
    __shared__ float sb[64];
    int m = blockIdx.x * 256 + threadIdx.x;
    int d0 = blockIdx.y * 64;
    for (int i = threadIdx.x; i < 16 * 64; i += 256)
        sW[i >> 6][i & 63] = Wdt[(size_t)(i >> 6) * DI + d0 + (i & 63)];
    if (threadIdx.x < 64) sb[threadIdx.x] = bdt[d0 + threadIdx.x];
    __syncthreads();
    float r[16];
#pragma unroll
    for (int i = 0; i < 16; i++) r[i] = g_dbc[(size_t)i * TOK + m];
    for (int dd = 0; dd < 64; dd++) {
        float acc = sb[dd];
#pragma unroll
        for (int i = 0; i < 16; i++) acc += r[i] * sW[i][dd];
        g_delta[(size_t)(d0 + dd) * TOK + m] = softplusf(acc);
    }
}

// ---------------- selective scan over t (L=16), fused D-skip + silu(res) gate ----------------
__global__ __launch_bounds__(256) void k_scan(const float* __restrict__ A_log,
                                              const float* __restrict__ Dv) {
    int tx = threadIdx.x;                 // b within 32-chunk
    int ty = threadIdx.y;                 // d within 8-group
    int b0 = blockIdx.x * 32;
    int d = blockIdx.y * 8 + ty;
    int tid = ty * 32 + tx;

    float A_[16];
#pragma unroll
    for (int n = 0; n < 16; n++) A_[n] = -__expf(A_log[d * 16 + n]);
    float Dd = Dv[d];

    float h[16];
#pragma unroll
    for (int n = 0; n < 16; n++) h[n] = 0.f;

    __shared__ float sB[16][32];
    __shared__ float sC[16][32];

    for (int t = 0; t < NT; t++) {
        int tokbase = t * NB + b0;
        // stage B (rows 16..31) and C (rows 32..47) for these 32 b's
#pragma unroll
        for (int q = 0; q < 4; q++) {
            int idx = tid + q * 256;
            int j = idx >> 5;
            int bl = idx & 31;
            float v = g_dbc[(size_t)(16 + j) * TOK + tokbase + bl];
            if (j < 16) sB[j][bl] = v;
            else        sC[j - 16][bl] = v;
        }
        __syncthreads();

        int tok = tokbase + tx;
        size_t off = (size_t)d * TOK + tok;
        float dlt = g_delta[off];
        float xv = g_xm[off];
        float dxu = dlt * xv;
        float y = 0.f;
#pragma unroll
        for (int n = 0; n < 16; n++) {
            float dA = __expf(dlt * A_[n]);
            h[n] = dA * h[n] + dxu * sB[n][tx];
            y += h[n] * sC[n][tx];
        }
        g_y[off] = (y + xv * Dd) * g_sres[off];
        __syncthreads();
    }
}

// ---------------- GEMM out: out[c][m] = sum_d w_out[d][c]*g_y[d][m] + feature ----------------
__global__ __launch_bounds__(256) void k_gemmout(const float* __restrict__ W,
                                                 const float* __restrict__ feat,
                                                 float* __restrict__ out) {
    __shared__ float sW[8][128];
    __shared__ float sX[8][128];
    int bm = blockIdx.x * 128, bn = blockIdx.y * 128;
    int tid = threadIdx.x;
    int txm = tid & 15, tyn = tid >> 4;
    float acc[8][8];
#pragma unroll
    for (int i = 0; i < 8; i++)
#pragma unroll
        for (int j = 0; j < 8; j++) acc[i][j] = 0.f;

    int lr = tid >> 5;
    int lc = (tid & 31) * 4;
    const float* Wp = W + (size_t)lr * DM + bn + lc;
    const float* Xp = g_y + (size_t)lr * TOK + bm + lc;

    for (int k0 = 0; k0 < DI; k0 += 8) {
        *(float4*)&sW[lr][lc] = *(const float4*)(Wp + (size_t)k0 * DM);
        *(float4*)&sX[lr][lc] = *(const float4*)(Xp + (size_t)k0 * TOK);
        __syncthreads();
#pragma unroll
        for (int k = 0; k < 8; k++) {
            float a[8], bb[8];
            *(float4*)&a[0] = *(const float4*)&sW[k][tyn * 4];
            *(float4*)&a[4] = *(const float4*)&sW[k][64 + tyn * 4];
            *(float4*)&bb[0] = *(const float4*)&sX[k][txm * 4];
            *(float4*)&bb[4] = *(const float4*)&sX[k][64 + txm * 4];
#pragma unroll
            for (int i = 0; i < 8; i++)
#pragma unroll
                for (int j = 0; j < 8; j++) acc[i][j] += a[i] * bb[j];
        }
        __syncthreads();
    }
#pragma unroll
    for (int i = 0; i < 8; i++) {
        int n = bn + ((i < 4) ? (tyn * 4 + i) : (64 + tyn * 4 + i - 4));  // channel c
#pragma unroll
        for (int jq = 0; jq < 2; jq++) {
            int m = bm + ((jq == 0) ? (txm * 4) : (64 + txm * 4));
            int t = m >> 10;
            int b = m & 1023;
            size_t off = (size_t)t * DM * NB + (size_t)n * NB + b;
            float4 r = *(const float4*)&feat[off];
            float4 v;
            v.x = acc[i][jq * 4 + 0] + r.x;
            v.y = acc[i][jq * 4 + 1] + r.y;
            v.z = acc[i][jq * 4 + 2] + r.z;
            v.w = acc[i][jq * 4 + 3] + r.w;
            *(float4*)&out[off] = v;
        }
    }
}

extern "C" void kernel_launch(void* const* d_in, const int* in_sizes, int n_in,
                              void* d_out, int out_size) {
    const float* feature = (const float*)d_in[0];
    const float* norm_w  = (const float*)d_in[1];
    const float* w_in    = (const float*)d_in[2];
    const float* conv_w  = (const float*)d_in[3];
    const float* conv_b  = (const float*)d_in[4];
    const float* w_xproj = (const float*)d_in[5];
    const float* w_dt    = (const float*)d_in[6];
    const float* b_dt    = (const float*)d_in[7];
    const float* A_log   = (const float*)d_in[8];
    const float* Dv      = (const float*)d_in[9];
    const float* w_out   = (const float*)d_in[10];
    float* out = (float*)d_out;

    k_rmsnorm<<<dim3(32, 16), dim3(32, 8)>>>(feature, norm_w);
    k_gemm1<<<dim3(128, 8), 256>>>(w_in);
    k_conv<<<dim3(64, 512), 256>>>(conv_w, conv_b);
    k_xproj<<<dim3(64, 2), 256>>>(w_xproj);
    k_dt<<<dim3(64, 8), 256>>>(w_dt, b_dt);
    k_scan<<<dim3(32, 64), dim3(32, 8)>>>(A_log, Dv);
    k_gemmout<<<dim3(128, 2), 256>>>(w_out, feature, out);
}

// round 3
// speedup vs baseline: 1.0037x; 1.0037x over previous
#include <cuda_runtime.h>

#define NB 1024      // number of sequences (spatial positions)
#define NT 16        // sequence length (original batch)
#define TOK 16384    // NB*NT tokens, token = t*NB + b
#define DM 256       // d_model
#define DI 512       // d_inner
#define DS 16        // d_state
#define DR 16        // dt_rank

// ---- scratch (channel-major [C][token], token contiguous) ----
__device__ float g_xn[DM * TOK];      // rmsnorm output
__device__ float g_u[DI * TOK];       // pre-conv xm (first half of GEMM1)
__device__ float g_sres[DI * TOK];    // silu(res) (second half of GEMM1)
__device__ float g_xm[DI * TOK];      // post conv+silu
__device__ float g_dbc[48 * TOK];     // rows 0..15 delta_in, 16..31 B, 32..47 C
__device__ float g_delta[DI * TOK];   // softplus(delta_in @ w_dt + b_dt)
__device__ float g_y[DI * TOK];       // scan output * silu(res)

__device__ __forceinline__ float siluf(float x) {
    return __fdividef(x, 1.f + __expf(-x));
}
__device__ __forceinline__ float softplusf(float x) {
    float ax = fabsf(x);
    return fmaxf(x, 0.f) + __logf(1.f + __expf(-ax));
}

// ---------------- RMSNorm: feature [t][c][b] -> g_xn[c][t*NB+b] ----------------
__global__ __launch_bounds__(256) void k_rmsnorm(const float* __restrict__ feat,
                                                 const float* __restrict__ nw) {
    int t = blockIdx.y;
    int tx = threadIdx.x;            // b within chunk of 32
    int ty = threadIdx.y;            // 0..7
    int b = blockIdx.x * 32 + tx;
    const float* base = feat + (size_t)t * DM * NB + b;
    float v[32];
    float ss = 0.f;
#pragma unroll
    for (int i = 0; i < 32; i++) {
        int c = ty + i * 8;
        float x = base[(size_t)c * NB];
        v[i] = x;
        ss += x * x;
    }
    __shared__ float sred[8][32];
    sred[ty][tx] = ss;
    __syncthreads();
    float tot = 0.f;
#pragma unroll
    for (int j = 0; j < 8; j++) tot += sred[j][tx];
    float sc = rsqrtf(tot * (1.f / DM) + 1e-5f);
    int tok = t * NB + b;
#pragma unroll
    for (int i = 0; i < 32; i++) {
        int c = ty + i * 8;
        g_xn[(size_t)c * TOK + tok] = v[i] * sc * nw[c];
    }
}

// ---------------- GEMM1: out[n][m] = sum_k w_in[k][n] * g_xn[k][m] ----------------
// n<512 -> g_u raw ; n>=512 -> g_sres = silu
__global__ __launch_bounds__(256) void k_gemm1(const float* __restrict__ W) {
    __shared__ float sW[8][128];
    __shared__ float sX[8][128];
    int bm = blockIdx.x * 128, bn = blockIdx.y * 128;
    int tid = threadIdx.x;
    int txm = tid & 15, tyn = tid >> 4;
    float acc[8][8];
#pragma unroll
    for (int i = 0; i < 8; i++)
#pragma unroll
        for (int j = 0; j < 8; j++) acc[i][j] = 0.f;

    int lr = tid >> 5;
    int lc = (tid & 31) * 4;
    const float* Wp = W + (size_t)lr * 1024 + bn + lc;
    const float* Xp = g_xn + (size_t)lr * TOK + bm + lc;

    for (int k0 = 0; k0 < DM; k0 += 8) {
        *(float4*)&sW[lr][lc] = *(const float4*)(Wp + (size_t)k0 * 1024);
        *(float4*)&sX[lr][lc] = *(const float4*)(Xp + (size_t)k0 * TOK);
        __syncthreads();
#pragma unroll
        for (int k = 0; k < 8; k++) {
            float a[8], bb[8];
            *(float4*)&a[0] = *(const float4*)&sW[k][tyn * 4];
            *(float4*)&a[4] = *(const float4*)&sW[k][64 + tyn * 4];
            *(float4*)&bb[0] = *(const float4*)&sX[k][txm * 4];
            *(float4*)&bb[4] = *(const float4*)&sX[k][64 + txm * 4];
#pragma unroll
            for (int i = 0; i < 8; i++)
#pragma unroll
                for (int j = 0; j < 8; j++) acc[i][j] += a[i] * bb[j];
        }
        __syncthreads();
    }
    bool isRes = (bn >= DI);
#pragma unroll
    for (int i = 0; i < 8; i++) {
        int n = bn + ((i < 4) ? (tyn * 4 + i) : (64 + tyn * 4 + i - 4));
#pragma unroll
        for (int jq = 0; jq < 2; jq++) {
            int m = bm + ((jq == 0) ? (txm * 4) : (64 + txm * 4));
            float4 v;
            v.x = acc[i][jq * 4 + 0]; v.y = acc[i][jq * 4 + 1];
            v.z = acc[i][jq * 4 + 2]; v.w = acc[i][jq * 4 + 3];
            if (!isRes) {
                *(float4*)&g_u[(size_t)n * TOK + m] = v;
            } else {
                v.x = siluf(v.x); v.y = siluf(v.y); v.z = siluf(v.z); v.w = siluf(v.w);
                *(float4*)&g_sres[(size_t)(n - DI) * TOK + m] = v;
            }
        }
    }
}

// ---------------- depthwise causal conv (k=3) over t + silu ----------------
__global__ __launch_bounds__(256) void k_conv(const float* __restrict__ cw,
                                              const float* __restrict__ cb) {
    int m = blockIdx.x * 256 + threadIdx.x;
    int d = blockIdx.y;
    int t = m >> 10;
    float w0 = cw[d * 3 + 0], w1 = cw[d * 3 + 1], w2 = cw[d * 3 + 2];
    size_t base = (size_t)d * TOK + m;
    float acc = cb[d] + w2 * g_u[base];
    if (t >= 1) acc += w1 * g_u[base - NB];
    if (t >= 2) acc += w0 * g_u[base - 2 * NB];
    g_xm[base] = siluf(acc);
}

// ---------------- xproj: g_dbc[j][m] = sum_d w_xproj[d][j] * g_xm[d][m] ----------------
__global__ __launch_bounds__(256) void k_xproj(const float* __restrict__ Wx) {
    int m = blockIdx.x * 256 + threadIdx.x;
    int j0 = blockIdx.y * 24;
    __shared__ float sW[32][24];
    float acc[24];
#pragma unroll
    for (int j = 0; j < 24; j++) acc[j] = 0.f;
    for (int k0 = 0; k0 < DI; k0 += 32) {
        for (int i = threadIdx.x; i < 32 * 24; i += 256)
            sW[i / 24][i % 24] = Wx[(size_t)(k0 + i / 24) * 48 + j0 + (i % 24)];
        __syncthreads();
#pragma unroll
        for (int kk = 0; kk < 32; kk++) {
            float xv = g_xm[(size_t)(k0 + kk) * TOK + m];
#pragma unroll
            for (int j = 0; j < 24; j++) acc[j] += xv * sW[kk][j];
        }
        __syncthreads();
    }
#pragma unroll
    for (int j = 0; j < 24; j++) g_dbc[(size_t)(j0 + j) * TOK + m] = acc[j];
}

// ---------------- dt: g_delta[d][m] = softplus(sum_r g_dbc[r][m]*w_dt[r][d] + b_dt[d]) ----------------
__global__ __launch_bounds__(256) void k_dt(const float* __restrict__ Wdt,
                                            const float* __restrict__ bdt) {
    __shared__ float sW[16][64];
    __shared__ float sb[64];
    int m = blockIdx.x * 256 + threadIdx.x;
    int d0 = blockIdx.y * 64;
    for (int i = threadIdx.x; i < 16 * 64; i += 256)
        sW[i >> 6][i & 63] = Wdt[(size_t)(i >> 6) * DI + d0 + (i & 63)];
    if (threadIdx.x < 64) sb[threadIdx.x] = bdt[d0 + threadIdx.x];
    __syncthreads();
    float r[16];
#pragma unroll
    for (int i = 0; i < 16; i++) r[i] = g_dbc[(size_t)i * TOK + m];
    for (int dd = 0; dd < 64; dd++) {
        float acc = sb[dd];
#pragma unroll
        for (int i = 0; i < 16; i++) acc += r[i] * sW[i][dd];
        g_delta[(size_t)(d0 + dd) * TOK + m] = softplusf(acc);
    }
}

// ---------------- selective scan over t (L=16), fused D-skip + silu(res) gate ----------------
__global__ __launch_bounds__(256) void k_scan(const float* __restrict__ A_log,
                                              const float* __restrict__ Dv) {
    int tx = threadIdx.x;                 // b within 32-chunk
    int ty = threadIdx.y;                 // d within 8-group
    int b0 = blockIdx.x * 32;
    int d = blockIdx.y * 8 + ty;
    int tid = ty * 32 + tx;

    float A_[16];
#pragma unroll
    for (int n = 0; n < 16; n++) A_[n] = -__expf(A_log[d * 16 + n]);
    float Dd = Dv[d];

    float h[16];
#pragma unroll
    for (int n = 0; n < 16; n++) h[n] = 0.f;

    __shared__ float sB[16][32];
    __shared__ float sC[16][32];

    for (int t = 0; t < NT; t++) {
        int tokbase = t * NB + b0;
        // stage B (rows 16..31) and C (rows 32..47) for these 32 b's
#pragma unroll
        for (int q = 0; q < 4; q++) {
            int idx = tid + q * 256;
            int j = idx >> 5;
            int bl = idx & 31;
            float v = g_dbc[(size_t)(16 + j) * TOK + tokbase + bl];
            if (j < 16) sB[j][bl] = v;
            else        sC[j - 16][bl] = v;
        }
        __syncthreads();

        int tok = tokbase + tx;
        size_t off = (size_t)d * TOK + tok;
        float dlt = g_delta[off];
        float xv = g_xm[off];
        float dxu = dlt * xv;
        float y = 0.f;
#pragma unroll
        for (int n = 0; n < 16; n++) {
            float dA = __expf(dlt * A_[n]);
            h[n] = dA * h[n] + dxu * sB[n][tx];
            y += h[n] * sC[n][tx];
        }
        g_y[off] = (y + xv * Dd) * g_sres[off];
        __syncthreads();
    }
}

// ---------------- GEMM out: out[c][m] = sum_d w_out[d][c]*g_y[d][m] + feature ----------------
__global__ __launch_bounds__(256) void k_gemmout(const float* __restrict__ W,
                                                 const float* __restrict__ feat,
                                                 float* __restrict__ out) {
    __shared__ float sW[8][128];
    __shared__ float sX[8][128];
    int bm = blockIdx.x * 128, bn = blockIdx.y * 128;
    int tid = threadIdx.x;
    int txm = tid & 15, tyn = tid >> 4;
    float acc[8][8];
#pragma unroll
    for (int i = 0; i < 8; i++)
#pragma unroll
        for (int j = 0; j < 8; j++) acc[i][j] = 0.f;

    int lr = tid >> 5;
    int lc = (tid & 31) * 4;
    const float* Wp = W + (size_t)lr * DM + bn + lc;
    const float* Xp = g_y + (size_t)lr * TOK + bm + lc;

    for (int k0 = 0; k0 < DI; k0 += 8) {
        *(float4*)&sW[lr][lc] = *(const float4*)(Wp + (size_t)k0 * DM);
        *(float4*)&sX[lr][lc] = *(const float4*)(Xp + (size_t)k0 * TOK);
        __syncthreads();
#pragma unroll
        for (int k = 0; k < 8; k++) {
            float a[8], bb[8];
            *(float4*)&a[0] = *(const float4*)&sW[k][tyn * 4];
            *(float4*)&a[4] = *(const float4*)&sW[k][64 + tyn * 4];
            *(float4*)&bb[0] = *(const float4*)&sX[k][txm * 4];
            *(float4*)&bb[4] = *(const float4*)&sX[k][64 + txm * 4];
#pragma unroll
            for (int i = 0; i < 8; i++)
#pragma unroll
                for (int j = 0; j < 8; j++) acc[i][j] += a[i] * bb[j];
        }
        __syncthreads();
    }
#pragma unroll
    for (int i = 0; i < 8; i++) {
        int n = bn + ((i < 4) ? (tyn * 4 + i) : (64 + tyn * 4 + i - 4));  // channel c
#pragma unroll
        for (int jq = 0; jq < 2; jq++) {
            int m = bm + ((jq == 0) ? (txm * 4) : (64 + txm * 4));
            int t = m >> 10;
            int b = m & 1023;
            size_t off = (size_t)t * DM * NB + (size_t)n * NB + b;
            float4 r = *(const float4*)&feat[off];
            float4 v;
            v.x = acc[i][jq * 4 + 0] + r.x;
            v.y = acc[i][jq * 4 + 1] + r.y;
            v.z = acc[i][jq * 4 + 2] + r.z;
            v.w = acc[i][jq * 4 + 3] + r.w;
            *(float4*)&out[off] = v;
        }
    }
}

extern "C" void kernel_launch(void* const* d_in, const int* in_sizes, int n_in,
                              void* d_out, int out_size) {
    const float* feature = (const float*)d_in[0];
    const float* norm_w  = (const float*)d_in[1];
    const float* w_in    = (const float*)d_in[2];
    const float* conv_w  = (const float*)d_in[3];
    const float* conv_b  = (const float*)d_in[4];
    const float* w_xproj = (const float*)d_in[5];
    const float* w_dt    = (const float*)d_in[6];
    const float* b_dt    = (const float*)d_in[7];
    const float* A_log   = (const float*)d_in[8];
    const float* Dv      = (const float*)d_in[9];
    const float* w_out   = (const float*)d_in[10];
    float* out = (float*)d_out;

    k_rmsnorm<<<dim3(32, 16), dim3(32, 8)>>>(feature, norm_w);
    k_gemm1<<<dim3(128, 8), 256>>>(w_in);
    k_conv<<<dim3(64, 512), 256>>>(conv_w, conv_b);
    k_xproj<<<dim3(64, 2), 256>>>(w_xproj);
    k_dt<<<dim3(64, 8), 256>>>(w_dt, b_dt);
    k_scan<<<dim3(32, 64), dim3(32, 8)>>>(A_log, Dv);
    k_gemmout<<<dim3(128, 2), 256>>>(w_out, feature, out);
}

// round 5
// speedup vs baseline: 1.4844x; 1.4789x over previous
#include <cuda_runtime.h>
#include <cuda_bf16.h>
#include <cstdint>

#define NB 1024      // sequences (spatial positions)
#define NT 16        // sequence length (original batch)
#define TOK 16384    // NB*NT tokens, token = t*NB + b
#define DM 256
#define DI 512

// ---------------- scratch (__device__ globals; no allocations) ----------------
__device__ __align__(128) __nv_bfloat16 g_winT[1024 * 256];   // w_in^T  [n][k=256]
__device__ __align__(128) __nv_bfloat16 g_woutT[256 * 512];   // w_out^T [c][d=512]
__device__ __align__(128) __nv_bfloat16 g_wxT[48 * 512];      // w_xproj^T [j][d=512]
__device__ __align__(128) __nv_bfloat16 g_xnbf[TOK * DM];     // rmsnorm out, token-major [m][k]
__device__ __align__(128) __nv_bfloat16 g_uh[DI * TOK];       // pre-conv, channel-major [d][m]
__device__ __align__(128) __nv_bfloat16 g_sresh[DI * TOK];    // silu(res), channel-major
__device__ __align__(128) __nv_bfloat16 g_xmh[DI * TOK];      // post conv+silu, channel-major
__device__ __align__(128) __nv_bfloat16 g_xmbf[TOK * DI];     // same, token-major [m][d]
__device__ __align__(128) float         g_dbc[48 * TOK];      // channel-major [j][m]
__device__ __align__(128) __nv_bfloat16 g_ybf[TOK * DI];      // gated scan out, token-major

// ---------------- helpers ----------------
__device__ __forceinline__ uint32_t smem_u32(const void* p) {
    uint32_t a;
    asm("{ .reg .u64 t; cvta.to.shared.u64 t, %1; cvt.u32.u64 %0, t; }" : "=r"(a) : "l"(p));
    return a;
}
__device__ __forceinline__ float siluf(float x) { return __fdividef(x, 1.f + __expf(-x)); }
__device__ __forceinline__ float softplusf(float x) {
    return fmaxf(x, 0.f) + __logf(1.f + __expf(-fabsf(x)));
}
__device__ __forceinline__ uint32_t packbf(float a, float b) {
    __nv_bfloat162 t = __floats2bfloat162_rn(a, b);
    return *reinterpret_cast<uint32_t*>(&t);
}

#define LDSM_X4(r0, r1, r2, r3, addr) \
    asm volatile("ldmatrix.sync.aligned.m8n8.x4.shared.b16 {%0,%1,%2,%3}, [%4];" \
                 : "=r"(r0), "=r"(r1), "=r"(r2), "=r"(r3) : "r"(addr))

__device__ __forceinline__ void mma_bf16(float* c, uint32_t a0, uint32_t a1, uint32_t a2,
                                         uint32_t a3, uint32_t b0, uint32_t b1) {
    asm volatile(
        "mma.sync.aligned.m16n8k16.row.col.f32.bf16.bf16.f32 "
        "{%0,%1,%2,%3}, {%4,%5,%6,%7}, {%8,%9}, {%0,%1,%2,%3};"
        : "+f"(c[0]), "+f"(c[1]), "+f"(c[2]), "+f"(c[3])
        : "r"(a0), "r"(a1), "r"(a2), "r"(a3), "r"(b0), "r"(b1));
}

__device__ __forceinline__ uint32_t swz(uint32_t off) { return off ^ ((off >> 3) & 0x70); }

// load a [ROWS x 64] bf16 chunk (K-major rows, leading dim ld) into swizzled smem (128B rows)
template <int ROWS>
__device__ __forceinline__ void ldchunk(const __nv_bfloat16* __restrict__ g, int row0, int ld,
                                        int k0, char* sm, int tid) {
    for (int u = tid; u < ROWS * 8; u += 256) {
        int r = u >> 3, q = u & 7;
        uint4 v = *(const uint4*)(g + (size_t)(row0 + r) * ld + k0 + q * 8);
        *(uint4*)(sm + swz(r * 128 + q * 16)) = v;
    }
}

// A-fragment (16x16 tile at feature row f, k-byte kb) from swizzled smem
#define LOAD_AFRAG(a, sb, f, kb, lane)                                              \
    do {                                                                            \
        uint32_t off = (uint32_t)(((f) + ((lane) & 15)) * 128 + (kb) + (((lane) >> 4) << 4)); \
        LDSM_X4((a)[0], (a)[1], (a)[2], (a)[3], (sb) + swz(off));                   \
    } while (0)

// B-fragments for two adjacent n-tiles (16 rows at n0, k-byte kb)
#define LOAD_BFRAG(b0a, b0b, b1a, b1b, sb, n0, kb, lane)                            \
    do {                                                                            \
        int r = (n0) + ((lane) & 7) + (((lane) >> 4) << 3);                         \
        uint32_t off = (uint32_t)(r * 128 + (kb) + (((lane) >> 3) & 1) * 16);       \
        LDSM_X4(b0a, b0b, b1a, b1b, (sb) + swz(off));                               \
    } while (0)

// ---------------- weight transpose fp32 -> bf16 ----------------
__global__ __launch_bounds__(256) void k_transpose(const float* __restrict__ in,
                                                   int R, int C, int which) {
    __nv_bfloat16* out = (which == 0) ? g_winT : ((which == 1) ? g_woutT : g_wxT);
    __shared__ float tile[32][33];
    int c0 = blockIdx.x * 32, r0 = blockIdx.y * 32;
    int tx = threadIdx.x, ty = threadIdx.y;
#pragma unroll
    for (int i = 0; i < 4; i++) {
        int r = r0 + ty + 8 * i;
        if (r < R && c0 + tx < C) tile[ty + 8 * i][tx] = in[(size_t)r * C + c0 + tx];
    }
    __syncthreads();
#pragma unroll
    for (int i = 0; i < 4; i++) {
        int c = c0 + ty + 8 * i;
        if (c < C && r0 + tx < R)
            out[(size_t)c * R + r0 + tx] = __float2bfloat16(tile[tx][ty + 8 * i]);
    }
}

// ---------------- RMSNorm: feature [t][c][b] -> g_xnbf[m][c] bf16 token-major ----------------
__global__ __launch_bounds__(256) void k_rmsnorm(const float* __restrict__ feat,
                                                 const float* __restrict__ nw) {
    __shared__ float sred[8][32];
    __shared__ __align__(16) __nv_bfloat16 sX[32][264];
    int tx = threadIdx.x, ty = threadIdx.y;
    int t = blockIdx.y;
    int b = blockIdx.x * 32 + tx;
    const float* base = feat + (size_t)t * DM * NB + b;
    float v[32];
    float ss = 0.f;
#pragma unroll
    for (int i = 0; i < 32; i++) {
        float x = base[(size_t)(ty + 8 * i) * NB];
        v[i] = x;
        ss += x * x;
    }
    sred[ty][tx] = ss;
    __syncthreads();
    float tot = 0.f;
#pragma unroll
    for (int j = 0; j < 8; j++) tot += sred[j][tx];
    float sc = rsqrtf(tot * (1.f / DM) + 1e-5f);
#pragma unroll
    for (int i = 0; i < 32; i++)
        sX[tx][ty + 8 * i] = __float2bfloat16(v[i] * sc * nw[ty + 8 * i]);
    __syncthreads();
    int tid = ty * 32 + tx;
    size_t tok0 = (size_t)t * NB + blockIdx.x * 32;
    for (int u = tid; u < 32 * 32; u += 256) {
        int r = u >> 5, q = u & 31;
        *(uint4*)(g_xnbf + (tok0 + r) * DM + q * 8) = *(uint4*)&sX[r][q * 8];
    }
}

// ---------------- GEMM1 (HMMA): D[n][m] = w_inT[n][:] . xn[m][:] ----------------
// block: 128 features x 128 tokens, K=256 in 4 chunks of 64
__global__ __launch_bounds__(256, 1) void k_gemm1() {
    __shared__ __align__(16) char sA[128 * 128];
    __shared__ __align__(16) char sB[128 * 128];
    int tid = threadIdx.x, wid = tid >> 5, lane = tid & 31;
    int wy = wid >> 2, wx = wid & 3;                   // warp: 64 feats x 32 toks
    int fbase = blockIdx.y * 128, tbase = blockIdx.x * 128;
    uint32_t sbA = smem_u32(sA), sbB = smem_u32(sB);
    float acc[4][4][4];
#pragma unroll
    for (int i = 0; i < 4; i++)
#pragma unroll
        for (int j = 0; j < 4; j++)
#pragma unroll
            for (int q = 0; q < 4; q++) acc[i][j][q] = 0.f;

    for (int kc = 0; kc < 4; kc++) {
        ldchunk<128>(g_winT, fbase, 256, kc * 64, sA, tid);
        ldchunk<128>(g_xnbf, tbase, 256, kc * 64, sB, tid);
        __syncthreads();
#pragma unroll
        for (int ks = 0; ks < 4; ks++) {
            int kb = ks * 32;
            uint32_t a[4][4], b[4][2];
#pragma unroll
            for (int ft = 0; ft < 4; ft++) LOAD_AFRAG(a[ft], sbA, wy * 64 + ft * 16, kb, lane);
#pragma unroll
            for (int np = 0; np < 2; np++)
                LOAD_BFRAG(b[np * 2][0], b[np * 2][1], b[np * 2 + 1][0], b[np * 2 + 1][1],
                           sbB, wx * 32 + np * 16, kb, lane);
#pragma unroll
            for (int ft = 0; ft < 4; ft++)
#pragma unroll
                for (int nt = 0; nt < 4; nt++)
                    mma_bf16(acc[ft][nt], a[ft][0], a[ft][1], a[ft][2], a[ft][3],
                             b[nt][0], b[nt][1]);
        }
        __syncthreads();
    }

    bool isRes = (fbase >= DI);
    __nv_bfloat16* base = isRes ? g_sresh : g_uh;
    int fb = isRes ? (fbase - DI) : fbase;
#pragma unroll
    for (int ft = 0; ft < 4; ft++) {
#pragma unroll
        for (int nt = 0; nt < 4; nt++) {
            float* c = acc[ft][nt];
            int f = fb + wy * 64 + ft * 16 + (lane >> 2);
            int m = tbase + wx * 32 + nt * 8 + (lane & 3) * 2;
            if (isRes) {
                *(uint32_t*)(base + (size_t)f * TOK + m)       = packbf(siluf(c[0]), siluf(c[1]));
                *(uint32_t*)(base + (size_t)(f + 8) * TOK + m) = packbf(siluf(c[2]), siluf(c[3]));
            } else {
                *(uint32_t*)(base + (size_t)f * TOK + m)       = packbf(c[0], c[1]);
                *(uint32_t*)(base + (size_t)(f + 8) * TOK + m) = packbf(c[2], c[3]);
            }
        }
    }
}

// ---------------- depthwise causal conv (k=3) + silu; dual-layout output ----------------
__global__ __launch_bounds__(256) void k_conv(const float* __restrict__ cw,
                                              const float* __restrict__ cb) {
    __shared__ __nv_bfloat16 sT[32][33];
    int tx = threadIdx.x, ty = threadIdx.y;
    int m = blockIdx.x * 32 + tx;
    int d0 = blockIdx.y * 32;
    int t = m >> 10;
#pragma unroll
    for (int i = 0; i < 4; i++) {
        int d = d0 + ty + 8 * i;
        size_t base = (size_t)d * TOK + m;
        float acc = cb[d] + cw[d * 3 + 2] * __bfloat162float(g_uh[base]);
        if (t >= 1) acc += cw[d * 3 + 1] * __bfloat162float(g_uh[base - NB]);
        if (t >= 2) acc += cw[d * 3 + 0] * __bfloat162float(g_uh[base - 2 * NB]);
        __nv_bfloat16 hb = __float2bfloat16(siluf(acc));
        g_xmh[base] = hb;
        sT[ty + 8 * i][tx] = hb;
    }
    __syncthreads();
#pragma unroll
    for (int i = 0; i < 4; i++) {
        int mm = blockIdx.x * 32 + ty + 8 * i;
        g_xmbf[(size_t)mm * DI + d0 + tx] = sT[tx][ty + 8 * i];
    }
}

// ---------------- xproj (HMMA): dbc[j][m] = wxT[j][:] . xm[m][:]  (channel-major out) ----------------
// block: 48 features x 128 tokens, K=512 in 8 chunks; warp = 48 x 16 toks
__global__ __launch_bounds__(256, 1) void k_xproj() {
    __shared__ __align__(16) char sA[48 * 128];
    __shared__ __align__(16) char sB[128 * 128];
    int tid = threadIdx.x, wid = tid >> 5, lane = tid & 31;
    int tbase = blockIdx.x * 128;
    uint32_t sbA = smem_u32(sA), sbB = smem_u32(sB);
    float acc[3][2][4];
#pragma unroll
    for (int i = 0; i < 3; i++)
#pragma unroll
        for (int j = 0; j < 2; j++)
#pragma unroll
            for (int q = 0; q < 4; q++) acc[i][j][q] = 0.f;

    for (int kc = 0; kc < 8; kc++) {
        ldchunk<48>(g_wxT, 0, 512, kc * 64, sA, tid);
        ldchunk<128>(g_xmbf, tbase, 512, kc * 64, sB, tid);
        __syncthreads();
#pragma unroll
        for (int ks = 0; ks < 4; ks++) {
            int kb = ks * 32;
            uint32_t a[3][4], b[2][2];
#pragma unroll
            for (int ft = 0; ft < 3; ft++) LOAD_AFRAG(a[ft], sbA, ft * 16, kb, lane);
            LOAD_BFRAG(b[0][0], b[0][1], b[1][0], b[1][1], sbB, wid * 16, kb, lane);
#pragma unroll
            for (int ft = 0; ft < 3; ft++)
#pragma unroll
                for (int nt = 0; nt < 2; nt++)
                    mma_bf16(acc[ft][nt], a[ft][0], a[ft][1], a[ft][2], a[ft][3],
                             b[nt][0], b[nt][1]);
        }
        __syncthreads();
    }
#pragma unroll
    for (int ft = 0; ft < 3; ft++) {
#pragma unroll
        for (int nt = 0; nt < 2; nt++) {
            float* c = acc[ft][nt];
            int j = ft * 16 + (lane >> 2);
            int m = tbase + wid * 16 + nt * 8 + (lane & 3) * 2;
            float2 v0; v0.x = c[0]; v0.y = c[1];
            float2 v1; v1.x = c[2]; v1.y = c[3];
            *(float2*)(g_dbc + (size_t)j * TOK + m) = v0;
            *(float2*)(g_dbc + (size_t)(j + 8) * TOK + m) = v1;
        }
    }
}

// ---------------- fused dt + selective scan + D-skip + silu gate ----------------
__global__ __launch_bounds__(256) void k_scan(const float* __restrict__ A_log,
                                              const float* __restrict__ Dv,
                                              const float* __restrict__ w_dt,
                                              const float* __restrict__ b_dt) {
    __shared__ float sAll[48][32];
    __shared__ float sWdt[16][8];
    __shared__ float sbdt[8];
    __shared__ __nv_bfloat16 sY[8][32];
    int tx = threadIdx.x, ty = threadIdx.y;
    int tid = ty * 32 + tx;
    int b0 = blockIdx.x * 32;
    int d0 = blockIdx.y * 8;
    int d = d0 + ty;
    if (tid < 128) sWdt[tid >> 3][tid & 7] = w_dt[(size_t)(tid >> 3) * DI + d0 + (tid & 7)];
    if (tid < 8) sbdt[tid] = b_dt[d0 + tid];
    float A_[16];
    bool fast = true;
#pragma unroll
    for (int n = 0; n < 16; n++) {
        A_[n] = -__expf(A_log[d * 16 + n]);
        fast = fast && (fabsf(A_[n] + (float)(n + 1)) < 1e-3f * (n + 1));
    }
    float Dd = Dv[d];
    float h[16];
#pragma unroll
    for (int n = 0; n < 16; n++) h[n] = 0.f;
    __syncthreads();

    for (int t = 0; t < NT; t++) {
        int tokbase = t * NB + b0;
        for (int u = tid; u < 48 * 32; u += 256) {
            int j = u >> 5, c = u & 31;
            sAll[j][c] = g_dbc[(size_t)j * TOK + tokbase + c];
        }
        __syncthreads();

        size_t off = (size_t)d * TOK + tokbase + tx;
        float dlt = sbdt[ty];
#pragma unroll
        for (int r = 0; r < 16; r++) dlt += sAll[r][tx] * sWdt[r][ty];
        dlt = softplusf(dlt);
        float xv = __bfloat162float(g_xmh[off]);
        float dxu = dlt * xv;
        float y = 0.f;
        if (fast) {
            float p = __expf(-dlt), pn = 1.f;
#pragma unroll
            for (int n = 0; n < 16; n++) {
                pn *= p;
                h[n] = pn * h[n] + dxu * sAll[16 + n][tx];
                y += h[n] * sAll[32 + n][tx];
            }
        } else {
#pragma unroll
            for (int n = 0; n < 16; n++) {
                float dA = __expf(dlt * A_[n]);
                h[n] = dA * h[n] + dxu * sAll[16 + n][tx];
                y += h[n] * sAll[32 + n][tx];
            }
        }
        float sres = __bfloat162float(g_sresh[off]);
        sY[ty][tx] = __float2bfloat16((y + xv * Dd) * sres);
        __syncthreads();
        int bl = tid >> 3, j = tid & 7;
        g_ybf[(size_t)(tokbase + bl) * DI + d0 + j] = sY[j][bl];
        __syncthreads();
    }
}

// ---------------- GEMM out (HMMA): out[c][m] = w_outT[c][:] . y[m][:] + feature ----------------
// block: 128 channels x 128 tokens, K=512 in 8 chunks
__global__ __launch_bounds__(256, 1) void k_gemmout(const float* __restrict__ feat,
                                                    float* __restrict__ out) {
    __shared__ __align__(16) char sA[128 * 128];
    __shared__ __align__(16) char sB[128 * 128];
    int tid = threadIdx.x, wid = tid >> 5, lane = tid & 31;
    int wy = wid >> 2, wx = wid & 3;
    int cbase = blockIdx.y * 128, tbase = blockIdx.x * 128;
    uint32_t sbA = smem_u32(sA), sbB = smem_u32(sB);
    float acc[4][4][4];
#pragma unroll
    for (int i = 0; i < 4; i++)
#pragma unroll
        for (int j = 0; j < 4; j++)
#pragma unroll
            for (int q = 0; q < 4; q++) acc[i][j][q] = 0.f;

    for (int kc = 0; kc < 8; kc++) {
        ldchunk<128>(g_woutT, cbase, 512, kc * 64, sA, tid);
        ldchunk<128>(g_ybf, tbase, 512, kc * 64, sB, tid);
        __syncthreads();
#pragma unroll
        for (int ks = 0; ks < 4; ks++) {
            int kb = ks * 32;
            uint32_t a[4][4], b[4][2];
#pragma unroll
            for (int ft = 0; ft < 4; ft++) LOAD_AFRAG(a[ft], sbA, wy * 64 + ft * 16, kb, lane);
#pragma unroll
            for (int np = 0; np < 2; np++)
                LOAD_BFRAG(b[np * 2][0], b[np * 2][1], b[np * 2 + 1][0], b[np * 2 + 1][1],
                           sbB, wx * 32 + np * 16, kb, lane);
#pragma unroll
            for (int ft = 0; ft < 4; ft++)
#pragma unroll
                for (int nt = 0; nt < 4; nt++)
                    mma_bf16(acc[ft][nt], a[ft][0], a[ft][1], a[ft][2], a[ft][3],
                             b[nt][0], b[nt][1]);
        }
        __syncthreads();
    }

    int t = tbase >> 10;              // whole block within one t (128 | 1024)
#pragma unroll
    for (int ft = 0; ft < 4; ft++) {
#pragma unroll
        for (int nt = 0; nt < 4; nt++) {
            float* c = acc[ft][nt];
            int cc = cbase + wy * 64 + ft * 16 + (lane >> 2);
            int m = tbase + wx * 32 + nt * 8 + (lane & 3) * 2;
            int b = m & 1023;
            size_t o0 = (size_t)t * DM * NB + (size_t)cc * NB + b;
            size_t o1 = o0 + 8 * (size_t)NB;
            float2 f0 = *(const float2*)(feat + o0);
            float2 f1 = *(const float2*)(feat + o1);
            float2 v0; v0.x = c[0] + f0.x; v0.y = c[1] + f0.y;
            float2 v1; v1.x = c[2] + f1.x; v1.y = c[3] + f1.y;
            *(float2*)(out + o0) = v0;
            *(float2*)(out + o1) = v1;
        }
    }
}

extern "C" void kernel_launch(void* const* d_in, const int* in_sizes, int n_in,
                              void* d_out, int out_size) {
    const float* feature = (const float*)d_in[0];
    const float* norm_w  = (const float*)d_in[1];
    const float* w_in    = (const float*)d_in[2];
    const float* conv_w  = (const float*)d_in[3];
    const float* conv_b  = (const float*)d_in[4];
    const float* w_xproj = (const float*)d_in[5];
    const float* w_dt    = (const float*)d_in[6];
    const float* b_dt    = (const float*)d_in[7];
    const float* A_log   = (const float*)d_in[8];
    const float* Dv      = (const float*)d_in[9];
    const float* w_out   = (const float*)d_in[10];
    float* out = (float*)d_out;

    k_transpose<<<dim3(32, 8), dim3(32, 8)>>>(w_in, 256, 1024, 0);
    k_transpose<<<dim3(8, 16), dim3(32, 8)>>>(w_out, 512, 256, 1);
    k_transpose<<<dim3(2, 16), dim3(32, 8)>>>(w_xproj, 512, 48, 2);
    k_rmsnorm<<<dim3(32, 16), dim3(32, 8)>>>(feature, norm_w);
    k_gemm1<<<dim3(128, 8), 256>>>();
    k_conv<<<dim3(512, 16), dim3(32, 8)>>>(conv_w, conv_b);
    k_xproj<<<dim3(128, 1), 256>>>();
    k_scan<<<dim3(32, 64), dim3(32, 8)>>>(A_log, Dv, w_dt, b_dt);
    k_gemmout<<<dim3(128, 2), 256>>>(feature, out);
}

// round 6
// speedup vs baseline: 2.0683x; 1.3934x over previous
#include <cuda_runtime.h>
#include <cuda_bf16.h>
#include <cstdint>

#define NB 1024      // sequences (spatial positions)
#define NT 16        // sequence length (original batch)
#define TOK 16384    // NB*NT tokens, token = t*NB + b
#define DM 256
#define DI 512

// ---------------- scratch (__device__ globals; no allocations) ----------------
__device__ __align__(128) __nv_bfloat16 g_winT[1024 * 256];   // w_in^T  [n][k=256]
__device__ __align__(128) __nv_bfloat16 g_woutT[256 * 512];   // w_out^T [c][d=512]
__device__ __align__(128) __nv_bfloat16 g_wxT[48 * 512];      // w_xproj^T [j][d=512]
__device__ __align__(128) __nv_bfloat16 g_xnbf[TOK * DM];     // rmsnorm out, token-major [m][k]
__device__ __align__(128) __nv_bfloat16 g_uh[DI * TOK];       // pre-conv, channel-major [d][m]
__device__ __align__(128) __nv_bfloat16 g_sresh[DI * TOK];    // silu(res), channel-major
__device__ __align__(128) __nv_bfloat16 g_xmh[DI * TOK];      // post conv+silu, channel-major
__device__ __align__(128) __nv_bfloat16 g_xmbf[TOK * DI];     // same, token-major [m][d]
__device__ __align__(128) float         g_dbc[48 * TOK];      // channel-major [j][m]
__device__ __align__(128) __nv_bfloat16 g_ybf[TOK * DI];      // gated scan out, token-major

// ---------------- helpers ----------------
__device__ __forceinline__ uint32_t smem_u32(const void* p) {
    uint32_t a;
    asm("{ .reg .u64 t; cvta.to.shared.u64 t, %1; cvt.u32.u64 %0, t; }" : "=r"(a) : "l"(p));
    return a;
}
__device__ __forceinline__ float siluf(float x) { return __fdividef(x, 1.f + __expf(-x)); }
__device__ __forceinline__ float softplusf(float x) {
    return fmaxf(x, 0.f) + __logf(1.f + __expf(-fabsf(x)));
}
__device__ __forceinline__ uint32_t packbf(float a, float b) {
    __nv_bfloat162 t = __floats2bfloat162_rn(a, b);
    return *reinterpret_cast<uint32_t*>(&t);
}

#define LDSM_X4(r0, r1, r2, r3, addr) \
    asm volatile("ldmatrix.sync.aligned.m8n8.x4.shared.b16 {%0,%1,%2,%3}, [%4];" \
                 : "=r"(r0), "=r"(r1), "=r"(r2), "=r"(r3) : "r"(addr))

__device__ __forceinline__ void mma_bf16(float* c, uint32_t a0, uint32_t a1, uint32_t a2,
                                         uint32_t a3, uint32_t b0, uint32_t b1) {
    asm volatile(
        "mma.sync.aligned.m16n8k16.row.col.f32.bf16.bf16.f32 "
        "{%0,%1,%2,%3}, {%4,%5,%6,%7}, {%8,%9}, {%0,%1,%2,%3};"
        : "+f"(c[0]), "+f"(c[1]), "+f"(c[2]), "+f"(c[3])
        : "r"(a0), "r"(a1), "r"(a2), "r"(a3), "r"(b0), "r"(b1));
}

__device__ __forceinline__ uint32_t swz(uint32_t off) { return off ^ ((off >> 3) & 0x70); }

#define CP16(dst, src) \
    asm volatile("cp.async.cg.shared.global [%0], [%1], 16;" :: "r"(dst), "l"(src))
#define CP_COMMIT() asm volatile("cp.async.commit_group;" ::: "memory")
#define CP_WAIT(n)  asm volatile("cp.async.wait_group %0;" :: "n"(n) : "memory")

// async-load a [ROWS x 64] bf16 chunk (K-major rows, leading dim ld) into swizzled smem
template <int ROWS>
__device__ __forceinline__ void ldchunk_async(const __nv_bfloat16* __restrict__ g, int row0,
                                              int ld, int k0, uint32_t sm, int tid) {
    for (int u = tid; u < ROWS * 8; u += 256) {
        int r = u >> 3, q = u & 7;
        const void* src = g + (size_t)(row0 + r) * ld + k0 + q * 8;
        CP16(sm + swz(r * 128 + q * 16), src);
    }
}

// A-fragment (16x16 tile at feature row f, k-byte kb) from swizzled smem
#define LOAD_AFRAG(a, sb, f, kb, lane)                                              \
    do {                                                                            \
        uint32_t off = (uint32_t)(((f) + ((lane) & 15)) * 128 + (kb) + (((lane) >> 4) << 4)); \
        LDSM_X4((a)[0], (a)[1], (a)[2], (a)[3], (sb) + swz(off));                   \
    } while (0)

// B-fragments for two adjacent n-tiles (16 rows at n0, k-byte kb)
#define LOAD_BFRAG(b0a, b0b, b1a, b1b, sb, n0, kb, lane)                            \
    do {                                                                            \
        int r = (n0) + ((lane) & 7) + (((lane) >> 4) << 3);                         \
        uint32_t off = (uint32_t)(r * 128 + (kb) + (((lane) >> 3) & 1) * 16);       \
        LDSM_X4(b0a, b0b, b1a, b1b, (sb) + swz(off));                               \
    } while (0)

// ---------------- weight transpose fp32 -> bf16 ----------------
__global__ __launch_bounds__(256) void k_transpose(const float* __restrict__ in,
                                                   int R, int C, int which) {
    __nv_bfloat16* out = (which == 0) ? g_winT : ((which == 1) ? g_woutT : g_wxT);
    __shared__ float tile[32][33];
    int c0 = blockIdx.x * 32, r0 = blockIdx.y * 32;
    int tx = threadIdx.x, ty = threadIdx.y;
#pragma unroll
    for (int i = 0; i < 4; i++) {
        int r = r0 + ty + 8 * i;
        if (r < R && c0 + tx < C) tile[ty + 8 * i][tx] = in[(size_t)r * C + c0 + tx];
    }
    __syncthreads();
#pragma unroll
    for (int i = 0; i < 4; i++) {
        int c = c0 + ty + 8 * i;
        if (c < C && r0 + tx < R)
            out[(size_t)c * R + r0 + tx] = __float2bfloat16(tile[tx][ty + 8 * i]);
    }
}

// ---------------- RMSNorm: feature [t][c][b] -> g_xnbf[m][c] bf16 token-major ----------------
__global__ __launch_bounds__(256) void k_rmsnorm(const float* __restrict__ feat,
                                                 const float* __restrict__ nw) {
    __shared__ float sred[8][32];
    __shared__ __align__(16) __nv_bfloat16 sX[32][264];
    int tx = threadIdx.x, ty = threadIdx.y;
    int t = blockIdx.y;
    int b = blockIdx.x * 32 + tx;
    const float* base = feat + (size_t)t * DM * NB + b;
    float v[32];
    float ss = 0.f;
#pragma unroll
    for (int i = 0; i < 32; i++) {
        float x = base[(size_t)(ty + 8 * i) * NB];
        v[i] = x;
        ss += x * x;
    }
    sred[ty][tx] = ss;
    __syncthreads();
    float tot = 0.f;
#pragma unroll
    for (int j = 0; j < 8; j++) tot += sred[j][tx];
    float sc = rsqrtf(tot * (1.f / DM) + 1e-5f);
#pragma unroll
    for (int i = 0; i < 32; i++)
        sX[tx][ty + 8 * i] = __float2bfloat16(v[i] * sc * nw[ty + 8 * i]);
    __syncthreads();
    int tid = ty * 32 + tx;
    size_t tok0 = (size_t)t * NB + blockIdx.x * 32;
    for (int u = tid; u < 32 * 32; u += 256) {
        int r = u >> 5, q = u & 31;
        *(uint4*)(g_xnbf + (tok0 + r) * DM + q * 8) = *(uint4*)&sX[r][q * 8];
    }
}

// ---------------- GEMM1 (HMMA + cp.async 2-stage): D[n][m] = w_inT[n][:] . xn[m][:] ----------------
__global__ __launch_bounds__(256, 2) void k_gemm1() {
    extern __shared__ __align__(1024) char sm[];
    int tid = threadIdx.x, wid = tid >> 5, lane = tid & 31;
    int wy = wid >> 2, wx = wid & 3;                   // warp: 64 feats x 32 toks
    int fbase = blockIdx.y * 128, tbase = blockIdx.x * 128;
    uint32_t sb = smem_u32(sm);                        // stage s: A @ s*32768, B @ +16384
    float acc[4][4][4];
#pragma unroll
    for (int i = 0; i < 4; i++)
#pragma unroll
        for (int j = 0; j < 4; j++)
#pragma unroll
            for (int q = 0; q < 4; q++) acc[i][j][q] = 0.f;

    ldchunk_async<128>(g_winT, fbase, 256, 0, sb, tid);
    ldchunk_async<128>(g_xnbf, tbase, 256, 0, sb + 16384, tid);
    CP_COMMIT();

    for (int kc = 0; kc < 4; kc++) {
        uint32_t cur = sb + (kc & 1) * 32768;
        if (kc < 3) {
            uint32_t nxt = sb + ((kc + 1) & 1) * 32768;
            ldchunk_async<128>(g_winT, fbase, 256, (kc + 1) * 64, nxt, tid);
            ldchunk_async<128>(g_xnbf, tbase, 256, (kc + 1) * 64, nxt + 16384, tid);
            CP_COMMIT();
            CP_WAIT(1);
        } else {
            CP_WAIT(0);
        }
        __syncthreads();
        uint32_t sbA = cur, sbB = cur + 16384;
#pragma unroll
        for (int ks = 0; ks < 4; ks++) {
            int kb = ks * 32;
            uint32_t a[4][4], b[4][2];
#pragma unroll
            for (int ft = 0; ft < 4; ft++) LOAD_AFRAG(a[ft], sbA, wy * 64 + ft * 16, kb, lane);
#pragma unroll
            for (int np = 0; np < 2; np++)
                LOAD_BFRAG(b[np * 2][0], b[np * 2][1], b[np * 2 + 1][0], b[np * 2 + 1][1],
                           sbB, wx * 32 + np * 16, kb, lane);
#pragma unroll
            for (int ft = 0; ft < 4; ft++)
#pragma unroll
                for (int nt = 0; nt < 4; nt++)
                    mma_bf16(acc[ft][nt], a[ft][0], a[ft][1], a[ft][2], a[ft][3],
                             b[nt][0], b[nt][1]);
        }
        __syncthreads();
    }

    bool isRes = (fbase >= DI);
    __nv_bfloat16* base = isRes ? g_sresh : g_uh;
    int fb = isRes ? (fbase - DI) : fbase;
#pragma unroll
    for (int ft = 0; ft < 4; ft++) {
#pragma unroll
        for (int nt = 0; nt < 4; nt++) {
            float* c = acc[ft][nt];
            int f = fb + wy * 64 + ft * 16 + (lane >> 2);
            int m = tbase + wx * 32 + nt * 8 + (lane & 3) * 2;
            if (isRes) {
                *(uint32_t*)(base + (size_t)f * TOK + m)       = packbf(siluf(c[0]), siluf(c[1]));
                *(uint32_t*)(base + (size_t)(f + 8) * TOK + m) = packbf(siluf(c[2]), siluf(c[3]));
            } else {
                *(uint32_t*)(base + (size_t)f * TOK + m)       = packbf(c[0], c[1]);
                *(uint32_t*)(base + (size_t)(f + 8) * TOK + m) = packbf(c[2], c[3]);
            }
        }
    }
}

// ---------------- depthwise causal conv (k=3) + silu; dual-layout output ----------------
__global__ __launch_bounds__(256) void k_conv(const float* __restrict__ cw,
                                              const float* __restrict__ cb) {
    __shared__ __nv_bfloat16 sT[32][33];
    int tx = threadIdx.x, ty = threadIdx.y;
    int m = blockIdx.x * 32 + tx;
    int d0 = blockIdx.y * 32;
    int t = m >> 10;
#pragma unroll
    for (int i = 0; i < 4; i++) {
        int d = d0 + ty + 8 * i;
        size_t base = (size_t)d * TOK + m;
        float acc = cb[d] + cw[d * 3 + 2] * __bfloat162float(g_uh[base]);
        if (t >= 1) acc += cw[d * 3 + 1] * __bfloat162float(g_uh[base - NB]);
        if (t >= 2) acc += cw[d * 3 + 0] * __bfloat162float(g_uh[base - 2 * NB]);
        __nv_bfloat16 hb = __float2bfloat16(siluf(acc));
        g_xmh[base] = hb;
        sT[ty + 8 * i][tx] = hb;
    }
    __syncthreads();
#pragma unroll
    for (int i = 0; i < 4; i++) {
        int mm = blockIdx.x * 32 + ty + 8 * i;
        g_xmbf[(size_t)mm * DI + d0 + tx] = sT[tx][ty + 8 * i];
    }
}

// ---------------- xproj (HMMA + cp.async): dbc[j][m] = wxT[j][:] . xm[m][:] ----------------
// A (48x512) fully preloaded; B double-buffered 128-token chunks
__global__ __launch_bounds__(256, 2) void k_xproj() {
    extern __shared__ __align__(1024) char sm[];
    int tid = threadIdx.x, wid = tid >> 5, lane = tid & 31;
    int tbase = blockIdx.x * 128;
    uint32_t sbA = smem_u32(sm);                       // 8 chunks x 6144B = 49152
    uint32_t sbB = sbA + 49152;                        // 2 stages x 16384
    float acc[3][2][4];
#pragma unroll
    for (int i = 0; i < 3; i++)
#pragma unroll
        for (int j = 0; j < 2; j++)
#pragma unroll
            for (int q = 0; q < 4; q++) acc[i][j][q] = 0.f;

#pragma unroll
    for (int c = 0; c < 8; c++)
        ldchunk_async<48>(g_wxT, 0, 512, c * 64, sbA + c * 6144, tid);
    ldchunk_async<128>(g_xmbf, tbase, 512, 0, sbB, tid);
    CP_COMMIT();

    for (int kc = 0; kc < 8; kc++) {
        uint32_t cur = sbB + (kc & 1) * 16384;
        if (kc < 7) {
            ldchunk_async<128>(g_xmbf, tbase, 512, (kc + 1) * 64, sbB + ((kc + 1) & 1) * 16384, tid);
            CP_COMMIT();
            CP_WAIT(1);
        } else {
            CP_WAIT(0);
        }
        __syncthreads();
        uint32_t aCh = sbA + kc * 6144;
#pragma unroll
        for (int ks = 0; ks < 4; ks++) {
            int kb = ks * 32;
            uint32_t a[3][4], b[2][2];
#pragma unroll
            for (int ft = 0; ft < 3; ft++) LOAD_AFRAG(a[ft], aCh, ft * 16, kb, lane);
            LOAD_BFRAG(b[0][0], b[0][1], b[1][0], b[1][1], cur, wid * 16, kb, lane);
#pragma unroll
            for (int ft = 0; ft < 3; ft++)
#pragma unroll
                for (int nt = 0; nt < 2; nt++)
                    mma_bf16(acc[ft][nt], a[ft][0], a[ft][1], a[ft][2], a[ft][3],
                             b[nt][0], b[nt][1]);
        }
        __syncthreads();
    }
#pragma unroll
    for (int ft = 0; ft < 3; ft++) {
#pragma unroll
        for (int nt = 0; nt < 2; nt++) {
            float* c = acc[ft][nt];
            int j = ft * 16 + (lane >> 2);
            int m = tbase + wid * 16 + nt * 8 + (lane & 3) * 2;
            float2 v0; v0.x = c[0]; v0.y = c[1];
            float2 v1; v1.x = c[2]; v1.y = c[3];
            *(float2*)(g_dbc + (size_t)j * TOK + m) = v0;
            *(float2*)(g_dbc + (size_t)(j + 8) * TOK + m) = v1;
        }
    }
}

// ---------------- fused dt + selective scan + D-skip + silu gate ----------------
__global__ __launch_bounds__(256) void k_scan(const float* __restrict__ A_log,
                                              const float* __restrict__ Dv,
                                              const float* __restrict__ w_dt,
                                              const float* __restrict__ b_dt) {
    __shared__ float sAll[48][32];
    __shared__ float sWdt[16][8];
    __shared__ float sbdt[8];
    __shared__ __nv_bfloat16 sY[8][32];
    int tx = threadIdx.x, ty = threadIdx.y;
    int tid = ty * 32 + tx;
    int b0 = blockIdx.x * 32;
    int d0 = blockIdx.y * 8;
    int d = d0 + ty;
    if (tid < 128) sWdt[tid >> 3][tid & 7] = w_dt[(size_t)(tid >> 3) * DI + d0 + (tid & 7)];
    if (tid < 8) sbdt[tid] = b_dt[d0 + tid];
    float A_[16];
    bool fast = true;
#pragma unroll
    for (int n = 0; n < 16; n++) {
        A_[n] = -__expf(A_log[d * 16 + n]);
        fast = fast && (fabsf(A_[n] + (float)(n + 1)) < 1e-3f * (n + 1));
    }
    float Dd = Dv[d];
    float h[16];
#pragma unroll
    for (int n = 0; n < 16; n++) h[n] = 0.f;
    __syncthreads();

    for (int t = 0; t < NT; t++) {
        int tokbase = t * NB + b0;
        for (int u = tid; u < 48 * 32; u += 256) {
            int j = u >> 5, c = u & 31;
            sAll[j][c] = g_dbc[(size_t)j * TOK + tokbase + c];
        }
        __syncthreads();

        size_t off = (size_t)d * TOK + tokbase + tx;
        float dlt = sbdt[ty];
#pragma unroll
        for (int r = 0; r < 16; r++) dlt += sAll[r][tx] * sWdt[r][ty];
        dlt = softplusf(dlt);
        float xv = __bfloat162float(g_xmh[off]);
        float dxu = dlt * xv;
        float y = 0.f;
        if (fast) {
            float p = __expf(-dlt), pn = 1.f;
#pragma unroll
            for (int n = 0; n < 16; n++) {
                pn *= p;
                h[n] = pn * h[n] + dxu * sAll[16 + n][tx];
                y += h[n] * sAll[32 + n][tx];
            }
        } else {
#pragma unroll
            for (int n = 0; n < 16; n++) {
                float dA = __expf(dlt * A_[n]);
                h[n] = dA * h[n] + dxu * sAll[16 + n][tx];
                y += h[n] * sAll[32 + n][tx];
            }
        }
        float sres = __bfloat162float(g_sresh[off]);
        sY[ty][tx] = __float2bfloat16((y + xv * Dd) * sres);
        __syncthreads();
        int bl = tid >> 3, j = tid & 7;
        g_ybf[(size_t)(tokbase + bl) * DI + d0 + j] = sY[j][bl];
        __syncthreads();
    }
}

// ---------------- GEMM out (HMMA + cp.async 2-stage): out[c][m] = w_outT[c][:] . y[m][:] + feat ----------------
__global__ __launch_bounds__(256, 2) void k_gemmout(const float* __restrict__ feat,
                                                    float* __restrict__ out) {
    extern __shared__ __align__(1024) char sm[];
    int tid = threadIdx.x, wid = tid >> 5, lane = tid & 31;
    int wy = wid >> 2, wx = wid & 3;
    int cbase = blockIdx.y * 128, tbase = blockIdx.x * 128;
    uint32_t sb = smem_u32(sm);
    float acc[4][4][4];
#pragma unroll
    for (int i = 0; i < 4; i++)
#pragma unroll
        for (int j = 0; j < 4; j++)
#pragma unroll
            for (int q = 0; q < 4; q++) acc[i][j][q] = 0.f;

    ldchunk_async<128>(g_woutT, cbase, 512, 0, sb, tid);
    ldchunk_async<128>(g_ybf, tbase, 512, 0, sb + 16384, tid);
    CP_COMMIT();

    for (int kc = 0; kc < 8; kc++) {
        uint32_t cur = sb + (kc & 1) * 32768;
        if (kc < 7) {
            uint32_t nxt = sb + ((kc + 1) & 1) * 32768;
            ldchunk_async<128>(g_woutT, cbase, 512, (kc + 1) * 64, nxt, tid);
            ldchunk_async<128>(g_ybf, tbase, 512, (kc + 1) * 64, nxt + 16384, tid);
            CP_COMMIT();
            CP_WAIT(1);
        } else {
            CP_WAIT(0);
        }
        __syncthreads();
        uint32_t sbA = cur, sbB = cur + 16384;
#pragma unroll
        for (int ks = 0; ks < 4; ks++) {
            int kb = ks * 32;
            uint32_t a[4][4], b[4][2];
#pragma unroll
            for (int ft = 0; ft < 4; ft++) LOAD_AFRAG(a[ft], sbA, wy * 64 + ft * 16, kb, lane);
#pragma unroll
            for (int np = 0; np < 2; np++)
                LOAD_BFRAG(b[np * 2][0], b[np * 2][1], b[np * 2 + 1][0], b[np * 2 + 1][1],
                           sbB, wx * 32 + np * 16, kb, lane);
#pragma unroll
            for (int ft = 0; ft < 4; ft++)
#pragma unroll
                for (int nt = 0; nt < 4; nt++)
                    mma_bf16(acc[ft][nt], a[ft][0], a[ft][1], a[ft][2], a[ft][3],
                             b[nt][0], b[nt][1]);
        }
        __syncthreads();
    }

    int t = tbase >> 10;              // whole block within one t (128 | 1024)
#pragma unroll
    for (int ft = 0; ft < 4; ft++) {
#pragma unroll
        for (int nt = 0; nt < 4; nt++) {
            float* c = acc[ft][nt];
            int cc = cbase + wy * 64 + ft * 16 + (lane >> 2);
            int m = tbase + wx * 32 + nt * 8 + (lane & 3) * 2;
            int b = m & 1023;
            size_t o0 = (size_t)t * DM * NB + (size_t)cc * NB + b;
            size_t o1 = o0 + 8 * (size_t)NB;
            float2 f0 = *(const float2*)(feat + o0);
            float2 f1 = *(const float2*)(feat + o1);
            float2 v0; v0.x = c[0] + f0.x; v0.y = c[1] + f0.y;
            float2 v1; v1.x = c[2] + f1.x; v1.y = c[3] + f1.y;
            *(float2*)(out + o0) = v0;
            *(float2*)(out + o1) = v1;
        }
    }
}

extern "C" void kernel_launch(void* const* d_in, const int* in_sizes, int n_in,
                              void* d_out, int out_size) {
    const float* feature = (const float*)d_in[0];
    const float* norm_w  = (const float*)d_in[1];
    const float* w_in    = (const float*)d_in[2];
    const float* conv_w  = (const float*)d_in[3];
    const float* conv_b  = (const float*)d_in[4];
    const float* w_xproj = (const float*)d_in[5];
    const float* w_dt    = (const float*)d_in[6];
    const float* b_dt    = (const float*)d_in[7];
    const float* A_log   = (const float*)d_in[8];
    const float* Dv      = (const float*)d_in[9];
    const float* w_out   = (const float*)d_in[10];
    float* out = (float*)d_out;

    const int SMEM_GEMM = 65536;              // 2 stages x (16KB A + 16KB B)
    const int SMEM_XP   = 49152 + 32768;      // full A + 2-stage B
    static bool attr_done = false;
    if (!attr_done) {
        cudaFuncSetAttribute(k_gemm1, cudaFuncAttributeMaxDynamicSharedMemorySize, SMEM_GEMM);
        cudaFuncSetAttribute(k_xproj, cudaFuncAttributeMaxDynamicSharedMemorySize, SMEM_XP);
        cudaFuncSetAttribute(k_gemmout, cudaFuncAttributeMaxDynamicSharedMemorySize, SMEM_GEMM);
        attr_done = true;
    }

    k_transpose<<<dim3(32, 8), dim3(32, 8)>>>(w_in, 256, 1024, 0);
    k_transpose<<<dim3(8, 16), dim3(32, 8)>>>(w_out, 512, 256, 1);
    k_transpose<<<dim3(2, 16), dim3(32, 8)>>>(w_xproj, 512, 48, 2);
    k_rmsnorm<<<dim3(32, 16), dim3(32, 8)>>>(feature, norm_w);
    k_gemm1<<<dim3(128, 8), 256, SMEM_GEMM>>>();
    k_conv<<<dim3(512, 16), dim3(32, 8)>>>(conv_w, conv_b);
    k_xproj<<<dim3(128, 1), 256, SMEM_XP>>>();
    k_scan<<<dim3(32, 64), dim3(32, 8)>>>(A_log, Dv, w_dt, b_dt);
    k_gemmout<<<dim3(128, 2), 256, SMEM_GEMM>>>(feature, out);
}

// round 7
// speedup vs baseline: 2.0691x; 1.0004x over previous
#include <cuda_runtime.h>
#include <cuda_bf16.h>
#include <cstdint>

#define NB 1024      // sequences (spatial positions)
#define NT 16        // sequence length (original batch)
#define TOK 16384    // NB*NT tokens, token = t*NB + b
#define DM 256
#define DI 512

// ---------------- scratch (__device__ globals; no allocations) ----------------
__device__ __align__(128) __nv_bfloat16 g_winT[1024 * 256];   // w_in^T  [n][k=256]
__device__ __align__(128) __nv_bfloat16 g_woutT[256 * 512];   // w_out^T [c][d=512]
__device__ __align__(128) __nv_bfloat16 g_wxT[48 * 512];      // w_xproj^T [j][d=512]
__device__ __align__(128) __nv_bfloat16 g_xnbf[TOK * DM];     // rmsnorm out, token-major [m][k]
__device__ __align__(128) __nv_bfloat16 g_uh[DI * TOK];       // pre-conv, channel-major [d][m]
__device__ __align__(128) __nv_bfloat16 g_sresh[DI * TOK];    // silu(res), channel-major
__device__ __align__(128) __nv_bfloat16 g_xmh[DI * TOK];      // post conv+silu, channel-major
__device__ __align__(128) __nv_bfloat16 g_xmbf[TOK * DI];     // same, token-major [m][d]
__device__ __align__(128) float         g_dbc[48 * TOK];      // channel-major [j][m]
__device__ __align__(128) __nv_bfloat16 g_ybf[TOK * DI];      // gated scan out, token-major

// ---------------- helpers ----------------
__device__ __forceinline__ uint32_t smem_u32(const void* p) {
    uint32_t a;
    asm("{ .reg .u64 t; cvta.to.shared.u64 t, %1; cvt.u32.u64 %0, t; }" : "=r"(a) : "l"(p));
    return a;
}
__device__ __forceinline__ float siluf(float x) { return __fdividef(x, 1.f + __expf(-x)); }
__device__ __forceinline__ float softplusf(float x) {
    return fmaxf(x, 0.f) + __logf(1.f + __expf(-fabsf(x)));
}
__device__ __forceinline__ uint32_t packbf(float a, float b) {
    __nv_bfloat162 t = __floats2bfloat162_rn(a, b);
    return *reinterpret_cast<uint32_t*>(&t);
}

#define LDSM_X4(r0, r1, r2, r3, addr) \
    asm volatile("ldmatrix.sync.aligned.m8n8.x4.shared.b16 {%0,%1,%2,%3}, [%4];" \
                 : "=r"(r0), "=r"(r1), "=r"(r2), "=r"(r3) : "r"(addr))

__device__ __forceinline__ void mma_bf16(float* c, uint32_t a0, uint32_t a1, uint32_t a2,
                                         uint32_t a3, uint32_t b0, uint32_t b1) {
    asm volatile(
        "mma.sync.aligned.m16n8k16.row.col.f32.bf16.bf16.f32 "
        "{%0,%1,%2,%3}, {%4,%5,%6,%7}, {%8,%9}, {%0,%1,%2,%3};"
        : "+f"(c[0]), "+f"(c[1]), "+f"(c[2]), "+f"(c[3])
        : "r"(a0), "r"(a1), "r"(a2), "r"(a3), "r"(b0), "r"(b1));
}

__device__ __forceinline__ uint32_t swz(uint32_t off) { return off ^ ((off >> 3) & 0x70); }

#define CP16(dst, src) \
    asm volatile("cp.async.cg.shared.global [%0], [%1], 16;" :: "r"(dst), "l"(src))
#define CP_COMMIT() asm volatile("cp.async.commit_group;" ::: "memory")
#define CP_WAIT(n)  asm volatile("cp.async.wait_group %0;" :: "n"(n) : "memory")

// async-load a [ROWS x 64] bf16 chunk (K-major rows, leading dim ld) into swizzled smem
template <int ROWS>
__device__ __forceinline__ void ldchunk_async(const __nv_bfloat16* __restrict__ g, int row0,
                                              int ld, int k0, uint32_t sm, int tid) {
    for (int u = tid; u < ROWS * 8; u += 256) {
        int r = u >> 3, q = u & 7;
        const void* src = g + (size_t)(row0 + r) * ld + k0 + q * 8;
        CP16(sm + swz(r * 128 + q * 16), src);
    }
}

// A-fragment (16x16 tile at feature row f, k-byte kb) from swizzled smem
#define LOAD_AFRAG(a, sb, f, kb, lane)                                              \
    do {                                                                            \
        uint32_t off = (uint32_t)(((f) + ((lane) & 15)) * 128 + (kb) + (((lane) >> 4) << 4)); \
        LDSM_X4((a)[0], (a)[1], (a)[2], (a)[3], (sb) + swz(off));                   \
    } while (0)

// B-fragments for two adjacent n-tiles (16 rows at n0, k-byte kb)
#define LOAD_BFRAG(b0a, b0b, b1a, b1b, sb, n0, kb, lane)                            \
    do {                                                                            \
        int r = (n0) + ((lane) & 7) + (((lane) >> 4) << 3);                         \
        uint32_t off = (uint32_t)(r * 128 + (kb) + (((lane) >> 3) & 1) * 16);       \
        LDSM_X4(b0a, b0b, b1a, b1b, (sb) + swz(off));                               \
    } while (0)

// ---------------- weight transpose fp32 -> bf16 ----------------
__global__ __launch_bounds__(256) void k_transpose(const float* __restrict__ in,
                                                   int R, int C, int which) {
    __nv_bfloat16* out = (which == 0) ? g_winT : ((which == 1) ? g_woutT : g_wxT);
    __shared__ float tile[32][33];
    int c0 = blockIdx.x * 32, r0 = blockIdx.y * 32;
    int tx = threadIdx.x, ty = threadIdx.y;
#pragma unroll
    for (int i = 0; i < 4; i++) {
        int r = r0 + ty + 8 * i;
        if (r < R && c0 + tx < C) tile[ty + 8 * i][tx] = in[(size_t)r * C + c0 + tx];
    }
    __syncthreads();
#pragma unroll
    for (int i = 0; i < 4; i++) {
        int c = c0 + ty + 8 * i;
        if (c < C && r0 + tx < R)
            out[(size_t)c * R + r0 + tx] = __float2bfloat16(tile[tx][ty + 8 * i]);
    }
}

// ---------------- RMSNorm: feature [t][c][b] -> g_xnbf[m][c] bf16 token-major ----------------
__global__ __launch_bounds__(256) void k_rmsnorm(const float* __restrict__ feat,
                                                 const float* __restrict__ nw) {
    __shared__ float sred[8][32];
    __shared__ __align__(16) __nv_bfloat16 sX[32][264];
    int tx = threadIdx.x, ty = threadIdx.y;
    int t = blockIdx.y;
    int b = blockIdx.x * 32 + tx;
    const float* base = feat + (size_t)t * DM * NB + b;
    float v[32];
    float ss = 0.f;
#pragma unroll
    for (int i = 0; i < 32; i++) {
        float x = base[(size_t)(ty + 8 * i) * NB];
        v[i] = x;
        ss += x * x;
    }
    sred[ty][tx] = ss;
    __syncthreads();
    float tot = 0.f;
#pragma unroll
    for (int j = 0; j < 8; j++) tot += sred[j][tx];
    float sc = rsqrtf(tot * (1.f / DM) + 1e-5f);
#pragma unroll
    for (int i = 0; i < 32; i++)
        sX[tx][ty + 8 * i] = __float2bfloat16(v[i] * sc * nw[ty + 8 * i]);
    __syncthreads();
    int tid = ty * 32 + tx;
    size_t tok0 = (size_t)t * NB + blockIdx.x * 32;
    for (int u = tid; u < 32 * 32; u += 256) {
        int r = u >> 5, q = u & 31;
        *(uint4*)(g_xnbf + (tok0 + r) * DM + q * 8) = *(uint4*)&sX[r][q * 8];
    }
}

// ---------------- GEMM1 (HMMA + cp.async 3-stage): D[n][m] = w_inT[n][:] . xn[m][:] ----------------
__global__ __launch_bounds__(256, 2) void k_gemm1() {
    extern __shared__ __align__(1024) char sm[];
    int tid = threadIdx.x, wid = tid >> 5, lane = tid & 31;
    int wy = wid >> 2, wx = wid & 3;                   // warp: 64 feats x 32 toks
    int fbase = blockIdx.y * 128, tbase = blockIdx.x * 128;
    uint32_t sb = smem_u32(sm);                        // stage s @ s*32768: A then B(+16384)
    float acc[4][4][4];
#pragma unroll
    for (int i = 0; i < 4; i++)
#pragma unroll
        for (int j = 0; j < 4; j++)
#pragma unroll
            for (int q = 0; q < 4; q++) acc[i][j][q] = 0.f;

#pragma unroll
    for (int s = 0; s < 2; s++) {
        ldchunk_async<128>(g_winT, fbase, 256, s * 64, sb + s * 32768, tid);
        ldchunk_async<128>(g_xnbf, tbase, 256, s * 64, sb + s * 32768 + 16384, tid);
        CP_COMMIT();
    }

    for (int kc = 0; kc < 4; kc++) {
        CP_WAIT(1);
        __syncthreads();
        if (kc + 2 < 4) {
            uint32_t nxt = sb + ((kc + 2) % 3) * 32768;
            ldchunk_async<128>(g_winT, fbase, 256, (kc + 2) * 64, nxt, tid);
            ldchunk_async<128>(g_xnbf, tbase, 256, (kc + 2) * 64, nxt + 16384, tid);
        }
        CP_COMMIT();
        uint32_t cur = sb + (kc % 3) * 32768;
        uint32_t sbA = cur, sbB = cur + 16384;
#pragma unroll
        for (int ks = 0; ks < 4; ks++) {
            int kb = ks * 32;
            uint32_t a[4][4], b[4][2];
#pragma unroll
            for (int ft = 0; ft < 4; ft++) LOAD_AFRAG(a[ft], sbA, wy * 64 + ft * 16, kb, lane);
#pragma unroll
            for (int np = 0; np < 2; np++)
                LOAD_BFRAG(b[np * 2][0], b[np * 2][1], b[np * 2 + 1][0], b[np * 2 + 1][1],
                           sbB, wx * 32 + np * 16, kb, lane);
#pragma unroll
            for (int ft = 0; ft < 4; ft++)
#pragma unroll
                for (int nt = 0; nt < 4; nt++)
                    mma_bf16(acc[ft][nt], a[ft][0], a[ft][1], a[ft][2], a[ft][3],
                             b[nt][0], b[nt][1]);
        }
    }

    bool isRes = (fbase >= DI);
    __nv_bfloat16* base = isRes ? g_sresh : g_uh;
    int fb = isRes ? (fbase - DI) : fbase;
#pragma unroll
    for (int ft = 0; ft < 4; ft++) {
#pragma unroll
        for (int nt = 0; nt < 4; nt++) {
            float* c = acc[ft][nt];
            int f = fb + wy * 64 + ft * 16 + (lane >> 2);
            int m = tbase + wx * 32 + nt * 8 + (lane & 3) * 2;
            if (isRes) {
                *(uint32_t*)(base + (size_t)f * TOK + m)       = packbf(siluf(c[0]), siluf(c[1]));
                *(uint32_t*)(base + (size_t)(f + 8) * TOK + m) = packbf(siluf(c[2]), siluf(c[3]));
            } else {
                *(uint32_t*)(base + (size_t)f * TOK + m)       = packbf(c[0], c[1]);
                *(uint32_t*)(base + (size_t)(f + 8) * TOK + m) = packbf(c[2], c[3]);
            }
        }
    }
}

// ---------------- depthwise causal conv (k=3) + silu; dual-layout output ----------------
__global__ __launch_bounds__(256) void k_conv(const float* __restrict__ cw,
                                              const float* __restrict__ cb) {
    __shared__ __nv_bfloat16 sT[32][33];
    int tx = threadIdx.x, ty = threadIdx.y;
    int m = blockIdx.x * 32 + tx;
    int d0 = blockIdx.y * 32;
    int t = m >> 10;
#pragma unroll
    for (int i = 0; i < 4; i++) {
        int d = d0 + ty + 8 * i;
        size_t base = (size_t)d * TOK + m;
        float acc = cb[d] + cw[d * 3 + 2] * __bfloat162float(g_uh[base]);
        if (t >= 1) acc += cw[d * 3 + 1] * __bfloat162float(g_uh[base - NB]);
        if (t >= 2) acc += cw[d * 3 + 0] * __bfloat162float(g_uh[base - 2 * NB]);
        __nv_bfloat16 hb = __float2bfloat16(siluf(acc));
        g_xmh[base] = hb;
        sT[ty + 8 * i][tx] = hb;
    }
    __syncthreads();
#pragma unroll
    for (int i = 0; i < 4; i++) {
        int mm = blockIdx.x * 32 + ty + 8 * i;
        g_xmbf[(size_t)mm * DI + d0 + tx] = sT[tx][ty + 8 * i];
    }
}

// ---------------- xproj (HMMA + cp.async): dbc[j][m] = wxT[j][:] . xm[m][:] ----------------
// A (48x512) fully preloaded; B 3-stage double-buffered 128-token chunks
__global__ __launch_bounds__(256, 2) void k_xproj() {
    extern __shared__ __align__(1024) char sm[];
    int tid = threadIdx.x, wid = tid >> 5, lane = tid & 31;
    int tbase = blockIdx.x * 128;
    uint32_t sbA = smem_u32(sm);                       // 8 chunks x 6144B = 49152
    uint32_t sbB = sbA + 49152;                        // 3 stages x 16384
    float acc[3][2][4];
#pragma unroll
    for (int i = 0; i < 3; i++)
#pragma unroll
        for (int j = 0; j < 2; j++)
#pragma unroll
            for (int q = 0; q < 4; q++) acc[i][j][q] = 0.f;

#pragma unroll
    for (int c = 0; c < 8; c++)
        ldchunk_async<48>(g_wxT, 0, 512, c * 64, sbA + c * 6144, tid);
    ldchunk_async<128>(g_xmbf, tbase, 512, 0, sbB, tid);
    CP_COMMIT();
    ldchunk_async<128>(g_xmbf, tbase, 512, 64, sbB + 16384, tid);
    CP_COMMIT();

    for (int kc = 0; kc < 8; kc++) {
        CP_WAIT(1);
        __syncthreads();
        if (kc + 2 < 8)
            ldchunk_async<128>(g_xmbf, tbase, 512, (kc + 2) * 64, sbB + ((kc + 2) % 3) * 16384, tid);
        CP_COMMIT();
        uint32_t cur = sbB + (kc % 3) * 16384;
        uint32_t aCh = sbA + kc * 6144;
#pragma unroll
        for (int ks = 0; ks < 4; ks++) {
            int kb = ks * 32;
            uint32_t a[3][4], b[2][2];
#pragma unroll
            for (int ft = 0; ft < 3; ft++) LOAD_AFRAG(a[ft], aCh, ft * 16, kb, lane);
            LOAD_BFRAG(b[0][0], b[0][1], b[1][0], b[1][1], cur, wid * 16, kb, lane);
#pragma unroll
            for (int ft = 0; ft < 3; ft++)
#pragma unroll
                for (int nt = 0; nt < 2; nt++)
                    mma_bf16(acc[ft][nt], a[ft][0], a[ft][1], a[ft][2], a[ft][3],
                             b[nt][0], b[nt][1]);
        }
    }
#pragma unroll
    for (int ft = 0; ft < 3; ft++) {
#pragma unroll
        for (int nt = 0; nt < 2; nt++) {
            float* c = acc[ft][nt];
            int j = ft * 16 + (lane >> 2);
            int m = tbase + wid * 16 + nt * 8 + (lane & 3) * 2;
            float2 v0; v0.x = c[0]; v0.y = c[1];
            float2 v1; v1.x = c[2]; v1.y = c[3];
            *(float2*)(g_dbc + (size_t)j * TOK + m) = v0;
            *(float2*)(g_dbc + (size_t)(j + 8) * TOK + m) = v1;
        }
    }
}

// ---------------- fused dt + selective scan + D-skip + silu gate ----------------
__global__ __launch_bounds__(256) void k_scan(const float* __restrict__ A_log,
                                              const float* __restrict__ Dv,
                                              const float* __restrict__ w_dt,
                                              const float* __restrict__ b_dt) {
    __shared__ float sAll[48][32];
    __shared__ float sWdt[16][8];
    __shared__ float sbdt[8];
    __shared__ __nv_bfloat16 sY[8][32];
    int tx = threadIdx.x, ty = threadIdx.y;
    int tid = ty * 32 + tx;
    int b0 = blockIdx.x * 32;
    int d0 = blockIdx.y * 8;
    int d = d0 + ty;
    if (tid < 128) sWdt[tid >> 3][tid & 7] = w_dt[(size_t)(tid >> 3) * DI + d0 + (tid & 7)];
    if (tid < 8) sbdt[tid] = b_dt[d0 + tid];
    float A_[16];
    bool fast = true;
#pragma unroll
    for (int n = 0; n < 16; n++) {
        A_[n] = -__expf(A_log[d * 16 + n]);
        fast = fast && (fabsf(A_[n] + (float)(n + 1)) < 1e-3f * (n + 1));
    }
    float Dd = Dv[d];
    float h[16];
#pragma unroll
    for (int n = 0; n < 16; n++) h[n] = 0.f;
    __syncthreads();

    for (int t = 0; t < NT; t++) {
        int tokbase = t * NB + b0;
        for (int u = tid; u < 48 * 32; u += 256) {
            int j = u >> 5, c = u & 31;
            sAll[j][c] = g_dbc[(size_t)j * TOK + tokbase + c];
        }
        __syncthreads();

        size_t off = (size_t)d * TOK + tokbase + tx;
        float dlt = sbdt[ty];
#pragma unroll
        for (int r = 0; r < 16; r++) dlt += sAll[r][tx] * sWdt[r][ty];
        dlt = softplusf(dlt);
        float xv = __bfloat162float(g_xmh[off]);
        float dxu = dlt * xv;
        float y = 0.f;
        if (fast) {
            float p = __expf(-dlt), pn = 1.f;
#pragma unroll
            for (int n = 0; n < 16; n++) {
                pn *= p;
                h[n] = pn * h[n] + dxu * sAll[16 + n][tx];
                y += h[n] * sAll[32 + n][tx];
            }
        } else {
#pragma unroll
            for (int n = 0; n < 16; n++) {
                float dA = __expf(dlt * A_[n]);
                h[n] = dA * h[n] + dxu * sAll[16 + n][tx];
                y += h[n] * sAll[32 + n][tx];
            }
        }
        float sres = __bfloat162float(g_sresh[off]);
        sY[ty][tx] = __float2bfloat16((y + xv * Dd) * sres);
        __syncthreads();
        int bl = tid >> 3, j = tid & 7;
        g_ybf[(size_t)(tokbase + bl) * DI + d0 + j] = sY[j][bl];
        __syncthreads();
    }
}

// ---------------- GEMM out (HMMA + cp.async 3-stage): out[c][m] = w_outT[c][:] . y[m][:] + feat ----------------
__global__ __launch_bounds__(256, 2) void k_gemmout(const float* __restrict__ feat,
                                                    float* __restrict__ out) {
    extern __shared__ __align__(1024) char sm[];
    int tid = threadIdx.x, wid = tid >> 5, lane = tid & 31;
    int wy = wid >> 2, wx = wid & 3;
    int cbase = blockIdx.y * 128, tbase = blockIdx.x * 128;
    uint32_t sb = smem_u32(sm);
    float acc[4][4][4];
#pragma unroll
    for (int i = 0; i < 4; i++)
#pragma unroll
        for (int j = 0; j < 4; j++)
#pragma unroll
            for (int q = 0; q < 4; q++) acc[i][j][q] = 0.f;

#pragma unroll
    for (int s = 0; s < 2; s++) {
        ldchunk_async<128>(g_woutT, cbase, 512, s * 64, sb + s * 32768, tid);
        ldchunk_async<128>(g_ybf, tbase, 512, s * 64, sb + s * 32768 + 16384, tid);
        CP_COMMIT();
    }

    for (int kc = 0; kc < 8; kc++) {
        CP_WAIT(1);
        __syncthreads();
        if (kc + 2 < 8) {
            uint32_t nxt = sb + ((kc + 2) % 3) * 32768;
            ldchunk_async<128>(g_woutT, cbase, 512, (kc + 2) * 64, nxt, tid);
            ldchunk_async<128>(g_ybf, tbase, 512, (kc + 2) * 64, nxt + 16384, tid);
        }
        CP_COMMIT();
        uint32_t cur = sb + (kc % 3) * 32768;
        uint32_t sbA = cur, sbB = cur + 16384;
#pragma unroll
        for (int ks = 0; ks < 4; ks++) {
            int kb = ks * 32;
            uint32_t a[4][4], b[4][2];
#pragma unroll
            for (int ft = 0; ft < 4; ft++) LOAD_AFRAG(a[ft], sbA, wy * 64 + ft * 16, kb, lane);
#pragma unroll
            for (int np = 0; np < 2; np++)
                LOAD_BFRAG(b[np * 2][0], b[np * 2][1], b[np * 2 + 1][0], b[np * 2 + 1][1],
                           sbB, wx * 32 + np * 16, kb, lane);
#pragma unroll
            for (int ft = 0; ft < 4; ft++)
#pragma unroll
                for (int nt = 0; nt < 4; nt++)
                    mma_bf16(acc[ft][nt], a[ft][0], a[ft][1], a[ft][2], a[ft][3],
                             b[nt][0], b[nt][1]);
        }
    }

    int t = tbase >> 10;              // whole block within one t (128 | 1024)
#pragma unroll
    for (int ft = 0; ft < 4; ft++) {
#pragma unroll
        for (int nt = 0; nt < 4; nt++) {
            float* c = acc[ft][nt];
            int cc = cbase + wy * 64 + ft * 16 + (lane >> 2);
            int m = tbase + wx * 32 + nt * 8 + (lane & 3) * 2;
            int b = m & 1023;
            size_t o0 = (size_t)t * DM * NB + (size_t)cc * NB + b;
            size_t o1 = o0 + 8 * (size_t)NB;
            float2 f0 = *(const float2*)(feat + o0);
            float2 f1 = *(const float2*)(feat + o1);
            float2 v0; v0.x = c[0] + f0.x; v0.y = c[1] + f0.y;
            float2 v1; v1.x = c[2] + f1.x; v1.y = c[3] + f1.y;
            *(float2*)(out + o0) = v0;
            *(float2*)(out + o1) = v1;
        }
    }
}

extern "C" void kernel_launch(void* const* d_in, const int* in_sizes, int n_in,
                              void* d_out, int out_size) {
    const float* feature = (const float*)d_in[0];
    const float* norm_w  = (const float*)d_in[1];
    const float* w_in    = (const float*)d_in[2];
    const float* conv_w  = (const float*)d_in[3];
    const float* conv_b  = (const float*)d_in[4];
    const float* w_xproj = (const float*)d_in[5];
    const float* w_dt    = (const float*)d_in[6];
    const float* b_dt    = (const float*)d_in[7];
    const float* A_log   = (const float*)d_in[8];
    const float* Dv      = (const float*)d_in[9];
    const float* w_out   = (const float*)d_in[10];
    float* out = (float*)d_out;

    const int SMEM_GEMM = 3 * 32768;          // 3 stages x (16KB A + 16KB B)
    const int SMEM_XP   = 49152 + 3 * 16384;  // full A + 3-stage B
    static bool attr_done = false;
    if (!attr_done) {
        cudaFuncSetAttribute(k_gemm1, cudaFuncAttributeMaxDynamicSharedMemorySize, SMEM_GEMM);
        cudaFuncSetAttribute(k_xproj, cudaFuncAttributeMaxDynamicSharedMemorySize, SMEM_XP);
        cudaFuncSetAttribute(k_gemmout, cudaFuncAttributeMaxDynamicSharedMemorySize, SMEM_GEMM);
        attr_done = true;
    }

    k_transpose<<<dim3(32, 8), dim3(32, 8)>>>(w_in, 256, 1024, 0);
    k_transpose<<<dim3(8, 16), dim3(32, 8)>>>(w_out, 512, 256, 1);
    k_transpose<<<dim3(2, 16), dim3(32, 8)>>>(w_xproj, 512, 48, 2);
    k_rmsnorm<<<dim3(32, 16), dim3(32, 8)>>>(feature, norm_w);
    k_gemm1<<<dim3(128, 8), 256, SMEM_GEMM>>>();
    k_conv<<<dim3(512, 16), dim3(32, 8)>>>(conv_w, conv_b);
    k_xproj<<<dim3(128, 1), 256, SMEM_XP>>>();
    k_scan<<<dim3(32, 64), dim3(32, 8)>>>(A_log, Dv, w_dt, b_dt);
    k_gemmout<<<dim3(128, 2), 256, SMEM_GEMM>>>(feature, out);
}

// round 8
// speedup vs baseline: 2.1427x; 1.0356x over previous
#include <cuda_runtime.h>
#include <cuda_bf16.h>
#include <cstdint>

#define NB 1024      // sequences (spatial positions)
#define NT 16        // sequence length (original batch)
#define TOK 16384    // NB*NT tokens, token = t*NB + b
#define DM 256
#define DI 512

// ---------------- scratch (__device__ globals; no allocations) ----------------
__device__ __align__(128) __nv_bfloat16 g_winT[1024 * 256];   // w_in^T  [n][k=256]
__device__ __align__(128) __nv_bfloat16 g_woutT[256 * 512];   // w_out^T [c][d=512]
__device__ __align__(128) __nv_bfloat16 g_wxT[48 * 512];      // w_xproj^T [j][d=512]
__device__ __align__(128) __nv_bfloat16 g_xnbf[TOK * DM];     // rmsnorm out, token-major [m][k]
__device__ __align__(128) __nv_bfloat16 g_uh[DI * TOK];       // pre-conv, channel-major [d][m]
__device__ __align__(128) __nv_bfloat16 g_sresh[DI * TOK];    // silu(res), channel-major
__device__ __align__(128) __nv_bfloat16 g_xmh[DI * TOK];      // post conv+silu, channel-major
__device__ __align__(128) __nv_bfloat16 g_xmbf[TOK * DI];     // same, token-major [m][d]
__device__ __align__(128) float         g_dbc[48 * TOK];      // channel-major [j][m]
__device__ __align__(128) __nv_bfloat16 g_ybf[TOK * DI];      // gated scan out, token-major

// ---------------- helpers ----------------
__device__ __forceinline__ uint32_t smem_u32(const void* p) {
    uint32_t a;
    asm("{ .reg .u64 t; cvta.to.shared.u64 t, %1; cvt.u32.u64 %0, t; }" : "=r"(a) : "l"(p));
    return a;
}
__device__ __forceinline__ float siluf(float x) { return __fdividef(x, 1.f + __expf(-x)); }
__device__ __forceinline__ float softplusf(float x) {
    return fmaxf(x, 0.f) + __logf(1.f + __expf(-fabsf(x)));
}
__device__ __forceinline__ uint32_t packbf(float a, float b) {
    __nv_bfloat162 t = __floats2bfloat162_rn(a, b);
    return *reinterpret_cast<uint32_t*>(&t);
}

#define LDSM_X4(r0, r1, r2, r3, addr) \
    asm volatile("ldmatrix.sync.aligned.m8n8.x4.shared.b16 {%0,%1,%2,%3}, [%4];" \
                 : "=r"(r0), "=r"(r1), "=r"(r2), "=r"(r3) : "r"(addr))

__device__ __forceinline__ void mma_bf16(float* c, uint32_t a0, uint32_t a1, uint32_t a2,
                                         uint32_t a3, uint32_t b0, uint32_t b1) {
    asm volatile(
        "mma.sync.aligned.m16n8k16.row.col.f32.bf16.bf16.f32 "
        "{%0,%1,%2,%3}, {%4,%5,%6,%7}, {%8,%9}, {%0,%1,%2,%3};"
        : "+f"(c[0]), "+f"(c[1]), "+f"(c[2]), "+f"(c[3])
        : "r"(a0), "r"(a1), "r"(a2), "r"(a3), "r"(b0), "r"(b1));
}

__device__ __forceinline__ uint32_t swz(uint32_t off) { return off ^ ((off >> 3) & 0x70); }

#define CP16(dst, src) \
    asm volatile("cp.async.cg.shared.global [%0], [%1], 16;" :: "r"(dst), "l"(src))
#define CP_COMMIT() asm volatile("cp.async.commit_group;" ::: "memory")
#define CP_WAIT(n)  asm volatile("cp.async.wait_group %0;" :: "n"(n) : "memory")

// async-load a [ROWS x 64] bf16 chunk (K-major rows, leading dim ld) into swizzled smem
template <int ROWS>
__device__ __forceinline__ void ldchunk_async(const __nv_bfloat16* __restrict__ g, int row0,
                                              int ld, int k0, uint32_t sm, int tid) {
    for (int u = tid; u < ROWS * 8; u += 256) {
        int r = u >> 3, q = u & 7;
        const void* src = g + (size_t)(row0 + r) * ld + k0 + q * 8;
        CP16(sm + swz(r * 128 + q * 16), src);
    }
}

// A-fragment (16x16 tile at feature row f, k-byte kb) from swizzled smem
#define LOAD_AFRAG(a, sb, f, kb, lane)                                              \
    do {                                                                            \
        uint32_t off = (uint32_t)(((f) + ((lane) & 15)) * 128 + (kb) + (((lane) >> 4) << 4)); \
        LDSM_X4((a)[0], (a)[1], (a)[2], (a)[3], (sb) + swz(off));                   \
    } while (0)

// B-fragments for two adjacent n-tiles (16 rows at n0, k-byte kb)
#define LOAD_BFRAG(b0a, b0b, b1a, b1b, sb, n0, kb, lane)                            \
    do {                                                                            \
        int r = (n0) + ((lane) & 7) + (((lane) >> 4) << 3);                         \
        uint32_t off = (uint32_t)(r * 128 + (kb) + (((lane) >> 3) & 1) * 16);       \
        LDSM_X4(b0a, b0b, b1a, b1b, (sb) + swz(off));                               \
    } while (0)

// ---------------- weight transpose fp32 -> bf16 ----------------
__global__ __launch_bounds__(256) void k_transpose(const float* __restrict__ in,
                                                   int R, int C, int which) {
    __nv_bfloat16* out = (which == 0) ? g_winT : ((which == 1) ? g_woutT : g_wxT);
    __shared__ float tile[32][33];
    int c0 = blockIdx.x * 32, r0 = blockIdx.y * 32;
    int tx = threadIdx.x, ty = threadIdx.y;
#pragma unroll
    for (int i = 0; i < 4; i++) {
        int r = r0 + ty + 8 * i;
        if (r < R && c0 + tx < C) tile[ty + 8 * i][tx] = in[(size_t)r * C + c0 + tx];
    }
    __syncthreads();
#pragma unroll
    for (int i = 0; i < 4; i++) {
        int c = c0 + ty + 8 * i;
        if (c < C && r0 + tx < R)
            out[(size_t)c * R + r0 + tx] = __float2bfloat16(tile[tx][ty + 8 * i]);
    }
}

// ---------------- RMSNorm: feature [t][c][b] -> g_xnbf[m][c] bf16 token-major ----------------
__global__ __launch_bounds__(256) void k_rmsnorm(const float* __restrict__ feat,
                                                 const float* __restrict__ nw) {
    __shared__ float sred[8][32];
    __shared__ __align__(16) __nv_bfloat16 sX[32][264];
    int tx = threadIdx.x, ty = threadIdx.y;
    int t = blockIdx.y;
    int b = blockIdx.x * 32 + tx;
    const float* base = feat + (size_t)t * DM * NB + b;
    float v[32];
    float ss = 0.f;
#pragma unroll
    for (int i = 0; i < 32; i++) {
        float x = base[(size_t)(ty + 8 * i) * NB];
        v[i] = x;
        ss += x * x;
    }
    sred[ty][tx] = ss;
    __syncthreads();
    float tot = 0.f;
#pragma unroll
    for (int j = 0; j < 8; j++) tot += sred[j][tx];
    float sc = rsqrtf(tot * (1.f / DM) + 1e-5f);
#pragma unroll
    for (int i = 0; i < 32; i++)
        sX[tx][ty + 8 * i] = __float2bfloat16(v[i] * sc * nw[ty + 8 * i]);
    __syncthreads();
    int tid = ty * 32 + tx;
    size_t tok0 = (size_t)t * NB + blockIdx.x * 32;
    for (int u = tid; u < 32 * 32; u += 256) {
        int r = u >> 5, q = u & 31;
        *(uint4*)(g_xnbf + (tok0 + r) * DM + q * 8) = *(uint4*)&sX[r][q * 8];
    }
}

// ---------------- GEMM1 (HMMA; A preloaded, B 3-stage): D[n][m] = w_inT[n][:] . xn[m][:] ----------------
__global__ __launch_bounds__(256, 2) void k_gemm1() {
    extern __shared__ __align__(1024) char sm[];
    int tid = threadIdx.x, wid = tid >> 5, lane = tid & 31;
    int wy = wid >> 2, wx = wid & 3;                   // warp: 64 feats x 32 toks
    int fbase = blockIdx.y * 128, tbase = blockIdx.x * 128;
    uint32_t sbA = smem_u32(sm);                       // 4 chunks x 16384 = 65536 (full A)
    uint32_t sbB = sbA + 65536;                        // 3-stage B ring
    float acc[4][4][4];
#pragma unroll
    for (int i = 0; i < 4; i++)
#pragma unroll
        for (int j = 0; j < 4; j++)
#pragma unroll
            for (int q = 0; q < 4; q++) acc[i][j][q] = 0.f;

#pragma unroll
    for (int c = 0; c < 4; c++)
        ldchunk_async<128>(g_winT, fbase, 256, c * 64, sbA + c * 16384, tid);
    ldchunk_async<128>(g_xnbf, tbase, 256, 0, sbB, tid);
    CP_COMMIT();
    ldchunk_async<128>(g_xnbf, tbase, 256, 64, sbB + 16384, tid);
    CP_COMMIT();

    for (int kc = 0; kc < 4; kc++) {
        CP_WAIT(1);
        __syncthreads();
        if (kc + 2 < 4)
            ldchunk_async<128>(g_xnbf, tbase, 256, (kc + 2) * 64, sbB + ((kc + 2) % 3) * 16384, tid);
        CP_COMMIT();
        uint32_t aCh = sbA + kc * 16384;
        uint32_t bCur = sbB + (kc % 3) * 16384;
#pragma unroll
        for (int ks = 0; ks < 4; ks++) {
            int kb = ks * 32;
            uint32_t b[4][2];
#pragma unroll
            for (int np = 0; np < 2; np++)
                LOAD_BFRAG(b[np * 2][0], b[np * 2][1], b[np * 2 + 1][0], b[np * 2 + 1][1],
                           bCur, wx * 32 + np * 16, kb, lane);
#pragma unroll
            for (int ft = 0; ft < 4; ft++) {
                uint32_t a[4];
                LOAD_AFRAG(a, aCh, wy * 64 + ft * 16, kb, lane);
#pragma unroll
                for (int nt = 0; nt < 4; nt++)
                    mma_bf16(acc[ft][nt], a[0], a[1], a[2], a[3], b[nt][0], b[nt][1]);
            }
        }
    }

    bool isRes = (fbase >= DI);
    __nv_bfloat16* base = isRes ? g_sresh : g_uh;
    int fb = isRes ? (fbase - DI) : fbase;
#pragma unroll
    for (int ft = 0; ft < 4; ft++) {
#pragma unroll
        for (int nt = 0; nt < 4; nt++) {
            float* c = acc[ft][nt];
            int f = fb + wy * 64 + ft * 16 + (lane >> 2);
            int m = tbase + wx * 32 + nt * 8 + (lane & 3) * 2;
            if (isRes) {
                *(uint32_t*)(base + (size_t)f * TOK + m)       = packbf(siluf(c[0]), siluf(c[1]));
                *(uint32_t*)(base + (size_t)(f + 8) * TOK + m) = packbf(siluf(c[2]), siluf(c[3]));
            } else {
                *(uint32_t*)(base + (size_t)f * TOK + m)       = packbf(c[0], c[1]);
                *(uint32_t*)(base + (size_t)(f + 8) * TOK + m) = packbf(c[2], c[3]);
            }
        }
    }
}

// ---------------- depthwise causal conv (k=3) + silu; dual-layout output ----------------
__global__ __launch_bounds__(256) void k_conv(const float* __restrict__ cw,
                                              const float* __restrict__ cb) {
    __shared__ __nv_bfloat16 sT[32][33];
    int tx = threadIdx.x, ty = threadIdx.y;
    int m = blockIdx.x * 32 + tx;
    int d0 = blockIdx.y * 32;
    int t = m >> 10;
#pragma unroll
    for (int i = 0; i < 4; i++) {
        int d = d0 + ty + 8 * i;
        size_t base = (size_t)d * TOK + m;
        float acc = cb[d] + cw[d * 3 + 2] * __bfloat162float(g_uh[base]);
        if (t >= 1) acc += cw[d * 3 + 1] * __bfloat162float(g_uh[base - NB]);
        if (t >= 2) acc += cw[d * 3 + 0] * __bfloat162float(g_uh[base - 2 * NB]);
        __nv_bfloat16 hb = __float2bfloat16(siluf(acc));
        g_xmh[base] = hb;
        sT[ty + 8 * i][tx] = hb;
    }
    __syncthreads();
#pragma unroll
    for (int i = 0; i < 4; i++) {
        int mm = blockIdx.x * 32 + ty + 8 * i;
        g_xmbf[(size_t)mm * DI + d0 + tx] = sT[tx][ty + 8 * i];
    }
}

// ---------------- xproj (HMMA + cp.async): dbc[j][m] = wxT[j][:] . xm[m][:] ----------------
// A (48x512) fully preloaded; B 3-stage 128-token chunks
__global__ __launch_bounds__(256, 2) void k_xproj() {
    extern __shared__ __align__(1024) char sm[];
    int tid = threadIdx.x, wid = tid >> 5, lane = tid & 31;
    int tbase = blockIdx.x * 128;
    uint32_t sbA = smem_u32(sm);                       // 8 chunks x 6144B = 49152
    uint32_t sbB = sbA + 49152;                        // 3 stages x 16384
    float acc[3][2][4];
#pragma unroll
    for (int i = 0; i < 3; i++)
#pragma unroll
        for (int j = 0; j < 2; j++)
#pragma unroll
            for (int q = 0; q < 4; q++) acc[i][j][q] = 0.f;

#pragma unroll
    for (int c = 0; c < 8; c++)
        ldchunk_async<48>(g_wxT, 0, 512, c * 64, sbA + c * 6144, tid);
    ldchunk_async<128>(g_xmbf, tbase, 512, 0, sbB, tid);
    CP_COMMIT();
    ldchunk_async<128>(g_xmbf, tbase, 512, 64, sbB + 16384, tid);
    CP_COMMIT();

    for (int kc = 0; kc < 8; kc++) {
        CP_WAIT(1);
        __syncthreads();
        if (kc + 2 < 8)
            ldchunk_async<128>(g_xmbf, tbase, 512, (kc + 2) * 64, sbB + ((kc + 2) % 3) * 16384, tid);
        CP_COMMIT();
        uint32_t cur = sbB + (kc % 3) * 16384;
        uint32_t aCh = sbA + kc * 6144;
#pragma unroll
        for (int ks = 0; ks < 4; ks++) {
            int kb = ks * 32;
            uint32_t b[2][2];
            LOAD_BFRAG(b[0][0], b[0][1], b[1][0], b[1][1], cur, wid * 16, kb, lane);
#pragma unroll
            for (int ft = 0; ft < 3; ft++) {
                uint32_t a[4];
                LOAD_AFRAG(a, aCh, ft * 16, kb, lane);
#pragma unroll
                for (int nt = 0; nt < 2; nt++)
                    mma_bf16(acc[ft][nt], a[0], a[1], a[2], a[3], b[nt][0], b[nt][1]);
            }
        }
    }
#pragma unroll
    for (int ft = 0; ft < 3; ft++) {
#pragma unroll
        for (int nt = 0; nt < 2; nt++) {
            float* c = acc[ft][nt];
            int j = ft * 16 + (lane >> 2);
            int m = tbase + wid * 16 + nt * 8 + (lane & 3) * 2;
            float2 v0; v0.x = c[0]; v0.y = c[1];
            float2 v1; v1.x = c[2]; v1.y = c[3];
            *(float2*)(g_dbc + (size_t)j * TOK + m) = v0;
            *(float2*)(g_dbc + (size_t)(j + 8) * TOK + m) = v1;
        }
    }
}

// ---------------- fused dt + selective scan + D-skip + silu gate (16 d per block) ----------------
__global__ __launch_bounds__(512) void k_scan(const float* __restrict__ A_log,
                                              const float* __restrict__ Dv,
                                              const float* __restrict__ w_dt,
                                              const float* __restrict__ b_dt) {
    __shared__ float sAll[48][32];
    __shared__ float sWdt[16][16];
    __shared__ float sbdt[16];
    __shared__ __nv_bfloat16 sY[16][32];
    int tx = threadIdx.x, ty = threadIdx.y;             // tx: b in 32, ty: d in 16
    int tid = ty * 32 + tx;
    int b0 = blockIdx.x * 32;
    int d0 = blockIdx.y * 16;
    int d = d0 + ty;
    if (tid < 256) sWdt[tid >> 4][tid & 15] = w_dt[(size_t)(tid >> 4) * DI + d0 + (tid & 15)];
    if (tid < 16) sbdt[tid] = b_dt[d0 + tid];
    float A_[16];
    bool fast = true;
#pragma unroll
    for (int n = 0; n < 16; n++) {
        A_[n] = -__expf(A_log[d * 16 + n]);
        fast = fast && (fabsf(A_[n] + (float)(n + 1)) < 1e-3f * (n + 1));
    }
    float Dd = Dv[d];
    float h[16];
#pragma unroll
    for (int n = 0; n < 16; n++) h[n] = 0.f;
    __syncthreads();

    for (int t = 0; t < NT; t++) {
        int tokbase = t * NB + b0;
        for (int u = tid; u < 48 * 32; u += 512) {
            int j = u >> 5, c = u & 31;
            sAll[j][c] = g_dbc[(size_t)j * TOK + tokbase + c];
        }
        __syncthreads();

        size_t off = (size_t)d * TOK + tokbase + tx;
        float dlt = sbdt[ty];
#pragma unroll
        for (int r = 0; r < 16; r++) dlt += sAll[r][tx] * sWdt[r][ty];
        dlt = softplusf(dlt);
        float xv = __bfloat162float(g_xmh[off]);
        float dxu = dlt * xv;
        float y = 0.f;
        if (fast) {
            float p = __expf(-dlt), pn = 1.f;
#pragma unroll
            for (int n = 0; n < 16; n++) {
                pn *= p;
                h[n] = pn * h[n] + dxu * sAll[16 + n][tx];
                y += h[n] * sAll[32 + n][tx];
            }
        } else {
#pragma unroll
            for (int n = 0; n < 16; n++) {
                float dA = __expf(dlt * A_[n]);
                h[n] = dA * h[n] + dxu * sAll[16 + n][tx];
                y += h[n] * sAll[32 + n][tx];
            }
        }
        float sres = __bfloat162float(g_sresh[off]);
        sY[ty][tx] = __float2bfloat16((y + xv * Dd) * sres);
        __syncthreads();
        int bl = tid >> 4, j = tid & 15;                // 32 tokens x 16 d
        g_ybf[(size_t)(tokbase + bl) * DI + d0 + j] = sY[j][bl];
    }
}

// ---------------- GEMM out (HMMA + cp.async 3-stage): out[c][m] = w_outT[c][:] . y[m][:] + feat ----------------
__global__ __launch_bounds__(256, 2) void k_gemmout(const float* __restrict__ feat,
                                                    float* __restrict__ out) {
    extern __shared__ __align__(1024) char sm[];
    int tid = threadIdx.x, wid = tid >> 5, lane = tid & 31;
    int wy = wid >> 2, wx = wid & 3;
    int cbase = blockIdx.y * 128, tbase = blockIdx.x * 128;
    uint32_t sb = smem_u32(sm);
    float acc[4][4][4];
#pragma unroll
    for (int i = 0; i < 4; i++)
#pragma unroll
        for (int j = 0; j < 4; j++)
#pragma unroll
            for (int q = 0; q < 4; q++) acc[i][j][q] = 0.f;

#pragma unroll
    for (int s = 0; s < 2; s++) {
        ldchunk_async<128>(g_woutT, cbase, 512, s * 64, sb + s * 32768, tid);
        ldchunk_async<128>(g_ybf, tbase, 512, s * 64, sb + s * 32768 + 16384, tid);
        CP_COMMIT();
    }

    for (int kc = 0; kc < 8; kc++) {
        CP_WAIT(1);
        __syncthreads();
        if (kc + 2 < 8) {
            uint32_t nxt = sb + ((kc + 2) % 3) * 32768;
            ldchunk_async<128>(g_woutT, cbase, 512, (kc + 2) * 64, nxt, tid);
            ldchunk_async<128>(g_ybf, tbase, 512, (kc + 2) * 64, nxt + 16384, tid);
        }
        CP_COMMIT();
        uint32_t cur = sb + (kc % 3) * 32768;
        uint32_t sbA = cur, sbB = cur + 16384;
#pragma unroll
        for (int ks = 0; ks < 4; ks++) {
            int kb = ks * 32;
            uint32_t b[4][2];
#pragma unroll
            for (int np = 0; np < 2; np++)
                LOAD_BFRAG(b[np * 2][0], b[np * 2][1], b[np * 2 + 1][0], b[np * 2 + 1][1],
                           sbB, wx * 32 + np * 16, kb, lane);
#pragma unroll
            for (int ft = 0; ft < 4; ft++) {
                uint32_t a[4];
                LOAD_AFRAG(a, sbA, wy * 64 + ft * 16, kb, lane);
#pragma unroll
                for (int nt = 0; nt < 4; nt++)
                    mma_bf16(acc[ft][nt], a[0], a[1], a[2], a[3], b[nt][0], b[nt][1]);
            }
        }
    }

    int t = tbase >> 10;              // whole block within one t (128 | 1024)
#pragma unroll
    for (int ft = 0; ft < 4; ft++) {
#pragma unroll
        for (int nt = 0; nt < 4; nt++) {
            float* c = acc[ft][nt];
            int cc = cbase + wy * 64 + ft * 16 + (lane >> 2);
            int m = tbase + wx * 32 + nt * 8 + (lane & 3) * 2;
            int b = m & 1023;
            size_t o0 = (size_t)t * DM * NB + (size_t)cc * NB + b;
            size_t o1 = o0 + 8 * (size_t)NB;
            float2 f0 = *(const float2*)(feat + o0);
            float2 f1 = *(const float2*)(feat + o1);
            float2 v0; v0.x = c[0] + f0.x; v0.y = c[1] + f0.y;
            float2 v1; v1.x = c[2] + f1.x; v1.y = c[3] + f1.y;
            *(float2*)(out + o0) = v0;
            *(float2*)(out + o1) = v1;
        }
    }
}

extern "C" void kernel_launch(void* const* d_in, const int* in_sizes, int n_in,
                              void* d_out, int out_size) {
    const float* feature = (const float*)d_in[0];
    const float* norm_w  = (const float*)d_in[1];
    const float* w_in    = (const float*)d_in[2];
    const float* conv_w  = (const float*)d_in[3];
    const float* conv_b  = (const float*)d_in[4];
    const float* w_xproj = (const float*)d_in[5];
    const float* w_dt    = (const float*)d_in[6];
    const float* b_dt    = (const float*)d_in[7];
    const float* A_log   = (const float*)d_in[8];
    const float* Dv      = (const float*)d_in[9];
    const float* w_out   = (const float*)d_in[10];
    float* out = (float*)d_out;

    const int SMEM_G1   = 65536 + 3 * 16384;  // full A + 3-stage B = 114688
    const int SMEM_GOUT = 3 * 32768;          // 3 stages x (A+B)
    const int SMEM_XP   = 49152 + 3 * 16384;  // full A + 3-stage B
    cudaFuncSetAttribute(k_gemm1, cudaFuncAttributeMaxDynamicSharedMemorySize, SMEM_G1);
    cudaFuncSetAttribute(k_xproj, cudaFuncAttributeMaxDynamicSharedMemorySize, SMEM_XP);
    cudaFuncSetAttribute(k_gemmout, cudaFuncAttributeMaxDynamicSharedMemorySize, SMEM_GOUT);

    k_transpose<<<dim3(32, 8), dim3(32, 8)>>>(w_in, 256, 1024, 0);
    k_transpose<<<dim3(8, 16), dim3(32, 8)>>>(w_out, 512, 256, 1);
    k_transpose<<<dim3(2, 16), dim3(32, 8)>>>(w_xproj, 512, 48, 2);
    k_rmsnorm<<<dim3(32, 16), dim3(32, 8)>>>(feature, norm_w);
    k_gemm1<<<dim3(128, 8), 256, SMEM_G1>>>();
    k_conv<<<dim3(512, 16), dim3(32, 8)>>>(conv_w, conv_b);
    k_xproj<<<dim3(128, 1), 256, SMEM_XP>>>();
    k_scan<<<dim3(32, 32), dim3(32, 16)>>>(A_log, Dv, w_dt, b_dt);
    k_gemmout<<<dim3(128, 2), 256, SMEM_GOUT>>>(feature, out);
}

// round 9
// speedup vs baseline: 2.2965x; 1.0718x over previous
#include <cuda_runtime.h>
#include <cuda_bf16.h>
#include <cstdint>

#define NB 1024      // sequences (spatial positions)
#define NT 16        // sequence length (original batch)
#define TOK 16384    // NB*NT tokens, token = t*NB + b
#define DM 256
#define DI 512

// ---------------- scratch (__device__ globals; no allocations) ----------------
__device__ __align__(128) __nv_bfloat16 g_winT[1024 * 256];   // w_in^T  [n][k=256]
__device__ __align__(128) __nv_bfloat16 g_woutT[256 * 512];   // w_out^T [c][d=512]
__device__ __align__(128) __nv_bfloat16 g_wxT[48 * 512];      // w_xproj^T [j][d=512]
__device__ __align__(128) __nv_bfloat16 g_xnbf[TOK * DM];     // rmsnorm out, token-major [m][k]
__device__ __align__(128) __nv_bfloat16 g_uh[DI * TOK];       // pre-conv, channel-major [d][m]
__device__ __align__(128) __nv_bfloat16 g_sresh[DI * TOK];    // silu(res), channel-major
__device__ __align__(128) __nv_bfloat16 g_xmh[DI * TOK];      // post conv+silu, channel-major
__device__ __align__(128) __nv_bfloat16 g_xmbf[TOK * DI];     // same, token-major [m][d]
__device__ __align__(128) __nv_bfloat16 g_dtin[TOK * 16];     // dt input, token-major [m][16]
__device__ __align__(128) uint32_t      g_bcp[16 * TOK];      // packed bf16x2: r<8 B-pairs, r>=8 C-pairs
__device__ __align__(128) float         g_delta[DI * TOK];    // softplus delta, channel-major
__device__ __align__(128) __nv_bfloat16 g_ybf[TOK * DI];      // gated scan out, token-major

// ---------------- helpers ----------------
__device__ __forceinline__ uint32_t smem_u32(const void* p) {
    uint32_t a;
    asm("{ .reg .u64 t; cvta.to.shared.u64 t, %1; cvt.u32.u64 %0, t; }" : "=r"(a) : "l"(p));
    return a;
}
__device__ __forceinline__ float siluf(float x) { return __fdividef(x, 1.f + __expf(-x)); }
__device__ __forceinline__ float softplusf(float x) {
    return fmaxf(x, 0.f) + __logf(1.f + __expf(-fabsf(x)));
}
__device__ __forceinline__ uint32_t packbf(float a, float b) {
    __nv_bfloat162 t = __floats2bfloat162_rn(a, b);
    return *reinterpret_cast<uint32_t*>(&t);
}
__device__ __forceinline__ float2 unpackbf(uint32_t u) {
    __nv_bfloat162 t = *reinterpret_cast<__nv_bfloat162*>(&u);
    return __bfloat1622float2(t);
}

#define LDSM_X4(r0, r1, r2, r3, addr) \
    asm volatile("ldmatrix.sync.aligned.m8n8.x4.shared.b16 {%0,%1,%2,%3}, [%4];" \
                 : "=r"(r0), "=r"(r1), "=r"(r2), "=r"(r3) : "r"(addr))

__device__ __forceinline__ void mma_bf16(float* c, uint32_t a0, uint32_t a1, uint32_t a2,
                                         uint32_t a3, uint32_t b0, uint32_t b1) {
    asm volatile(
        "mma.sync.aligned.m16n8k16.row.col.f32.bf16.bf16.f32 "
        "{%0,%1,%2,%3}, {%4,%5,%6,%7}, {%8,%9}, {%0,%1,%2,%3};"
        : "+f"(c[0]), "+f"(c[1]), "+f"(c[2]), "+f"(c[3])
        : "r"(a0), "r"(a1), "r"(a2), "r"(a3), "r"(b0), "r"(b1));
}

__device__ __forceinline__ uint32_t swz(uint32_t off) { return off ^ ((off >> 3) & 0x70); }

#define CP16(dst, src) \
    asm volatile("cp.async.cg.shared.global [%0], [%1], 16;" :: "r"(dst), "l"(src))
#define CP_COMMIT() asm volatile("cp.async.commit_group;" ::: "memory")
#define CP_WAIT(n)  asm volatile("cp.async.wait_group %0;" :: "n"(n) : "memory")

template <int ROWS>
__device__ __forceinline__ void ldchunk_async(const __nv_bfloat16* __restrict__ g, int row0,
                                              int ld, int k0, uint32_t sm, int tid) {
    for (int u = tid; u < ROWS * 8; u += 256) {
        int r = u >> 3, q = u & 7;
        const void* src = g + (size_t)(row0 + r) * ld + k0 + q * 8;
        CP16(sm + swz(r * 128 + q * 16), src);
    }
}

#define LOAD_AFRAG(a, sb, f, kb, lane)                                              \
    do {                                                                            \
        uint32_t off = (uint32_t)(((f) + ((lane) & 15)) * 128 + (kb) + (((lane) >> 4) << 4)); \
        LDSM_X4((a)[0], (a)[1], (a)[2], (a)[3], (sb) + swz(off));                   \
    } while (0)

#define LOAD_BFRAG(b0a, b0b, b1a, b1b, sb, n0, kb, lane)                            \
    do {                                                                            \
        int r = (n0) + ((lane) & 7) + (((lane) >> 4) << 3);                         \
        uint32_t off = (uint32_t)(r * 128 + (kb) + (((lane) >> 3) & 1) * 16);       \
        LDSM_X4(b0a, b0b, b1a, b1b, (sb) + swz(off));                               \
    } while (0)

// ---------------- weight transpose fp32 -> bf16 ----------------
__global__ __launch_bounds__(256) void k_transpose(const float* __restrict__ in,
                                                   int R, int C, int which) {
    __nv_bfloat16* out = (which == 0) ? g_winT : ((which == 1) ? g_woutT : g_wxT);
    __shared__ float tile[32][33];
    int c0 = blockIdx.x * 32, r0 = blockIdx.y * 32;
    int tx = threadIdx.x, ty = threadIdx.y;
#pragma unroll
    for (int i = 0; i < 4; i++) {
        int r = r0 + ty + 8 * i;
        if (r < R && c0 + tx < C) tile[ty + 8 * i][tx] = in[(size_t)r * C + c0 + tx];
    }
    __syncthreads();
#pragma unroll
    for (int i = 0; i < 4; i++) {
        int c = c0 + ty + 8 * i;
        if (c < C && r0 + tx < R)
            out[(size_t)c * R + r0 + tx] = __float2bfloat16(tile[tx][ty + 8 * i]);
    }
}

// ---------------- RMSNorm ----------------
__global__ __launch_bounds__(256) void k_rmsnorm(const float* __restrict__ feat,
                                                 const float* __restrict__ nw) {
    __shared__ float sred[8][32];
    __shared__ __align__(16) __nv_bfloat16 sX[32][264];
    int tx = threadIdx.x, ty = threadIdx.y;
    int t = blockIdx.y;
    int b = blockIdx.x * 32 + tx;
    const float* base = feat + (size_t)t * DM * NB + b;
    float v[32];
    float ss = 0.f;
#pragma unroll
    for (int i = 0; i < 32; i++) {
        float x = base[(size_t)(ty + 8 * i) * NB];
        v[i] = x;
        ss += x * x;
    }
    sred[ty][tx] = ss;
    __syncthreads();
    float tot = 0.f;
#pragma unroll
    for (int j = 0; j < 8; j++) tot += sred[j][tx];
    float sc = rsqrtf(tot * (1.f / DM) + 1e-5f);
#pragma unroll
    for (int i = 0; i < 32; i++)
        sX[tx][ty + 8 * i] = __float2bfloat16(v[i] * sc * nw[ty + 8 * i]);
    __syncthreads();
    int tid = ty * 32 + tx;
    size_t tok0 = (size_t)t * NB + blockIdx.x * 32;
    for (int u = tid; u < 32 * 32; u += 256) {
        int r = u >> 5, q = u & 31;
        *(uint4*)(g_xnbf + (tok0 + r) * DM + q * 8) = *(uint4*)&sX[r][q * 8];
    }
}

// ---------------- GEMM1 (HMMA; A preloaded, B 3-stage) ----------------
__global__ __launch_bounds__(256, 2) void k_gemm1() {
    extern __shared__ __align__(1024) char sm[];
    int tid = threadIdx.x, wid = tid >> 5, lane = tid & 31;
    int wy = wid >> 2, wx = wid & 3;
    int fbase = blockIdx.y * 128, tbase = blockIdx.x * 128;
    uint32_t sbA = smem_u32(sm);
    uint32_t sbB = sbA + 65536;
    float acc[4][4][4];
#pragma unroll
    for (int i = 0; i < 4; i++)
#pragma unroll
        for (int j = 0; j < 4; j++)
#pragma unroll
            for (int q = 0; q < 4; q++) acc[i][j][q] = 0.f;

#pragma unroll
    for (int c = 0; c < 4; c++)
        ldchunk_async<128>(g_winT, fbase, 256, c * 64, sbA + c * 16384, tid);
    ldchunk_async<128>(g_xnbf, tbase, 256, 0, sbB, tid);
    CP_COMMIT();
    ldchunk_async<128>(g_xnbf, tbase, 256, 64, sbB + 16384, tid);
    CP_COMMIT();

    for (int kc = 0; kc < 4; kc++) {
        CP_WAIT(1);
        __syncthreads();
        if (kc + 2 < 4)
            ldchunk_async<128>(g_xnbf, tbase, 256, (kc + 2) * 64, sbB + ((kc + 2) % 3) * 16384, tid);
        CP_COMMIT();
        uint32_t aCh = sbA + kc * 16384;
        uint32_t bCur = sbB + (kc % 3) * 16384;
#pragma unroll
        for (int ks = 0; ks < 4; ks++) {
            int kb = ks * 32;
            uint32_t b[4][2];
#pragma unroll
            for (int np = 0; np < 2; np++)
                LOAD_BFRAG(b[np * 2][0], b[np * 2][1], b[np * 2 + 1][0], b[np * 2 + 1][1],
                           bCur, wx * 32 + np * 16, kb, lane);
#pragma unroll
            for (int ft = 0; ft < 4; ft++) {
                uint32_t a[4];
                LOAD_AFRAG(a, aCh, wy * 64 + ft * 16, kb, lane);
#pragma unroll
                for (int nt = 0; nt < 4; nt++)
                    mma_bf16(acc[ft][nt], a[0], a[1], a[2], a[3], b[nt][0], b[nt][1]);
            }
        }
    }

    bool isRes = (fbase >= DI);
    __nv_bfloat16* base = isRes ? g_sresh : g_uh;
    int fb = isRes ? (fbase - DI) : fbase;
#pragma unroll
    for (int ft = 0; ft < 4; ft++) {
#pragma unroll
        for (int nt = 0; nt < 4; nt++) {
            float* c = acc[ft][nt];
            int f = fb + wy * 64 + ft * 16 + (lane >> 2);
            int m = tbase + wx * 32 + nt * 8 + (lane & 3) * 2;
            if (isRes) {
                *(uint32_t*)(base + (size_t)f * TOK + m)       = packbf(siluf(c[0]), siluf(c[1]));
                *(uint32_t*)(base + (size_t)(f + 8) * TOK + m) = packbf(siluf(c[2]), siluf(c[3]));
            } else {
                *(uint32_t*)(base + (size_t)f * TOK + m)       = packbf(c[0], c[1]);
                *(uint32_t*)(base + (size_t)(f + 8) * TOK + m) = packbf(c[2], c[3]);
            }
        }
    }
}

// ---------------- depthwise causal conv (k=3) + silu; dual-layout output ----------------
__global__ __launch_bounds__(256) void k_conv(const float* __restrict__ cw,
                                              const float* __restrict__ cb) {
    __shared__ __nv_bfloat16 sT[32][33];
    int tx = threadIdx.x, ty = threadIdx.y;
    int m = blockIdx.x * 32 + tx;
    int d0 = blockIdx.y * 32;
    int t = m >> 10;
#pragma unroll
    for (int i = 0; i < 4; i++) {
        int d = d0 + ty + 8 * i;
        size_t base = (size_t)d * TOK + m;
        float acc = cb[d] + cw[d * 3 + 2] * __bfloat162float(g_uh[base]);
        if (t >= 1) acc += cw[d * 3 + 1] * __bfloat162float(g_uh[base - NB]);
        if (t >= 2) acc += cw[d * 3 + 0] * __bfloat162float(g_uh[base - 2 * NB]);
        __nv_bfloat16 hb = __float2bfloat16(siluf(acc));
        g_xmh[base] = hb;
        sT[ty + 8 * i][tx] = hb;
    }
    __syncthreads();
#pragma unroll
    for (int i = 0; i < 4; i++) {
        int mm = blockIdx.x * 32 + ty + 8 * i;
        g_xmbf[(size_t)mm * DI + d0 + tx] = sT[tx][ty + 8 * i];
    }
}

// ---------------- xproj (HMMA): outputs g_dtin (token-major bf16) + g_bcp (packed pairs) ----------------
__global__ __launch_bounds__(256, 2) void k_xproj() {
    extern __shared__ __align__(1024) char sm[];
    int tid = threadIdx.x, wid = tid >> 5, lane = tid & 31;
    int tbase = blockIdx.x * 128;
    uint32_t sbA = smem_u32(sm);                       // 8 chunks x 6144B = 49152
    uint32_t sbB = sbA + 49152;                        // 3 stages x 16384
    float acc[3][2][4];
#pragma unroll
    for (int i = 0; i < 3; i++)
#pragma unroll
        for (int j = 0; j < 2; j++)
#pragma unroll
            for (int q = 0; q < 4; q++) acc[i][j][q] = 0.f;

#pragma unroll
    for (int c = 0; c < 8; c++)
        ldchunk_async<48>(g_wxT, 0, 512, c * 64, sbA + c * 6144, tid);
    ldchunk_async<128>(g_xmbf, tbase, 512, 0, sbB, tid);
    CP_COMMIT();
    ldchunk_async<128>(g_xmbf, tbase, 512, 64, sbB + 16384, tid);
    CP_COMMIT();

    for (int kc = 0; kc < 8; kc++) {
        CP_WAIT(1);
        __syncthreads();
        if (kc + 2 < 8)
            ldchunk_async<128>(g_xmbf, tbase, 512, (kc + 2) * 64, sbB + ((kc + 2) % 3) * 16384, tid);
        CP_COMMIT();
        uint32_t cur = sbB + (kc % 3) * 16384;
        uint32_t aCh = sbA + kc * 6144;
#pragma unroll
        for (int ks = 0; ks < 4; ks++) {
            int kb = ks * 32;
            uint32_t b[2][2];
            LOAD_BFRAG(b[0][0], b[0][1], b[1][0], b[1][1], cur, wid * 16, kb, lane);
#pragma unroll
            for (int ft = 0; ft < 3; ft++) {
                uint32_t a[4];
                LOAD_AFRAG(a, aCh, ft * 16, kb, lane);
#pragma unroll
                for (int nt = 0; nt < 2; nt++)
                    mma_bf16(acc[ft][nt], a[0], a[1], a[2], a[3], b[nt][0], b[nt][1]);
            }
        }
    }

    // stage results into smem (reuse B ring region; safe after mainloop + sync)
    __syncthreads();
    float* st = (float*)(sm + 49152);                  // [48][132]
#pragma unroll
    for (int ft = 0; ft < 3; ft++) {
#pragma unroll
        for (int nt = 0; nt < 2; nt++) {
            float* c = acc[ft][nt];
            int j = ft * 16 + (lane >> 2);
            int ml = wid * 16 + nt * 8 + (lane & 3) * 2;
            st[j * 132 + ml] = c[0];
            st[j * 132 + ml + 1] = c[1];
            st[(j + 8) * 132 + ml] = c[2];
            st[(j + 8) * 132 + ml + 1] = c[3];
        }
    }
    __syncthreads();
    // dtin: token-major [m][16] bf16
    if (tid < 128) {
        uint32_t w[8];
#pragma unroll
        for (int r = 0; r < 8; r++)
            w[r] = packbf(st[(2 * r) * 132 + tid], st[(2 * r + 1) * 132 + tid]);
        *(uint4*)(g_dtin + (size_t)(tbase + tid) * 16)     = *(uint4*)&w[0];
        *(uint4*)(g_dtin + (size_t)(tbase + tid) * 16 + 8) = *(uint4*)&w[4];
    }
    // bcp: 16 packed rows (B pairs then C pairs), channel-major
    for (int v = tid; v < 16 * 128; v += 256) {
        int rr = v >> 7, mm = v & 127;
        g_bcp[(size_t)rr * TOK + tbase + mm] =
            packbf(st[(16 + 2 * rr) * 132 + mm], st[(17 + 2 * rr) * 132 + mm]);
    }
}

// ---------------- dt: delta[d][m] = softplus(dtin[m][:] . w_dt[:][d] + b_dt[d]) ----------------
__global__ __launch_bounds__(256) void k_dt(const float* __restrict__ w_dt,
                                            const float* __restrict__ b_dt) {
    __shared__ float sW[16][64];
    __shared__ float sB[64];
    int tid = threadIdx.x;
    int m0 = blockIdx.x * 512, d0 = blockIdx.y * 64;
    for (int i = tid; i < 16 * 64; i += 256)
        sW[i >> 6][i & 63] = w_dt[(size_t)(i >> 6) * DI + d0 + (i & 63)];
    if (tid < 64) sB[tid] = b_dt[d0 + tid];
    __syncthreads();
    int m = m0 + tid * 2;
    uint4 p0 = *(const uint4*)(g_dtin + (size_t)m * 16);
    uint4 p1 = *(const uint4*)(g_dtin + (size_t)m * 16 + 8);
    uint4 q0 = *(const uint4*)(g_dtin + (size_t)(m + 1) * 16);
    uint4 q1 = *(const uint4*)(g_dtin + (size_t)(m + 1) * 16 + 8);
    float x0[16], x1[16];
    {
        const uint32_t* pu = (const uint32_t*)&p0;
        const uint32_t* pv = (const uint32_t*)&p1;
        const uint32_t* qu = (const uint32_t*)&q0;
        const uint32_t* qv = (const uint32_t*)&q1;
#pragma unroll
        for (int r = 0; r < 4; r++) {
            float2 a = unpackbf(pu[r]); x0[2 * r] = a.x; x0[2 * r + 1] = a.y;
            float2 b = unpackbf(pv[r]); x0[8 + 2 * r] = b.x; x0[9 + 2 * r] = b.y;
            float2 c = unpackbf(qu[r]); x1[2 * r] = c.x; x1[2 * r + 1] = c.y;
            float2 e = unpackbf(qv[r]); x1[8 + 2 * r] = e.x; x1[9 + 2 * r] = e.y;
        }
    }
    for (int dd = 0; dd < 64; dd++) {
        float a0 = sB[dd], a1 = sB[dd];
#pragma unroll
        for (int r = 0; r < 16; r++) {
            float w = sW[r][dd];
            a0 += x0[r] * w;
            a1 += x1[r] * w;
        }
        float2 o;
        o.x = softplusf(a0);
        o.y = softplusf(a1);
        *(float2*)(g_delta + (size_t)(d0 + dd) * TOK + m) = o;
    }
}

// ---------------- selective scan + D-skip + silu gate (16 d x 32 b per block) ----------------
__global__ __launch_bounds__(512) void k_scan(const float* __restrict__ A_log,
                                              const float* __restrict__ Dv) {
    __shared__ uint32_t sBC[16][32];
    __shared__ __nv_bfloat16 sY[16][32];
    int tx = threadIdx.x, ty = threadIdx.y;
    int tid = ty * 32 + tx;
    int b0 = blockIdx.x * 32;
    int d0 = blockIdx.y * 16;
    int d = d0 + ty;
    float A_[16];
    bool fast = true;
#pragma unroll
    for (int n = 0; n < 16; n++) {
        A_[n] = -__expf(A_log[d * 16 + n]);
        fast = fast && (fabsf(A_[n] + (float)(n + 1)) < 1e-3f * (n + 1));
    }
    float Dd = Dv[d];
    float h[16];
#pragma unroll
    for (int n = 0; n < 16; n++) h[n] = 0.f;

    for (int t = 0; t < NT; t++) {
        int tokbase = t * NB + b0;
        if (tid < 512) {
            int j = tid >> 5, c = tid & 31;
            if (j < 16) sBC[j][c] = g_bcp[(size_t)j * TOK + tokbase + c];
        }
        __syncthreads();

        size_t off = (size_t)d * TOK + tokbase + tx;
        float dlt = g_delta[off];
        float xv = __bfloat162float(g_xmh[off]);
        float dxu = dlt * xv;
        float y = 0.f;
        if (fast) {
            float p = __expf(-dlt), pn = 1.f;
#pragma unroll
            for (int r = 0; r < 8; r++) {
                float2 Bp = unpackbf(sBC[r][tx]);
                float2 Cp = unpackbf(sBC[8 + r][tx]);
                pn *= p;
                h[2 * r] = pn * h[2 * r] + dxu * Bp.x;
                y += h[2 * r] * Cp.x;
                pn *= p;
                h[2 * r + 1] = pn * h[2 * r + 1] + dxu * Bp.y;
                y += h[2 * r + 1] * Cp.y;
            }
        } else {
#pragma unroll
            for (int r = 0; r < 8; r++) {
                float2 Bp = unpackbf(sBC[r][tx]);
                float2 Cp = unpackbf(sBC[8 + r][tx]);
                float dA0 = __expf(dlt * A_[2 * r]);
                float dA1 = __expf(dlt * A_[2 * r + 1]);
                h[2 * r] = dA0 * h[2 * r] + dxu * Bp.x;
                y += h[2 * r] * Cp.x;
                h[2 * r + 1] = dA1 * h[2 * r + 1] + dxu * Bp.y;
                y += h[2 * r + 1] * Cp.y;
            }
        }
        float sres = __bfloat162float(g_sresh[off]);
        sY[ty][tx] = __float2bfloat16((y + xv * Dd) * sres);
        __syncthreads();
        int bl = tid >> 4, j = tid & 15;
        g_ybf[(size_t)(tokbase + bl) * DI + d0 + j] = sY[j][bl];
    }
}

// ---------------- GEMM out (HMMA + cp.async 3-stage) ----------------
__global__ __launch_bounds__(256, 2) void k_gemmout(const float* __restrict__ feat,
                                                    float* __restrict__ out) {
    extern __shared__ __align__(1024) char sm[];
    int tid = threadIdx.x, wid = tid >> 5, lane = tid & 31;
    int wy = wid >> 2, wx = wid & 3;
    int cbase = blockIdx.y * 128, tbase = blockIdx.x * 128;
    uint32_t sb = smem_u32(sm);
    float acc[4][4][4];
#pragma unroll
    for (int i = 0; i < 4; i++)
#pragma unroll
        for (int j = 0; j < 4; j++)
#pragma unroll
            for (int q = 0; q < 4; q++) acc[i][j][q] = 0.f;

#pragma unroll
    for (int s = 0; s < 2; s++) {
        ldchunk_async<128>(g_woutT, cbase, 512, s * 64, sb + s * 32768, tid);
        ldchunk_async<128>(g_ybf, tbase, 512, s * 64, sb + s * 32768 + 16384, tid);
        CP_COMMIT();
    }

    for (int kc = 0; kc < 8; kc++) {
        CP_WAIT(1);
        __syncthreads();
        if (kc + 2 < 8) {
            uint32_t nxt = sb + ((kc + 2) % 3) * 32768;
            ldchunk_async<128>(g_woutT, cbase, 512, (kc + 2) * 64, nxt, tid);
            ldchunk_async<128>(g_ybf, tbase, 512, (kc + 2) * 64, nxt + 16384, tid);
        }
        CP_COMMIT();
        uint32_t cur = sb + (kc % 3) * 32768;
        uint32_t sbA = cur, sbB = cur + 16384;
#pragma unroll
        for (int ks = 0; ks < 4; ks++) {
            int kb = ks * 32;
            uint32_t b[4][2];
#pragma unroll
            for (int np = 0; np < 2; np++)
                LOAD_BFRAG(b[np * 2][0], b[np * 2][1], b[np * 2 + 1][0], b[np * 2 + 1][1],
                           sbB, wx * 32 + np * 16, kb, lane);
#pragma unroll
            for (int ft = 0; ft < 4; ft++) {
                uint32_t a[4];
                LOAD_AFRAG(a, sbA, wy * 64 + ft * 16, kb, lane);
#pragma unroll
                for (int nt = 0; nt < 4; nt++)
                    mma_bf16(acc[ft][nt], a[0], a[1], a[2], a[3], b[nt][0], b[nt][1]);
            }
        }
    }

    int t = tbase >> 10;
#pragma unroll
    for (int ft = 0; ft < 4; ft++) {
#pragma unroll
        for (int nt = 0; nt < 4; nt++) {
            float* c = acc[ft][nt];
            int cc = cbase + wy * 64 + ft * 16 + (lane >> 2);
            int m = tbase + wx * 32 + nt * 8 + (lane & 3) * 2;
            int b = m & 1023;
            size_t o0 = (size_t)t * DM * NB + (size_t)cc * NB + b;
            size_t o1 = o0 + 8 * (size_t)NB;
            float2 f0 = *(const float2*)(feat + o0);
            float2 f1 = *(const float2*)(feat + o1);
            float2 v0; v0.x = c[0] + f0.x; v0.y = c[1] + f0.y;
            float2 v1; v1.x = c[2] + f1.x; v1.y = c[3] + f1.y;
            *(float2*)(out + o0) = v0;
            *(float2*)(out + o1) = v1;
        }
    }
}

extern "C" void kernel_launch(void* const* d_in, const int* in_sizes, int n_in,
                              void* d_out, int out_size) {
    const float* feature = (const float*)d_in[0];
    const float* norm_w  = (const float*)d_in[1];
    const float* w_in    = (const float*)d_in[2];
    const float* conv_w  = (const float*)d_in[3];
    const float* conv_b  = (const float*)d_in[4];
    const float* w_xproj = (const float*)d_in[5];
    const float* w_dt    = (const float*)d_in[6];
    const float* b_dt    = (const float*)d_in[7];
    const float* A_log   = (const float*)d_in[8];
    const float* Dv      = (const float*)d_in[9];
    const float* w_out   = (const float*)d_in[10];
    float* out = (float*)d_out;

    const int SMEM_G1   = 65536 + 3 * 16384;  // 114688
    const int SMEM_GOUT = 3 * 32768;
    const int SMEM_XP   = 49152 + 3 * 16384;
    cudaFuncSetAttribute(k_gemm1, cudaFuncAttributeMaxDynamicSharedMemorySize, SMEM_G1);
    cudaFuncSetAttribute(k_xproj, cudaFuncAttributeMaxDynamicSharedMemorySize, SMEM_XP);
    cudaFuncSetAttribute(k_gemmout, cudaFuncAttributeMaxDynamicSharedMemorySize, SMEM_GOUT);

    k_transpose<<<dim3(32, 8), dim3(32, 8)>>>(w_in, 256, 1024, 0);
    k_transpose<<<dim3(2, 16), dim3(32, 8)>>>(w_xproj, 512, 48, 2);
    k_rmsnorm<<<dim3(32, 16), dim3(32, 8)>>>(feature, norm_w);
    k_gemm1<<<dim3(128, 8), 256, SMEM_G1>>>();           // launch #4 -> ncu slot
    k_conv<<<dim3(512, 16), dim3(32, 8)>>>(conv_w, conv_b);
    k_xproj<<<dim3(128, 1), 256, SMEM_XP>>>();
    k_dt<<<dim3(32, 8), 256>>>(w_dt, b_dt);
    k_scan<<<dim3(32, 32), dim3(32, 16)>>>(A_log, Dv);
    k_transpose<<<dim3(8, 16), dim3(32, 8)>>>(w_out, 512, 256, 1);
    k_gemmout<<<dim3(128, 2), 256, SMEM_GOUT>>>(feature, out);
}

// round 10
// speedup vs baseline: 2.5561x; 1.1131x over previous
#include <cuda_runtime.h>
#include <cuda_bf16.h>
#include <cstdint>

#define NB 1024      // sequences (spatial positions)
#define NT 16        // sequence length (original batch)
#define TOK 16384    // NB*NT tokens, token = t*NB + b
#define DM 256
#define DI 512

// ---------------- scratch (__device__ globals; no allocations) ----------------
__device__ __align__(128) __nv_bfloat16 g_winT[1024 * 256];   // w_in^T  [n][k=256]
__device__ __align__(128) __nv_bfloat16 g_woutT[256 * 512];   // w_out^T [c][d=512]
__device__ __align__(128) __nv_bfloat16 g_wxT[48 * 512];      // w_xproj^T [j][d=512]
__device__ __align__(128) __nv_bfloat16 g_wdth[16 * 512];     // w_dt bf16 [r][d]
__device__ __align__(128) __nv_bfloat16 g_xnbf[TOK * DM];     // rmsnorm out, token-major [m][k]
__device__ __align__(128) __nv_bfloat16 g_uh[DI * TOK];       // pre-conv, channel-major [d][m]
__device__ __align__(128) __nv_bfloat16 g_sresh[DI * TOK];    // silu(res), channel-major
__device__ __align__(128) __nv_bfloat16 g_xmh[DI * TOK];      // post conv+silu, channel-major
__device__ __align__(128) __nv_bfloat16 g_xmbf[TOK * DI];     // same, token-major [m][d]
__device__ __align__(128) uint32_t      g_bcp[16 * TOK];      // packed bf16x2: r<8 B-pairs, r>=8 C-pairs
__device__ __align__(128) __nv_bfloat16 g_deltah[DI * TOK];   // softplus delta bf16, channel-major
__device__ __align__(128) __nv_bfloat16 g_ybf[TOK * DI];      // gated scan out, token-major

// ---------------- helpers ----------------
__device__ __forceinline__ uint32_t smem_u32(const void* p) {
    uint32_t a;
    asm("{ .reg .u64 t; cvta.to.shared.u64 t, %1; cvt.u32.u64 %0, t; }" : "=r"(a) : "l"(p));
    return a;
}
__device__ __forceinline__ float siluf(float x) { return __fdividef(x, 1.f + __expf(-x)); }
__device__ __forceinline__ float softplusf(float x) {
    return fmaxf(x, 0.f) + __logf(1.f + __expf(-fabsf(x)));
}
__device__ __forceinline__ uint32_t packbf(float a, float b) {
    __nv_bfloat162 t = __floats2bfloat162_rn(a, b);
    return *reinterpret_cast<uint32_t*>(&t);
}
__device__ __forceinline__ float2 unpackbf(uint32_t u) {
    __nv_bfloat162 t = *reinterpret_cast<__nv_bfloat162*>(&u);
    return __bfloat1622float2(t);
}

#define LDSM_X4(r0, r1, r2, r3, addr) \
    asm volatile("ldmatrix.sync.aligned.m8n8.x4.shared.b16 {%0,%1,%2,%3}, [%4];" \
                 : "=r"(r0), "=r"(r1), "=r"(r2), "=r"(r3) : "r"(addr))

__device__ __forceinline__ void mma_bf16(float* c, uint32_t a0, uint32_t a1, uint32_t a2,
                                         uint32_t a3, uint32_t b0, uint32_t b1) {
    asm volatile(
        "mma.sync.aligned.m16n8k16.row.col.f32.bf16.bf16.f32 "
        "{%0,%1,%2,%3}, {%4,%5,%6,%7}, {%8,%9}, {%0,%1,%2,%3};"
        : "+f"(c[0]), "+f"(c[1]), "+f"(c[2]), "+f"(c[3])
        : "r"(a0), "r"(a1), "r"(a2), "r"(a3), "r"(b0), "r"(b1));
}

__device__ __forceinline__ uint32_t swz(uint32_t off) { return off ^ ((off >> 3) & 0x70); }

#define CP16(dst, src) \
    asm volatile("cp.async.cg.shared.global [%0], [%1], 16;" :: "r"(dst), "l"(src))
#define CP_COMMIT() asm volatile("cp.async.commit_group;" ::: "memory")
#define CP_WAIT(n)  asm volatile("cp.async.wait_group %0;" :: "n"(n) : "memory")

template <int ROWS>
__device__ __forceinline__ void ldchunk_async(const __nv_bfloat16* __restrict__ g, int row0,
                                              int ld, int k0, uint32_t sm, int tid) {
    for (int u = tid; u < ROWS * 8; u += 256) {
        int r = u >> 3, q = u & 7;
        const void* src = g + (size_t)(row0 + r) * ld + k0 + q * 8;
        CP16(sm + swz(r * 128 + q * 16), src);
    }
}

#define LOAD_AFRAG(a, sb, f, kb, lane)                                              \
    do {                                                                            \
        uint32_t off = (uint32_t)(((f) + ((lane) & 15)) * 128 + (kb) + (((lane) >> 4) << 4)); \
        LDSM_X4((a)[0], (a)[1], (a)[2], (a)[3], (sb) + swz(off));                   \
    } while (0)

#define LOAD_BFRAG(b0a, b0b, b1a, b1b, sb, n0, kb, lane)                            \
    do {                                                                            \
        int r = (n0) + ((lane) & 7) + (((lane) >> 4) << 3);                         \
        uint32_t off = (uint32_t)(r * 128 + (kb) + (((lane) >> 3) & 1) * 16);       \
        LDSM_X4(b0a, b0b, b1a, b1b, (sb) + swz(off));                               \
    } while (0)

// ---------------- combined weight prep: 3 transposes + w_dt convert ----------------
__global__ __launch_bounds__(256) void k_prep(const float* __restrict__ w_in,
                                              const float* __restrict__ w_out,
                                              const float* __restrict__ w_xproj,
                                              const float* __restrict__ w_dt) {
    __shared__ float tile[32][33];
    int which = blockIdx.z;
    int tx = threadIdx.x, ty = threadIdx.y;
    if (which == 3) {
        int idx = (blockIdx.y * gridDim.x + blockIdx.x) * 256 + ty * 32 + tx;
        if (idx < 16 * 512) g_wdth[idx] = __float2bfloat16(w_dt[idx]);
        return;
    }
    const float* in = (which == 0) ? w_in : ((which == 1) ? w_out : w_xproj);
    __nv_bfloat16* out = (which == 0) ? g_winT : ((which == 1) ? g_woutT : g_wxT);
    int R = (which == 0) ? 256 : 512;
    int C = (which == 0) ? 1024 : ((which == 1) ? 256 : 48);
    int c0 = blockIdx.x * 32, r0 = blockIdx.y * 32;
    if (c0 >= C || r0 >= R) return;
#pragma unroll
    for (int i = 0; i < 4; i++) {
        int r = r0 + ty + 8 * i;
        if (r < R && c0 + tx < C) tile[ty + 8 * i][tx] = in[(size_t)r * C + c0 + tx];
    }
    __syncthreads();
#pragma unroll
    for (int i = 0; i < 4; i++) {
        int c = c0 + ty + 8 * i;
        if (c < C && r0 + tx < R)
            out[(size_t)c * R + r0 + tx] = __float2bfloat16(tile[tx][ty + 8 * i]);
    }
}

// ---------------- RMSNorm ----------------
__global__ __launch_bounds__(256) void k_rmsnorm(const float* __restrict__ feat,
                                                 const float* __restrict__ nw) {
    __shared__ float sred[8][32];
    __shared__ __align__(16) __nv_bfloat16 sX[32][264];
    int tx = threadIdx.x, ty = threadIdx.y;
    int t = blockIdx.y;
    int b = blockIdx.x * 32 + tx;
    const float* base = feat + (size_t)t * DM * NB + b;
    float v[32];
    float ss = 0.f;
#pragma unroll
    for (int i = 0; i < 32; i++) {
        float x = base[(size_t)(ty + 8 * i) * NB];
        v[i] = x;
        ss += x * x;
    }
    sred[ty][tx] = ss;
    __syncthreads();
    float tot = 0.f;
#pragma unroll
    for (int j = 0; j < 8; j++) tot += sred[j][tx];
    float sc = rsqrtf(tot * (1.f / DM) + 1e-5f);
#pragma unroll
    for (int i = 0; i < 32; i++)
        sX[tx][ty + 8 * i] = __float2bfloat16(v[i] * sc * nw[ty + 8 * i]);
    __syncthreads();
    int tid = ty * 32 + tx;
    size_t tok0 = (size_t)t * NB + blockIdx.x * 32;
    for (int u = tid; u < 32 * 32; u += 256) {
        int r = u >> 5, q = u & 31;
        *(uint4*)(g_xnbf + (tok0 + r) * DM + q * 8) = *(uint4*)&sX[r][q * 8];
    }
}

// ---------------- GEMM1 (HMMA; A preloaded, B 3-stage) ----------------
__global__ __launch_bounds__(256, 2) void k_gemm1() {
    extern __shared__ __align__(1024) char sm[];
    int tid = threadIdx.x, wid = tid >> 5, lane = tid & 31;
    int wy = wid >> 2, wx = wid & 3;
    int fbase = blockIdx.y * 128, tbase = blockIdx.x * 128;
    uint32_t sbA = smem_u32(sm);
    uint32_t sbB = sbA + 65536;
    float acc[4][4][4];
#pragma unroll
    for (int i = 0; i < 4; i++)
#pragma unroll
        for (int j = 0; j < 4; j++)
#pragma unroll
            for (int q = 0; q < 4; q++) acc[i][j][q] = 0.f;

#pragma unroll
    for (int c = 0; c < 4; c++)
        ldchunk_async<128>(g_winT, fbase, 256, c * 64, sbA + c * 16384, tid);
    ldchunk_async<128>(g_xnbf, tbase, 256, 0, sbB, tid);
    CP_COMMIT();
    ldchunk_async<128>(g_xnbf, tbase, 256, 64, sbB + 16384, tid);
    CP_COMMIT();

    for (int kc = 0; kc < 4; kc++) {
        CP_WAIT(1);
        __syncthreads();
        if (kc + 2 < 4)
            ldchunk_async<128>(g_xnbf, tbase, 256, (kc + 2) * 64, sbB + ((kc + 2) % 3) * 16384, tid);
        CP_COMMIT();
        uint32_t aCh = sbA + kc * 16384;
        uint32_t bCur = sbB + (kc % 3) * 16384;
#pragma unroll
        for (int ks = 0; ks < 4; ks++) {
            int kb = ks * 32;
            uint32_t b[4][2];
#pragma unroll
            for (int np = 0; np < 2; np++)
                LOAD_BFRAG(b[np * 2][0], b[np * 2][1], b[np * 2 + 1][0], b[np * 2 + 1][1],
                           bCur, wx * 32 + np * 16, kb, lane);
#pragma unroll
            for (int ft = 0; ft < 4; ft++) {
                uint32_t a[4];
                LOAD_AFRAG(a, aCh, wy * 64 + ft * 16, kb, lane);
#pragma unroll
                for (int nt = 0; nt < 4; nt++)
                    mma_bf16(acc[ft][nt], a[0], a[1], a[2], a[3], b[nt][0], b[nt][1]);
            }
        }
    }

    bool isRes = (fbase >= DI);
    __nv_bfloat16* base = isRes ? g_sresh : g_uh;
    int fb = isRes ? (fbase - DI) : fbase;
#pragma unroll
    for (int ft = 0; ft < 4; ft++) {
#pragma unroll
        for (int nt = 0; nt < 4; nt++) {
            float* c = acc[ft][nt];
            int f = fb + wy * 64 + ft * 16 + (lane >> 2);
            int m = tbase + wx * 32 + nt * 8 + (lane & 3) * 2;
            if (isRes) {
                *(uint32_t*)(base + (size_t)f * TOK + m)       = packbf(siluf(c[0]), siluf(c[1]));
                *(uint32_t*)(base + (size_t)(f + 8) * TOK + m) = packbf(siluf(c[2]), siluf(c[3]));
            } else {
                *(uint32_t*)(base + (size_t)f * TOK + m)       = packbf(c[0], c[1]);
                *(uint32_t*)(base + (size_t)(f + 8) * TOK + m) = packbf(c[2], c[3]);
            }
        }
    }
}

// ---------------- depthwise causal conv (k=3) + silu; dual-layout output ----------------
__global__ __launch_bounds__(256) void k_conv(const float* __restrict__ cw,
                                              const float* __restrict__ cb) {
    __shared__ __nv_bfloat16 sT[32][33];
    int tx = threadIdx.x, ty = threadIdx.y;
    int m = blockIdx.x * 32 + tx;
    int d0 = blockIdx.y * 32;
    int t = m >> 10;
#pragma unroll
    for (int i = 0; i < 4; i++) {
        int d = d0 + ty + 8 * i;
        size_t base = (size_t)d * TOK + m;
        float acc = cb[d] + cw[d * 3 + 2] * __bfloat162float(g_uh[base]);
        if (t >= 1) acc += cw[d * 3 + 1] * __bfloat162float(g_uh[base - NB]);
        if (t >= 2) acc += cw[d * 3 + 0] * __bfloat162float(g_uh[base - 2 * NB]);
        __nv_bfloat16 hb = __float2bfloat16(siluf(acc));
        g_xmh[base] = hb;
        sT[ty + 8 * i][tx] = hb;
    }
    __syncthreads();
#pragma unroll
    for (int i = 0; i < 4; i++) {
        int mm = blockIdx.x * 32 + ty + 8 * i;
        g_xmbf[(size_t)mm * DI + d0 + tx] = sT[tx][ty + 8 * i];
    }
}

// ---------------- xproj (HMMA) + fused dt: outputs g_bcp + g_deltah ----------------
__global__ __launch_bounds__(256) void k_xproj(const float* __restrict__ b_dt) {
    extern __shared__ __align__(1024) char sm[];
    int tid = threadIdx.x, wid = tid >> 5, lane = tid & 31;
    int tbase = blockIdx.x * 128;
    uint32_t sbA = smem_u32(sm);                       // 8 chunks x 6144B = 49152
    uint32_t sbB = sbA + 49152;                        // 3 stages x 16384 -> 98304
    uint32_t sbW = sbA + 98304;                        // w_dt bf16 16x512 = 16384
    uint32_t sbBD = sbA + 114688;                      // b_dt fp32 = 2048
    float acc[3][2][4];
#pragma unroll
    for (int i = 0; i < 3; i++)
#pragma unroll
        for (int j = 0; j < 2; j++)
#pragma unroll
            for (int q = 0; q < 4; q++) acc[i][j][q] = 0.f;

#pragma unroll
    for (int c = 0; c < 8; c++)
        ldchunk_async<48>(g_wxT, 0, 512, c * 64, sbA + c * 6144, tid);
    // stage w_dt + b_dt alongside the first group
    for (int u = tid; u < 1024; u += 256) CP16(sbW + u * 16, g_wdth + u * 8);
    for (int u = tid; u < 128; u += 256) CP16(sbBD + u * 16, b_dt + u * 4);
    ldchunk_async<128>(g_xmbf, tbase, 512, 0, sbB, tid);
    CP_COMMIT();
    ldchunk_async<128>(g_xmbf, tbase, 512, 64, sbB + 16384, tid);
    CP_COMMIT();

    for (int kc = 0; kc < 8; kc++) {
        CP_WAIT(1);
        __syncthreads();
        if (kc + 2 < 8)
            ldchunk_async<128>(g_xmbf, tbase, 512, (kc + 2) * 64, sbB + ((kc + 2) % 3) * 16384, tid);
        CP_COMMIT();
        uint32_t cur = sbB + (kc % 3) * 16384;
        uint32_t aCh = sbA + kc * 6144;
#pragma unroll
        for (int ks = 0; ks < 4; ks++) {
            int kb = ks * 32;
            uint32_t b[2][2];
            LOAD_BFRAG(b[0][0], b[0][1], b[1][0], b[1][1], cur, wid * 16, kb, lane);
#pragma unroll
            for (int ft = 0; ft < 3; ft++) {
                uint32_t a[4];
                LOAD_AFRAG(a, aCh, ft * 16, kb, lane);
#pragma unroll
                for (int nt = 0; nt < 2; nt++)
                    mma_bf16(acc[ft][nt], a[0], a[1], a[2], a[3], b[nt][0], b[nt][1]);
            }
        }
    }

    // stage results into smem (reuse B ring region; safe after mainloop + sync)
    __syncthreads();
    float* st = (float*)(sm + 49152);                  // [48][132]
#pragma unroll
    for (int ft = 0; ft < 3; ft++) {
#pragma unroll
        for (int nt = 0; nt < 2; nt++) {
            float* c = acc[ft][nt];
            int j = ft * 16 + (lane >> 2);
            int ml = wid * 16 + nt * 8 + (lane & 3) * 2;
            st[j * 132 + ml] = c[0];
            st[j * 132 + ml + 1] = c[1];
            st[(j + 8) * 132 + ml] = c[2];
            st[(j + 8) * 132 + ml + 1] = c[3];
        }
    }
    __syncthreads();
    // bcp: 16 packed rows (B pairs then C pairs), channel-major
    for (int v = tid; v < 16 * 128; v += 256) {
        int rr = v >> 7, mm = v & 127;
        g_bcp[(size_t)rr * TOK + tbase + mm] =
            packbf(st[(16 + 2 * rr) * 132 + mm], st[(17 + 2 * rr) * 132 + mm]);
    }
    // fused dt: delta[d][token] = softplus(b_dt[d] + sum_r st[r][token]*w_dt[r][d])
    {
        int token = tid & 63, dg = tid >> 6;            // 4 d-groups of 128
        const __nv_bfloat16* wd = (const __nv_bfloat16*)(sm + 98304);
        const float* bd = (const float*)(sm + 114688);
        float x0[16], x1[16];
#pragma unroll
        for (int r = 0; r < 16; r++) {
            x0[r] = st[r * 132 + token];
            x1[r] = st[r * 132 + token + 64];
        }
        for (int db = 0; db < 128; db += 8) {
            int d = dg * 128 + db;
            float a0[8], a1[8];
#pragma unroll
            for (int i = 0; i < 8; i++) { a0[i] = bd[d + i]; a1[i] = a0[i]; }
#pragma unroll
            for (int r = 0; r < 16; r++) {
                uint4 w4 = *(const uint4*)(wd + r * 512 + d);
                const uint32_t* wp = (const uint32_t*)&w4;
#pragma unroll
                for (int p = 0; p < 4; p++) {
                    float2 w = unpackbf(wp[p]);
                    a0[2 * p] += x0[r] * w.x;  a0[2 * p + 1] += x0[r] * w.y;
                    a1[2 * p] += x1[r] * w.x;  a1[2 * p + 1] += x1[r] * w.y;
                }
            }
#pragma unroll
            for (int i = 0; i < 8; i++) {
                g_deltah[(size_t)(d + i) * TOK + tbase + token] =
                    __float2bfloat16(softplusf(a0[i]));
                g_deltah[(size_t)(d + i) * TOK + tbase + token + 64] =
                    __float2bfloat16(softplusf(a1[i]));
            }
        }
    }
}

// ---------------- selective scan + D-skip + silu gate (16 d x 32 b, 1 sync/t) ----------------
__global__ __launch_bounds__(512) void k_scan(const float* __restrict__ A_log,
                                              const float* __restrict__ Dv) {
    __shared__ uint32_t sBC[2][16][32];
    __shared__ __nv_bfloat16 sY[2][16][32];
    int tx = threadIdx.x, ty = threadIdx.y;
    int tid = ty * 32 + tx;
    int b0 = blockIdx.x * 32;
    int d0 = blockIdx.y * 16;
    int d = d0 + ty;
    float A_[16];
    bool fast = true;
#pragma unroll
    for (int n = 0; n < 16; n++) {
        A_[n] = -__expf(A_log[d * 16 + n]);
        fast = fast && (fabsf(A_[n] + (float)(n + 1)) < 1e-3f * (n + 1));
    }
    float Dd = Dv[d];
    float h[16];
#pragma unroll
    for (int n = 0; n < 16; n++) h[n] = 0.f;

    int j0 = tid >> 5, c0 = tid & 31;
    sBC[0][j0][c0] = g_bcp[(size_t)j0 * TOK + b0 + c0];
    __syncthreads();

    for (int t = 0; t < NT; t++) {
        int cur = t & 1;
        int tokbase = t * NB + b0;
        if (t + 1 < NT)
            sBC[cur ^ 1][j0][c0] = g_bcp[(size_t)j0 * TOK + (t + 1) * NB + b0 + c0];

        size_t off = (size_t)d * TOK + tokbase + tx;
        float dlt = __bfloat162float(g_deltah[off]);
        float xv = __bfloat162float(g_xmh[off]);
        float dxu = dlt * xv;
        float y = 0.f;
        if (fast) {
            float p = __expf(-dlt), pn = 1.f;
#pragma unroll
            for (int r = 0; r < 8; r++) {
                float2 Bp = unpackbf(sBC[cur][r][tx]);
                float2 Cp = unpackbf(sBC[cur][8 + r][tx]);
                pn *= p;
                h[2 * r] = pn * h[2 * r] + dxu * Bp.x;
                y += h[2 * r] * Cp.x;
                pn *= p;
                h[2 * r + 1] = pn * h[2 * r + 1] + dxu * Bp.y;
                y += h[2 * r + 1] * Cp.y;
            }
        } else {
#pragma unroll
            for (int r = 0; r < 8; r++) {
                float2 Bp = unpackbf(sBC[cur][r][tx]);
                float2 Cp = unpackbf(sBC[cur][8 + r][tx]);
                float dA0 = __expf(dlt * A_[2 * r]);
                float dA1 = __expf(dlt * A_[2 * r + 1]);
                h[2 * r] = dA0 * h[2 * r] + dxu * Bp.x;
                y += h[2 * r] * Cp.x;
                h[2 * r + 1] = dA1 * h[2 * r + 1] + dxu * Bp.y;
                y += h[2 * r + 1] * Cp.y;
            }
        }
        float sres = __bfloat162float(g_sresh[off]);
        sY[cur][ty][tx] = __float2bfloat16((y + xv * Dd) * sres);
        __syncthreads();
        int bl = tid >> 4, j = tid & 15;
        g_ybf[(size_t)(tokbase + bl) * DI + d0 + j] = sY[cur][j][bl];
    }
}

// ---------------- GEMM out (HMMA + cp.async 3-stage) ----------------
__global__ __launch_bounds__(256, 2) void k_gemmout(const float* __restrict__ feat,
                                                    float* __restrict__ out) {
    extern __shared__ __align__(1024) char sm[];
    int tid = threadIdx.x, wid = tid >> 5, lane = tid & 31;
    int wy = wid >> 2, wx = wid & 3;
    int cbase = blockIdx.y * 128, tbase = blockIdx.x * 128;
    uint32_t sb = smem_u32(sm);
    float acc[4][4][4];
#pragma unroll
    for (int i = 0; i < 4; i++)
#pragma unroll
        for (int j = 0; j < 4; j++)
#pragma unroll
            for (int q = 0; q < 4; q++) acc[i][j][q] = 0.f;

#pragma unroll
    for (int s = 0; s < 2; s++) {
        ldchunk_async<128>(g_woutT, cbase, 512, s * 64, sb + s * 32768, tid);
        ldchunk_async<128>(g_ybf, tbase, 512, s * 64, sb + s * 32768 + 16384, tid);
        CP_COMMIT();
    }

    for (int kc = 0; kc < 8; kc++) {
        CP_WAIT(1);
        __syncthreads();
        if (kc + 2 < 8) {
            uint32_t nxt = sb + ((kc + 2) % 3) * 32768;
            ldchunk_async<128>(g_woutT, cbase, 512, (kc + 2) * 64, nxt, tid);
            ldchunk_async<128>(g_ybf, tbase, 512, (kc + 2) * 64, nxt + 16384, tid);
        }
        CP_COMMIT();
        uint32_t cur = sb + (kc % 3) * 32768;
        uint32_t sbA = cur, sbB = cur + 16384;
#pragma unroll
        for (int ks = 0; ks < 4; ks++) {
            int kb = ks * 32;
            uint32_t b[4][2];
#pragma unroll
            for (int np = 0; np < 2; np++)
                LOAD_BFRAG(b[np * 2][0], b[np * 2][1], b[np * 2 + 1][0], b[np * 2 + 1][1],
                           sbB, wx * 32 + np * 16, kb, lane);
#pragma unroll
            for (int ft = 0; ft < 4; ft++) {
                uint32_t a[4];
                LOAD_AFRAG(a, sbA, wy * 64 + ft * 16, kb, lane);
#pragma unroll
                for (int nt = 0; nt < 4; nt++)
                    mma_bf16(acc[ft][nt], a[0], a[1], a[2], a[3], b[nt][0], b[nt][1]);
            }
        }
    }

    int t = tbase >> 10;
#pragma unroll
    for (int ft = 0; ft < 4; ft++) {
#pragma unroll
        for (int nt = 0; nt < 4; nt++) {
            float* c = acc[ft][nt];
            int cc = cbase + wy * 64 + ft * 16 + (lane >> 2);
            int m = tbase + wx * 32 + nt * 8 + (lane & 3) * 2;
            int b = m & 1023;
            size_t o0 = (size_t)t * DM * NB + (size_t)cc * NB + b;
            size_t o1 = o0 + 8 * (size_t)NB;
            float2 f0 = *(const float2*)(feat + o0);
            float2 f1 = *(const float2*)(feat + o1);
            float2 v0; v0.x = c[0] + f0.x; v0.y = c[1] + f0.y;
            float2 v1; v1.x = c[2] + f1.x; v1.y = c[3] + f1.y;
            *(float2*)(out + o0) = v0;
            *(float2*)(out + o1) = v1;
        }
    }
}

extern "C" void kernel_launch(void* const* d_in, const int* in_sizes, int n_in,
                              void* d_out, int out_size) {
    const float* feature = (const float*)d_in[0];
    const float* norm_w  = (const float*)d_in[1];
    const float* w_in    = (const float*)d_in[2];
    const float* conv_w  = (const float*)d_in[3];
    const float* conv_b  = (const float*)d_in[4];
    const float* w_xproj = (const float*)d_in[5];
    const float* w_dt    = (const float*)d_in[6];
    const float* b_dt    = (const float*)d_in[7];
    const float* A_log   = (const float*)d_in[8];
    const float* Dv      = (const float*)d_in[9];
    const float* w_out   = (const float*)d_in[10];
    float* out = (float*)d_out;

    const int SMEM_G1   = 65536 + 3 * 16384;      // 114688
    const int SMEM_GOUT = 3 * 32768;
    const int SMEM_XP   = 49152 + 3 * 16384 + 16384 + 2048;  // 116736
    cudaFuncSetAttribute(k_gemm1, cudaFuncAttributeMaxDynamicSharedMemorySize, SMEM_G1);
    cudaFuncSetAttribute(k_xproj, cudaFuncAttributeMaxDynamicSharedMemorySize, SMEM_XP);
    cudaFuncSetAttribute(k_gemmout, cudaFuncAttributeMaxDynamicSharedMemorySize, SMEM_GOUT);

    k_prep<<<dim3(32, 16, 4), dim3(32, 8)>>>(w_in, w_out, w_xproj, w_dt);
    k_rmsnorm<<<dim3(32, 16), dim3(32, 8)>>>(feature, norm_w);
    k_gemm1<<<dim3(128, 8), 256, SMEM_G1>>>();
    k_conv<<<dim3(512, 16), dim3(32, 8)>>>(conv_w, conv_b);
    k_xproj<<<dim3(128, 1), 256, SMEM_XP>>>(b_dt);
    k_scan<<<dim3(32, 32), dim3(32, 16)>>>(A_log, Dv);
    k_gemmout<<<dim3(128, 2), 256, SMEM_GOUT>>>(feature, out);
}

// round 11
// speedup vs baseline: 2.7861x; 1.0900x over previous
#include <cuda_runtime.h>
#include <cuda_bf16.h>
#include <cstdint>

#define NB 1024      // sequences (spatial positions)
#define NT 16        // sequence length (original batch)
#define TOK 16384    // NB*NT tokens, token = t*NB + b
#define DM 256
#define DI 512

// ---------------- scratch (__device__ globals; no allocations) ----------------
__device__ __align__(128) __nv_bfloat16 g_winT[1024 * 256];   // w_in^T  [n][k=256]
__device__ __align__(128) __nv_bfloat16 g_woutT[256 * 512];   // w_out^T [c][d=512]
__device__ __align__(128) __nv_bfloat16 g_wxT[48 * 512];      // w_xproj^T [j][d=512]
__device__ __align__(128) __nv_bfloat16 g_wdth[16 * 512];     // w_dt bf16 [r][d]
__device__ __align__(128) __nv_bfloat16 g_xnbf[TOK * DM];     // rmsnorm out, token-major [m][k]
__device__ __align__(128) __nv_bfloat16 g_uh[DI * TOK];       // pre-conv, channel-major [d][m]
__device__ __align__(128) __nv_bfloat16 g_sresh[DI * TOK];    // silu(res), channel-major
__device__ __align__(128) __nv_bfloat16 g_xmh[DI * TOK];      // post conv+silu, channel-major
__device__ __align__(128) __nv_bfloat16 g_xmbf[TOK * DI];     // same, token-major [m][d]
__device__ __align__(128) uint32_t      g_bcp[16 * TOK];      // packed bf16x2: r<8 B-pairs, r>=8 C-pairs
__device__ __align__(128) __nv_bfloat16 g_deltah[DI * TOK];   // softplus delta bf16, channel-major
__device__ __align__(128) __nv_bfloat16 g_ybf[TOK * DI];      // gated scan out, token-major

// ---------------- helpers ----------------
__device__ __forceinline__ uint32_t smem_u32(const void* p) {
    uint32_t a;
    asm("{ .reg .u64 t; cvta.to.shared.u64 t, %1; cvt.u32.u64 %0, t; }" : "=r"(a) : "l"(p));
    return a;
}
__device__ __forceinline__ float siluf(float x) { return __fdividef(x, 1.f + __expf(-x)); }
__device__ __forceinline__ float softplusf(float x) {
    return fmaxf(x, 0.f) + __logf(1.f + __expf(-fabsf(x)));
}
__device__ __forceinline__ uint32_t packbf(float a, float b) {
    __nv_bfloat162 t = __floats2bfloat162_rn(a, b);
    return *reinterpret_cast<uint32_t*>(&t);
}
__device__ __forceinline__ float2 unpackbf(uint32_t u) {
    __nv_bfloat162 t = *reinterpret_cast<__nv_bfloat162*>(&u);
    return __bfloat1622float2(t);
}

#define LDSM_X4(r0, r1, r2, r3, addr) \
    asm volatile("ldmatrix.sync.aligned.m8n8.x4.shared.b16 {%0,%1,%2,%3}, [%4];" \
                 : "=r"(r0), "=r"(r1), "=r"(r2), "=r"(r3) : "r"(addr))

__device__ __forceinline__ void mma_bf16(float* c, uint32_t a0, uint32_t a1, uint32_t a2,
                                         uint32_t a3, uint32_t b0, uint32_t b1) {
    asm volatile(
        "mma.sync.aligned.m16n8k16.row.col.f32.bf16.bf16.f32 "
        "{%0,%1,%2,%3}, {%4,%5,%6,%7}, {%8,%9}, {%0,%1,%2,%3};"
        : "+f"(c[0]), "+f"(c[1]), "+f"(c[2]), "+f"(c[3])
        : "r"(a0), "r"(a1), "r"(a2), "r"(a3), "r"(b0), "r"(b1));
}

__device__ __forceinline__ uint32_t swz(uint32_t off) { return off ^ ((off >> 3) & 0x70); }

#define CP16(dst, src) \
    asm volatile("cp.async.cg.shared.global [%0], [%1], 16;" :: "r"(dst), "l"(src))
#define CP_COMMIT() asm volatile("cp.async.commit_group;" ::: "memory")
#define CP_WAIT(n)  asm volatile("cp.async.wait_group %0;" :: "n"(n) : "memory")

template <int ROWS>
__device__ __forceinline__ void ldchunk_async(const __nv_bfloat16* __restrict__ g, int row0,
                                              int ld, int k0, uint32_t sm, int tid) {
    for (int u = tid; u < ROWS * 8; u += 256) {
        int r = u >> 3, q = u & 7;
        const void* src = g + (size_t)(row0 + r) * ld + k0 + q * 8;
        CP16(sm + swz(r * 128 + q * 16), src);
    }
}

// precomputed-offset fragment loads: addr = stage_base + (swzoff ^ kb)
#define LDA_PRE(a, stage, swzoff, kb) \
    LDSM_X4((a)[0], (a)[1], (a)[2], (a)[3], (stage) + ((swzoff) ^ (uint32_t)(kb)))
#define LDB_PRE(b0a, b0b, b1a, b1b, stage, swzoff, kb) \
    LDSM_X4(b0a, b0b, b1a, b1b, (stage) + ((swzoff) ^ (uint32_t)(kb)))

// ---------------- combined weight prep: 3 transposes + w_dt convert ----------------
__global__ __launch_bounds__(256) void k_prep(const float* __restrict__ w_in,
                                              const float* __restrict__ w_out,
                                              const float* __restrict__ w_xproj,
                                              const float* __restrict__ w_dt) {
    __shared__ float tile[32][33];
    int which = blockIdx.z;
    int tx = threadIdx.x, ty = threadIdx.y;
    if (which == 3) {
        int idx = (blockIdx.y * gridDim.x + blockIdx.x) * 256 + ty * 32 + tx;
        if (idx < 16 * 512) g_wdth[idx] = __float2bfloat16(w_dt[idx]);
        return;
    }
    const float* in = (which == 0) ? w_in : ((which == 1) ? w_out : w_xproj);
    __nv_bfloat16* out = (which == 0) ? g_winT : ((which == 1) ? g_woutT : g_wxT);
    int R = (which == 0) ? 256 : 512;
    int C = (which == 0) ? 1024 : ((which == 1) ? 256 : 48);
    int c0 = blockIdx.x * 32, r0 = blockIdx.y * 32;
    if (c0 >= C || r0 >= R) return;
#pragma unroll
    for (int i = 0; i < 4; i++) {
        int r = r0 + ty + 8 * i;
        if (r < R && c0 + tx < C) tile[ty + 8 * i][tx] = in[(size_t)r * C + c0 + tx];
    }
    __syncthreads();
#pragma unroll
    for (int i = 0; i < 4; i++) {
        int c = c0 + ty + 8 * i;
        if (c < C && r0 + tx < R)
            out[(size_t)c * R + r0 + tx] = __float2bfloat16(tile[tx][ty + 8 * i]);
    }
}

// ---------------- RMSNorm ----------------
__global__ __launch_bounds__(256) void k_rmsnorm(const float* __restrict__ feat,
                                                 const float* __restrict__ nw) {
    __shared__ float sred[8][32];
    __shared__ __align__(16) __nv_bfloat16 sX[32][264];
    int tx = threadIdx.x, ty = threadIdx.y;
    int t = blockIdx.y;
    int b = blockIdx.x * 32 + tx;
    const float* base = feat + (size_t)t * DM * NB + b;
    float v[32];
    float ss = 0.f;
#pragma unroll
    for (int i = 0; i < 32; i++) {
        float x = base[(size_t)(ty + 8 * i) * NB];
        v[i] = x;
        ss += x * x;
    }
    sred[ty][tx] = ss;
    __syncthreads();
    float tot = 0.f;
#pragma unroll
    for (int j = 0; j < 8; j++) tot += sred[j][tx];
    float sc = rsqrtf(tot * (1.f / DM) + 1e-5f);
#pragma unroll
    for (int i = 0; i < 32; i++)
        sX[tx][ty + 8 * i] = __float2bfloat16(v[i] * sc * nw[ty + 8 * i]);
    __syncthreads();
    int tid = ty * 32 + tx;
    size_t tok0 = (size_t)t * NB + blockIdx.x * 32;
    for (int u = tid; u < 32 * 32; u += 256) {
        int r = u >> 5, q = u & 31;
        *(uint4*)(g_xnbf + (tok0 + r) * DM + q * 8) = *(uint4*)&sX[r][q * 8];
    }
}

// ---------------- GEMM1 (HMMA; A preloaded, B 3-stage) ----------------
__global__ __launch_bounds__(256, 2) void k_gemm1() {
    extern __shared__ __align__(1024) char sm[];
    int tid = threadIdx.x, wid = tid >> 5, lane = tid & 31;
    int wy = wid >> 2, wx = wid & 3;
    int fbase = blockIdx.y * 128, tbase = blockIdx.x * 128;
    uint32_t sbA = smem_u32(sm);
    uint32_t sbB = sbA + 65536;
    float acc[4][4][4];
#pragma unroll
    for (int i = 0; i < 4; i++)
#pragma unroll
        for (int j = 0; j < 4; j++)
#pragma unroll
            for (int q = 0; q < 4; q++) acc[i][j][q] = 0.f;

    uint32_t aoff[4], boff[2];
#pragma unroll
    for (int ft = 0; ft < 4; ft++)
        aoff[ft] = swz((uint32_t)((wy * 64 + ft * 16 + (lane & 15)) * 128 + ((lane >> 4) << 4)));
#pragma unroll
    for (int np = 0; np < 2; np++)
        boff[np] = swz((uint32_t)((wx * 32 + np * 16 + (lane & 7) + ((lane >> 4) << 3)) * 128 +
                                  (((lane >> 3) & 1) << 4)));

#pragma unroll
    for (int c = 0; c < 4; c++)
        ldchunk_async<128>(g_winT, fbase, 256, c * 64, sbA + c * 16384, tid);
    ldchunk_async<128>(g_xnbf, tbase, 256, 0, sbB, tid);
    CP_COMMIT();
    ldchunk_async<128>(g_xnbf, tbase, 256, 64, sbB + 16384, tid);
    CP_COMMIT();

    for (int kc = 0; kc < 4; kc++) {
        CP_WAIT(1);
        __syncthreads();
        if (kc + 2 < 4)
            ldchunk_async<128>(g_xnbf, tbase, 256, (kc + 2) * 64, sbB + ((kc + 2) % 3) * 16384, tid);
        CP_COMMIT();
        uint32_t aCh = sbA + kc * 16384;
        uint32_t bCur = sbB + (kc % 3) * 16384;
#pragma unroll
        for (int ks = 0; ks < 4; ks++) {
            int kb = ks * 32;
            uint32_t b[4][2];
#pragma unroll
            for (int np = 0; np < 2; np++)
                LDB_PRE(b[np * 2][0], b[np * 2][1], b[np * 2 + 1][0], b[np * 2 + 1][1],
                        bCur, boff[np], kb);
#pragma unroll
            for (int ft = 0; ft < 4; ft++) {
                uint32_t a[4];
                LDA_PRE(a, aCh, aoff[ft], kb);
#pragma unroll
                for (int nt = 0; nt < 4; nt++)
                    mma_bf16(acc[ft][nt], a[0], a[1], a[2], a[3], b[nt][0], b[nt][1]);
            }
        }
    }

    bool isRes = (fbase >= DI);
    __nv_bfloat16* base = isRes ? g_sresh : g_uh;
    int fb = isRes ? (fbase - DI) : fbase;
#pragma unroll
    for (int ft = 0; ft < 4; ft++) {
#pragma unroll
        for (int nt = 0; nt < 4; nt++) {
            float* c = acc[ft][nt];
            int f = fb + wy * 64 + ft * 16 + (lane >> 2);
            int m = tbase + wx * 32 + nt * 8 + (lane & 3) * 2;
            if (isRes) {
                *(uint32_t*)(base + (size_t)f * TOK + m)       = packbf(siluf(c[0]), siluf(c[1]));
                *(uint32_t*)(base + (size_t)(f + 8) * TOK + m) = packbf(siluf(c[2]), siluf(c[3]));
            } else {
                *(uint32_t*)(base + (size_t)f * TOK + m)       = packbf(c[0], c[1]);
                *(uint32_t*)(base + (size_t)(f + 8) * TOK + m) = packbf(c[2], c[3]);
            }
        }
    }
}

// ---------------- depthwise causal conv (k=3) + silu; vectorized, dual-layout ----------------
// block: 32 d x 64 m; each thread: 8 contiguous m of one d
__global__ __launch_bounds__(256) void k_conv(const float* __restrict__ cw,
                                              const float* __restrict__ cb) {
    __shared__ __align__(16) __nv_bfloat16 sT[32][72];
    int tid = threadIdx.x;
    int dl = tid >> 3;
    int ml = (tid & 7) << 3;
    int d = blockIdx.y * 32 + dl;
    int m0 = blockIdx.x * 64 + ml;
    int t = m0 >> 10;                     // all 8 m share t (64-aligned tile)
    size_t base = (size_t)d * TOK + m0;
    float w0 = cw[d * 3 + 0], w1 = cw[d * 3 + 1], w2 = cw[d * 3 + 2], bb = cb[d];
    uint4 z = make_uint4(0, 0, 0, 0);
    uint4 c2 = *(const uint4*)(g_uh + base);
    uint4 c1 = (t >= 1) ? *(const uint4*)(g_uh + base - NB) : z;
    uint4 c0 = (t >= 2) ? *(const uint4*)(g_uh + base - 2 * NB) : z;
    const uint32_t* p2 = (const uint32_t*)&c2;
    const uint32_t* p1 = (const uint32_t*)&c1;
    const uint32_t* p0 = (const uint32_t*)&c0;
    uint32_t outw[4];
#pragma unroll
    for (int p = 0; p < 4; p++) {
        float2 a2 = unpackbf(p2[p]), a1 = unpackbf(p1[p]), a0 = unpackbf(p0[p]);
        float r0 = bb + w2 * a2.x + w1 * a1.x + w0 * a0.x;
        float r1 = bb + w2 * a2.y + w1 * a1.y + w0 * a0.y;
        outw[p] = packbf(siluf(r0), siluf(r1));
    }
    *(uint4*)(g_xmh + base) = *(uint4*)outw;
    *(uint4*)(&sT[dl][ml]) = *(uint4*)outw;
    __syncthreads();
    int r = tid >> 2, c8 = (tid & 3) << 3;
    __nv_bfloat16 vals[8];
#pragma unroll
    for (int j = 0; j < 8; j++) vals[j] = sT[c8 + j][r];
    *(uint4*)(g_xmbf + (size_t)(blockIdx.x * 64 + r) * DI + blockIdx.y * 32 + c8) = *(uint4*)vals;
}

// ---------------- xproj (HMMA) + fused dt: outputs g_bcp + g_deltah ----------------
__global__ __launch_bounds__(256) void k_xproj(const float* __restrict__ b_dt) {
    extern __shared__ __align__(1024) char sm[];
    int tid = threadIdx.x, wid = tid >> 5, lane = tid & 31;
    int tbase = blockIdx.x * 128;
    uint32_t sbA = smem_u32(sm);                       // 8 chunks x 6144B = 49152
    uint32_t sbB = sbA + 49152;                        // 3 stages x 16384 -> 98304
    uint32_t sbW = sbA + 98304;                        // w_dt bf16 16x512 = 16384
    uint32_t sbBD = sbA + 114688;                      // b_dt fp32 = 2048
    float acc[3][2][4];
#pragma unroll
    for (int i = 0; i < 3; i++)
#pragma unroll
        for (int j = 0; j < 2; j++)
#pragma unroll
            for (int q = 0; q < 4; q++) acc[i][j][q] = 0.f;

    uint32_t aoff[3], boff;
#pragma unroll
    for (int ft = 0; ft < 3; ft++)
        aoff[ft] = swz((uint32_t)((ft * 16 + (lane & 15)) * 128 + ((lane >> 4) << 4)));
    boff = swz((uint32_t)((wid * 16 + (lane & 7) + ((lane >> 4) << 3)) * 128 +
                          (((lane >> 3) & 1) << 4)));

#pragma unroll
    for (int c = 0; c < 8; c++)
        ldchunk_async<48>(g_wxT, 0, 512, c * 64, sbA + c * 6144, tid);
    for (int u = tid; u < 1024; u += 256) CP16(sbW + u * 16, g_wdth + u * 8);
    for (int u = tid; u < 128; u += 256) CP16(sbBD + u * 16, b_dt + u * 4);
    ldchunk_async<128>(g_xmbf, tbase, 512, 0, sbB, tid);
    CP_COMMIT();
    ldchunk_async<128>(g_xmbf, tbase, 512, 64, sbB + 16384, tid);
    CP_COMMIT();

    for (int kc = 0; kc < 8; kc++) {
        CP_WAIT(1);
        __syncthreads();
        if (kc + 2 < 8)
            ldchunk_async<128>(g_xmbf, tbase, 512, (kc + 2) * 64, sbB + ((kc + 2) % 3) * 16384, tid);
        CP_COMMIT();
        uint32_t cur = sbB + (kc % 3) * 16384;
        uint32_t aCh = sbA + kc * 6144;
#pragma unroll
        for (int ks = 0; ks < 4; ks++) {
            int kb = ks * 32;
            uint32_t b[2][2];
            LDB_PRE(b[0][0], b[0][1], b[1][0], b[1][1], cur, boff, kb);
#pragma unroll
            for (int ft = 0; ft < 3; ft++) {
                uint32_t a[4];
                LDA_PRE(a, aCh, aoff[ft], kb);
#pragma unroll
                for (int nt = 0; nt < 2; nt++)
                    mma_bf16(acc[ft][nt], a[0], a[1], a[2], a[3], b[nt][0], b[nt][1]);
            }
        }
    }

    // stage results into smem (reuse B ring region; safe after mainloop + sync)
    __syncthreads();
    float* st = (float*)(sm + 49152);                  // [48][132]
#pragma unroll
    for (int ft = 0; ft < 3; ft++) {
#pragma unroll
        for (int nt = 0; nt < 2; nt++) {
            float* c = acc[ft][nt];
            int j = ft * 16 + (lane >> 2);
            int ml = wid * 16 + nt * 8 + (lane & 3) * 2;
            st[j * 132 + ml] = c[0];
            st[j * 132 + ml + 1] = c[1];
            st[(j + 8) * 132 + ml] = c[2];
            st[(j + 8) * 132 + ml + 1] = c[3];
        }
    }
    __syncthreads();
    // bcp: 16 packed rows (B pairs then C pairs), channel-major
    for (int v = tid; v < 16 * 128; v += 256) {
        int rr = v >> 7, mm = v & 127;
        g_bcp[(size_t)rr * TOK + tbase + mm] =
            packbf(st[(16 + 2 * rr) * 132 + mm], st[(17 + 2 * rr) * 132 + mm]);
    }
    // fused dt: delta[d][token] = softplus(b_dt[d] + sum_r st[r][token]*w_dt[r][d])
    {
        int token = tid & 63, dg = tid >> 6;            // 4 d-groups of 128
        const __nv_bfloat16* wd = (const __nv_bfloat16*)(sm + 98304);
        const float* bd = (const float*)(sm + 114688);
        float x0[16], x1[16];
#pragma unroll
        for (int r = 0; r < 16; r++) {
            x0[r] = st[r * 132 + token];
            x1[r] = st[r * 132 + token + 64];
        }
        for (int db = 0; db < 128; db += 8) {
            int d = dg * 128 + db;
            float a0[8], a1[8];
#pragma unroll
            for (int i = 0; i < 8; i++) { a0[i] = bd[d + i]; a1[i] = a0[i]; }
#pragma unroll
            for (int r = 0; r < 16; r++) {
                uint4 w4 = *(const uint4*)(wd + r * 512 + d);
                const uint32_t* wp = (const uint32_t*)&w4;
#pragma unroll
                for (int p = 0; p < 4; p++) {
                    float2 w = unpackbf(wp[p]);
                    a0[2 * p] += x0[r] * w.x;  a0[2 * p + 1] += x0[r] * w.y;
                    a1[2 * p] += x1[r] * w.x;  a1[2 * p + 1] += x1[r] * w.y;
                }
            }
#pragma unroll
            for (int i = 0; i < 8; i++) {
                g_deltah[(size_t)(d + i) * TOK + tbase + token] =
                    __float2bfloat16(softplusf(a0[i]));
                g_deltah[(size_t)(d + i) * TOK + tbase + token + 64] =
                    __float2bfloat16(softplusf(a1[i]));
            }
        }
    }
}

// ---------------- selective scan + D-skip + silu gate (16 d x 32 b, 1 sync/t) ----------------
__global__ __launch_bounds__(512) void k_scan(const float* __restrict__ A_log,
                                              const float* __restrict__ Dv) {
    __shared__ uint32_t sBC[2][16][32];
    __shared__ __nv_bfloat16 sY[2][16][32];
    int tx = threadIdx.x, ty = threadIdx.y;
    int tid = ty * 32 + tx;
    int b0 = blockIdx.x * 32;
    int d0 = blockIdx.y * 16;
    int d = d0 + ty;
    float A_[16];
    bool fast = true;
#pragma unroll
    for (int n = 0; n < 16; n++) {
        A_[n] = -__expf(A_log[d * 16 + n]);
        fast = fast && (fabsf(A_[n] + (float)(n + 1)) < 1e-3f * (n + 1));
    }
    float Dd = Dv[d];
    float h[16];
#pragma unroll
    for (int n = 0; n < 16; n++) h[n] = 0.f;

    int j0 = tid >> 5, c0 = tid & 31;
    sBC[0][j0][c0] = g_bcp[(size_t)j0 * TOK + b0 + c0];
    __syncthreads();

    for (int t = 0; t < NT; t++) {
        int cur = t & 1;
        int tokbase = t * NB + b0;
        if (t + 1 < NT)
            sBC[cur ^ 1][j0][c0] = g_bcp[(size_t)j0 * TOK + (t + 1) * NB + b0 + c0];

        size_t off = (size_t)d * TOK + tokbase + tx;
        float dlt = __bfloat162float(g_deltah[off]);
        float xv = __bfloat162float(g_xmh[off]);
        float dxu = dlt * xv;
        float y = 0.f;
        if (fast) {
            float p = __expf(-dlt), pn = 1.f;
#pragma unroll
            for (int r = 0; r < 8; r++) {
                float2 Bp = unpackbf(sBC[cur][r][tx]);
                float2 Cp = unpackbf(sBC[cur][8 + r][tx]);
                pn *= p;
                h[2 * r] = pn * h[2 * r] + dxu * Bp.x;
                y += h[2 * r] * Cp.x;
                pn *= p;
                h[2 * r + 1] = pn * h[2 * r + 1] + dxu * Bp.y;
                y += h[2 * r + 1] * Cp.y;
            }
        } else {
#pragma unroll
            for (int r = 0; r < 8; r++) {
                float2 Bp = unpackbf(sBC[cur][r][tx]);
                float2 Cp = unpackbf(sBC[cur][8 + r][tx]);
                float dA0 = __expf(dlt * A_[2 * r]);
                float dA1 = __expf(dlt * A_[2 * r + 1]);
                h[2 * r] = dA0 * h[2 * r] + dxu * Bp.x;
                y += h[2 * r] * Cp.x;
                h[2 * r + 1] = dA1 * h[2 * r + 1] + dxu * Bp.y;
                y += h[2 * r + 1] * Cp.y;
            }
        }
        float sres = __bfloat162float(g_sresh[off]);
        sY[cur][ty][tx] = __float2bfloat16((y + xv * Dd) * sres);
        __syncthreads();
        int bl = tid >> 4, j = tid & 15;
        g_ybf[(size_t)(tokbase + bl) * DI + d0 + j] = sY[cur][j][bl];
    }
}

// ---------------- GEMM out (HMMA + cp.async 3-stage) ----------------
__global__ __launch_bounds__(256, 2) void k_gemmout(const float* __restrict__ feat,
                                                    float* __restrict__ out) {
    extern __shared__ __align__(1024) char sm[];
    int tid = threadIdx.x, wid = tid >> 5, lane = tid & 31;
    int wy = wid >> 2, wx = wid & 3;
    int cbase = blockIdx.y * 128, tbase = blockIdx.x * 128;
    uint32_t sb = smem_u32(sm);
    float acc[4][4][4];
#pragma unroll
    for (int i = 0; i < 4; i++)
#pragma unroll
        for (int j = 0; j < 4; j++)
#pragma unroll
            for (int q = 0; q < 4; q++) acc[i][j][q] = 0.f;

    uint32_t aoff[4], boff[2];
#pragma unroll
    for (int ft = 0; ft < 4; ft++)
        aoff[ft] = swz((uint32_t)((wy * 64 + ft * 16 + (lane & 15)) * 128 + ((lane >> 4) << 4)));
#pragma unroll
    for (int np = 0; np < 2; np++)
        boff[np] = swz((uint32_t)((wx * 32 + np * 16 + (lane & 7) + ((lane >> 4) << 3)) * 128 +
                                  (((lane >> 3) & 1) << 4)));

#pragma unroll
    for (int s = 0; s < 2; s++) {
        ldchunk_async<128>(g_woutT, cbase, 512, s * 64, sb + s * 32768, tid);
        ldchunk_async<128>(g_ybf, tbase, 512, s * 64, sb + s * 32768 + 16384, tid);
        CP_COMMIT();
    }

    for (int kc = 0; kc < 8; kc++) {
        CP_WAIT(1);
        __syncthreads();
        if (kc + 2 < 8) {
            uint32_t nxt = sb + ((kc + 2) % 3) * 32768;
            ldchunk_async<128>(g_woutT, cbase, 512, (kc + 2) * 64, nxt, tid);
            ldchunk_async<128>(g_ybf, tbase, 512, (kc + 2) * 64, nxt + 16384, tid);
        }
        CP_COMMIT();
        uint32_t cur = sb + (kc % 3) * 32768;
        uint32_t sbA = cur, sbB = cur + 16384;
#pragma unroll
        for (int ks = 0; ks < 4; ks++) {
            int kb = ks * 32;
            uint32_t b[4][2];
#pragma unroll
            for (int np = 0; np < 2; np++)
                LDB_PRE(b[np * 2][0], b[np * 2][1], b[np * 2 + 1][0], b[np * 2 + 1][1],
                        sbB, boff[np], kb);
#pragma unroll
            for (int ft = 0; ft < 4; ft++) {
                uint32_t a[4];
                LDA_PRE(a, sbA, aoff[ft], kb);
#pragma unroll
                for (int nt = 0; nt < 4; nt++)
                    mma_bf16(acc[ft][nt], a[0], a[1], a[2], a[3], b[nt][0], b[nt][1]);
            }
        }
    }

    int t = tbase >> 10;
#pragma unroll
    for (int ft = 0; ft < 4; ft++) {
#pragma unroll
        for (int nt = 0; nt < 4; nt++) {
            float* c = acc[ft][nt];
            int cc = cbase + wy * 64 + ft * 16 + (lane >> 2);
            int m = tbase + wx * 32 + nt * 8 + (lane & 3) * 2;
            int b = m & 1023;
            size_t o0 = (size_t)t * DM * NB + (size_t)cc * NB + b;
            size_t o1 = o0 + 8 * (size_t)NB;
            float2 f0 = *(const float2*)(feat + o0);
            float2 f1 = *(const float2*)(feat + o1);
            float2 v0; v0.x = c[0] + f0.x; v0.y = c[1] + f0.y;
            float2 v1; v1.x = c[2] + f1.x; v1.y = c[3] + f1.y;
            *(float2*)(out + o0) = v0;
            *(float2*)(out + o1) = v1;
        }
    }
}

extern "C" void kernel_launch(void* const* d_in, const int* in_sizes, int n_in,
                              void* d_out, int out_size) {
    const float* feature = (const float*)d_in[0];
    const float* norm_w  = (const float*)d_in[1];
    const float* w_in    = (const float*)d_in[2];
    const float* conv_w  = (const float*)d_in[3];
    const float* conv_b  = (const float*)d_in[4];
    const float* w_xproj = (const float*)d_in[5];
    const float* w_dt    = (const float*)d_in[6];
    const float* b_dt    = (const float*)d_in[7];
    const float* A_log   = (const float*)d_in[8];
    const float* Dv      = (const float*)d_in[9];
    const float* w_out   = (const float*)d_in[10];
    float* out = (float*)d_out;

    const int SMEM_G1   = 65536 + 3 * 16384;      // 114688
    const int SMEM_GOUT = 3 * 32768;
    const int SMEM_XP   = 49152 + 3 * 16384 + 16384 + 2048;  // 116736
    cudaFuncSetAttribute(k_gemm1, cudaFuncAttributeMaxDynamicSharedMemorySize, SMEM_G1);
    cudaFuncSetAttribute(k_xproj, cudaFuncAttributeMaxDynamicSharedMemorySize, SMEM_XP);
    cudaFuncSetAttribute(k_gemmout, cudaFuncAttributeMaxDynamicSharedMemorySize, SMEM_GOUT);

    k_prep<<<dim3(32, 16, 4), dim3(32, 8)>>>(w_in, w_out, w_xproj, w_dt);
    k_rmsnorm<<<dim3(32, 16), dim3(32, 8)>>>(feature, norm_w);
    k_gemm1<<<dim3(128, 8), 256, SMEM_G1>>>();
    k_conv<<<dim3(256, 16), 256>>>(conv_w, conv_b);
    k_xproj<<<dim3(128, 1), 256, SMEM_XP>>>(b_dt);
    k_scan<<<dim3(32, 32), dim3(32, 16)>>>(A_log, Dv);
    k_gemmout<<<dim3(128, 2), 256, SMEM_GOUT>>>(feature, out);
}